// round 6
// baseline (speedup 1.0000x reference)
#include <cuda_runtime.h>
#include <cuda_bf16.h>
#include <cstdint>

#define N_PROD 100000
#define N_CUST 50000
#define HID    128
#define DOUT   64
#define E_PP   800000
#define E_PC   800000
#define E_LB   400000

typedef unsigned long long u64;
typedef __nv_bfloat16 bf16;

#define SWZ(x) ((x) ^ (((x) >> 3) & 0x70))

__device__ __forceinline__ uint32_t smem_u32(const void* p) {
    uint32_t a;
    asm("{ .reg .u64 t; cvta.to.shared.u64 t, %1; cvt.u32.u64 %0, t; }" : "=r"(a) : "l"(p));
    return a;
}
__device__ __forceinline__ void cp16(uint32_t dst, const void* src, int sz) {
    asm volatile("cp.async.cg.shared.global [%0],[%1],16,%2;"
                 :: "r"(dst), "l"(src), "r"(sz));
}
#define CP_WAIT() asm volatile("cp.async.wait_all;" ::: "memory")

__device__ __forceinline__ void ldm4(uint32_t addr, uint32_t* r) {
    asm volatile("ldmatrix.sync.aligned.m8n8.x4.shared.b16 {%0,%1,%2,%3},[%4];"
                 : "=r"(r[0]), "=r"(r[1]), "=r"(r[2]), "=r"(r[3]) : "r"(addr));
}
__device__ __forceinline__ void mma16816(float* d, const uint32_t* a,
                                         uint32_t b0, uint32_t b1) {
    asm volatile(
        "mma.sync.aligned.m16n8k16.row.col.f32.bf16.bf16.f32 "
        "{%0,%1,%2,%3},{%4,%5,%6,%7},{%8,%9},{%0,%1,%2,%3};"
        : "+f"(d[0]), "+f"(d[1]), "+f"(d[2]), "+f"(d[3])
        : "r"(a[0]), "r"(a[1]), "r"(a[2]), "r"(a[3]), "r"(b0), "r"(b1));
}
__device__ __forceinline__ void split1(float w, unsigned short& h, unsigned short& l) {
    bf16 hb = __float2bfloat16_rn(w);
    bf16 lb = __float2bfloat16_rn(w - __bfloat162float(hb));
    h = __bfloat16_as_ushort(hb);
    l = __bfloat16_as_ushort(lb);
}
__device__ __forceinline__ void split4(float a0, float a1, float a2, float a3,
                                       u64& hp, u64& lp) {
    unsigned short h0, l0, h1, l1, h2, l2, h3, l3;
    split1(a0, h0, l0); split1(a1, h1, l1);
    split1(a2, h2, l2); split1(a3, h3, l3);
    hp = (u64)h0 | ((u64)h1 << 16) | ((u64)h2 << 32) | ((u64)h3 << 48);
    lp = (u64)l0 | ((u64)l1 << 16) | ((u64)l2 << 32) | ((u64)l3 << 48);
}
// f32x2 helpers (decoder)
__device__ __forceinline__ u64 pack2(float lo, float hi) {
    u64 r; asm("mov.b64 %0,{%1,%2};" : "=l"(r) : "f"(lo), "f"(hi)); return r;
}
__device__ __forceinline__ u64 dup2(float a) {
    u64 r; asm("mov.b64 %0,{%1,%1};" : "=l"(r) : "f"(a)); return r;
}
__device__ __forceinline__ void fma2(u64& d, u64 a, u64 b) {
    asm("fma.rn.f32x2 %0,%1,%2,%0;" : "+l"(d) : "l"(a), "l"(b));
}
__device__ __forceinline__ void unpack2(u64 v, float& lo, float& hi) {
    asm("mov.b64 {%0,%1},%2;" : "=f"(lo), "=f"(hi) : "l"(v));
}

// ---------------------------------------------------------------------------
// Scratch planes
// ---------------------------------------------------------------------------
__device__ bf16 g_xPH[(size_t)N_PROD * HID];
__device__ bf16 g_xPL[(size_t)N_PROD * HID];
__device__ bf16 g_xCH[(size_t)N_CUST * HID];
__device__ bf16 g_xCL[(size_t)N_CUST * HID];
__device__ bf16 g_M0H[(size_t)N_PROD * HID];   // mean_pp(x) byproduct
__device__ bf16 g_M0L[(size_t)N_PROD * HID];
__device__ bf16 g_P1H[(size_t)N_PROD * HID];
__device__ bf16 g_P1L[(size_t)N_PROD * HID];
__device__ bf16 g_P2H[(size_t)N_PROD * HID];
__device__ bf16 g_P2L[(size_t)N_PROD * HID];
__device__ bf16 g_P3H[(size_t)N_PROD * HID];
__device__ bf16 g_P3L[(size_t)N_PROD * HID];
__device__ bf16 g_C1H[(size_t)N_CUST * HID];
__device__ bf16 g_C1L[(size_t)N_CUST * HID];
__device__ bf16 g_C2H[(size_t)N_CUST * HID];
__device__ bf16 g_C2L[(size_t)N_CUST * HID];
__device__ float g_zprod[(size_t)N_PROD * DOUT];
__device__ float g_zcust[(size_t)N_CUST * DOUT];

__device__ int g_cntP[N_PROD];
__device__ int g_cntC[N_CUST];
__device__ int g_offP[N_PROD];
__device__ int g_curP[N_PROD];
__device__ int g_csrP[E_PP];
__device__ int g_offC[N_CUST];
__device__ int g_curC[N_CUST];
__device__ int g_csrC[E_PC];
__device__ u64 g_lbP[128];
__device__ u64 g_lbC[64];

// ---------------------------------------------------------------------------
// Launch 0: convert x -> planes AND count both edge histograms
// ---------------------------------------------------------------------------
__global__ void k_pre(const float* __restrict__ xp, const float* __restrict__ xc,
                      const int* __restrict__ dstP, const int* __restrict__ dstC) {
    const int NP4 = N_PROD * HID / 4;
    const int NC4 = N_CUST * HID / 4;
    int i = blockIdx.x * blockDim.x + threadIdx.x;
    if (i < NP4 + NC4) {
        const float* src; bf16 *dh, *dl; int o;
        if (i < NP4) { src = xp; dh = g_xPH; dl = g_xPL; o = i; }
        else { src = xc; dh = g_xCH; dl = g_xCL; o = i - NP4; }
        float4 v = *reinterpret_cast<const float4*>(src + (size_t)o * 4);
        u64 hp, lp; split4(v.x, v.y, v.z, v.w, hp, lp);
        *reinterpret_cast<u64*>(dh + (size_t)o * 4) = hp;
        *reinterpret_cast<u64*>(dl + (size_t)o * 4) = lp;
        return;
    }
    int j = i - (NP4 + NC4);
    if (j < E_PP) { atomicAdd(&g_cntP[dstP[j]], 1); return; }
    j -= E_PP;
    if (j < E_PC) atomicAdd(&g_cntC[dstC[j]], 1);
}

// ---------------------------------------------------------------------------
// Launch 1: decoupled-lookback scan, P and C segments in one launch
// ---------------------------------------------------------------------------
__device__ void scan_seg(const int* __restrict__ cnt, int n,
                         int* __restrict__ off, int* __restrict__ cur,
                         u64* __restrict__ st, int bid) {
    __shared__ int s[1024];
    __shared__ int s_prefix;
    int tx = threadIdx.x;
    int gid = bid * 1024 + tx;
    int v = (gid < n) ? cnt[gid] : 0;
    s[tx] = v;
    __syncthreads();
#pragma unroll
    for (int d = 1; d < 1024; d <<= 1) {
        int t = (tx >= d) ? s[tx - d] : 0;
        __syncthreads();
        s[tx] += t;
        __syncthreads();
    }
    int incl = s[tx];
    int total = s[1023];
    if (tx == 0) {
        if (bid == 0) {
            s_prefix = 0;
            atomicExch(st, ((u64)(unsigned)total << 32) | 2ULL);
        } else {
            atomicExch(st + bid, ((u64)(unsigned)total << 32) | 1ULL);
            int run = 0, j = bid - 1;
            while (true) {
                u64 x;
                do { x = atomicAdd(st + j, 0ULL); } while ((x & 3ULL) == 0ULL);
                run += (int)(unsigned)(x >> 32);
                if ((x & 3ULL) == 2ULL) break;
                j--;
            }
            s_prefix = run;
            atomicExch(st + bid, ((u64)(unsigned)(run + total) << 32) | 2ULL);
        }
    }
    __syncthreads();
    if (gid < n) {
        int e = s_prefix + incl - v;
        off[gid] = e;
        cur[gid] = e;
    }
}

__global__ void k_scan2x() {
    const int nbP = (N_PROD + 1023) / 1024;
    if ((int)blockIdx.x < nbP)
        scan_seg(g_cntP, N_PROD, g_offP, g_curP, g_lbP, blockIdx.x);
    else
        scan_seg(g_cntC, N_CUST, g_offC, g_curC, g_lbC, blockIdx.x - nbP);
}

// ---------------------------------------------------------------------------
// Launch 2: fill both CSRs
// ---------------------------------------------------------------------------
__global__ void k_fill2x(const int* __restrict__ eP, const int* __restrict__ eC) {
    int e = blockIdx.x * blockDim.x + threadIdx.x;
    if (e < E_PP) {
        int d = eP[E_PP + e];
        int p = atomicAdd(&g_curP[d], 1);
        g_csrP[p] = eP[e];
    } else if (e < E_PP + E_PC) {
        int j = e - E_PP;
        int d = eC[E_PC + j];
        int p = atomicAdd(&g_curC[d], 1);
        g_csrC[p] = eC[j];
    }
}

__global__ void k_tail_zero() {
    int i = blockIdx.x * blockDim.x + threadIdx.x;
    if (i < N_PROD) g_cntP[i] = 0;
    if (i < N_CUST) g_cntC[i] = 0;
    if (i < 128) g_lbP[i] = 0;
    if (i < 64) g_lbC[i] = 0;
}

// ---------------------------------------------------------------------------
// HMMA bf16x3 GEMM with optional fused mean-aggregation on the A half.
//   AGG: 0 = A from planes via cp.async ; 1 = gather-mean from fp32 src ;
//        2 = gather-mean from plane src (hi+lo).
//   DUAL (K_TOT=256): X half staged from planes.
//   BYPROD: also write the computed mean planes to gmem (mH/mL).
// MTILE = 128 (dual) / 256 (single); 16 warps, each 16(M)x64(N) out tile.
// ---------------------------------------------------------------------------
template <int N_OUT, int K_TOT, int AGG, bool BYPROD, bool RELU, bool OUT_PLANES>
__global__ __launch_bounds__(512, 1) void hmma_gemm(
    const float* __restrict__ Af,
    const bf16* __restrict__ AH, const bf16* __restrict__ AL,
    const bf16* __restrict__ XH, const bf16* __restrict__ XL,
    const int* __restrict__ off, const int* __restrict__ csr, int E,
    const float* __restrict__ Wl, const float* __restrict__ Wr,
    const float* __restrict__ bias,
    float* __restrict__ outF, bf16* __restrict__ outH, bf16* __restrict__ outL,
    bf16* __restrict__ mH, bf16* __restrict__ mL,
    int n)
{
    constexpr bool DUAL  = (K_TOT == 256);
    constexpr int KSTEPS = K_TOT / 16;
    constexpr int NF2    = (N_OUT / 8) / 2;
    constexpr int MTILE  = DUAL ? 128 : 256;
    constexpr int SUBSZ  = MTILE * 128;        // one 64-col subtile, one plane
    constexpr int PLSZ   = 2 * SUBSZ;
    constexpr int BOFF   = 1024 + 2 * PLSZ;
    constexpr int BSPLIT = KSTEPS * NF2 * 32 * 16;
    constexpr int HALVES = K_TOT / 128;
    constexpr int RPW    = MTILE / 16;         // agg rows per warp

    extern __shared__ char smem[];
    const uint32_t sb = smem_u32(smem);
    const int tid = threadIdx.x;
    const int w = tid >> 5, lane = tid & 31;
    const int g     = (N_OUT == 128) ? (w & 1) : 0;
    const int warpM = (N_OUT == 128) ? (w >> 1) * 16 : w * 16;

    float* bs = (float*)smem;
    if (tid < N_OUT) bs[tid] = bias[tid];

    // W preload in fragment order (hi then lo)
    for (int idx = tid; idx < 2 * KSTEPS * NF2 * 32; idx += 512) {
        int l = idx & 31;
        int rest = idx >> 5;
        int nfp = rest % NF2;
        int rest2 = rest / NF2;
        int ks = rest2 % KSTEPS;
        int s = rest2 / KSTEPS;
        uint32_t vals[4];
#pragma unroll
        for (int e = 0; e < 2; e++) {
            int nf = nfp * 2 + e;
            int nn = nf * 8 + (l >> 2);
            int k0 = ks * 16 + (l & 3) * 2;
            const float* wp = Wl;
            int kk = k0;
            if (DUAL && k0 >= 128) { wp = Wr; kk = k0 - 128; }
            float2 wa = *reinterpret_cast<const float2*>(wp + nn * 128 + kk);
            float2 wb = *reinterpret_cast<const float2*>(wp + nn * 128 + kk + 8);
            unsigned short h, lo, r00, r01, r10, r11;
            split1(wa.x, h, lo); r00 = s ? lo : h;
            split1(wa.y, h, lo); r01 = s ? lo : h;
            split1(wb.x, h, lo); r10 = s ? lo : h;
            split1(wb.y, h, lo); r11 = s ? lo : h;
            vals[e * 2 + 0] = (uint32_t)r00 | ((uint32_t)r01 << 16);
            vals[e * 2 + 1] = (uint32_t)r10 | ((uint32_t)r11 << 16);
        }
        *reinterpret_cast<uint4*>(smem + BOFF + (size_t)idx * 16) =
            make_uint4(vals[0], vals[1], vals[2], vals[3]);
    }
    __syncthreads();

    const int ntiles = (n + MTILE - 1) / MTILE;

    for (int tt = blockIdx.x; tt < ntiles; tt += gridDim.x) {
        float acc[8][4];
#pragma unroll
        for (int nf = 0; nf < 8; nf++)
#pragma unroll
            for (int q = 0; q < 4; q++) acc[nf][q] = 0.f;

        for (int h = 0; h < HALVES; h++) {
            __syncthreads();
            bool used_cp = false;
            if (h == 0 && AGG != 0) {
                // fused mean-aggregation staging: lane owns 4 cols (lane*4..+3)
#pragma unroll
                for (int rr = 0; rr < RPW; rr++) {
                    int r0 = w * RPW + rr;
                    int gr = tt * MTILE + r0;
                    float a0 = 0.f, a1 = 0.f, a2 = 0.f, a3 = 0.f;
                    if (gr < n) {
                        int beg = off[gr];
                        int end = (gr + 1 < n) ? off[gr + 1] : E;
                        for (int j = beg; j < end; j++) {
                            int s0 = csr[j];
                            if (AGG == 1) {
                                float4 v = __ldg(reinterpret_cast<const float4*>(
                                    Af + (size_t)s0 * 128 + lane * 4));
                                a0 += v.x; a1 += v.y; a2 += v.z; a3 += v.w;
                            } else {
                                u64 hp = __ldg(reinterpret_cast<const u64*>(
                                    AH + (size_t)s0 * 128 + lane * 4));
                                u64 lp = __ldg(reinterpret_cast<const u64*>(
                                    AL + (size_t)s0 * 128 + lane * 4));
                                ushort4 hu = *reinterpret_cast<ushort4*>(&hp);
                                ushort4 lu = *reinterpret_cast<ushort4*>(&lp);
                                a0 += __bfloat162float(__ushort_as_bfloat16(hu.x)) +
                                      __bfloat162float(__ushort_as_bfloat16(lu.x));
                                a1 += __bfloat162float(__ushort_as_bfloat16(hu.y)) +
                                      __bfloat162float(__ushort_as_bfloat16(lu.y));
                                a2 += __bfloat162float(__ushort_as_bfloat16(hu.z)) +
                                      __bfloat162float(__ushort_as_bfloat16(lu.z));
                                a3 += __bfloat162float(__ushort_as_bfloat16(hu.w)) +
                                      __bfloat162float(__ushort_as_bfloat16(lu.w));
                            }
                        }
                        float sc = (end > beg) ? 1.0f / (float)(end - beg) : 0.f;
                        a0 *= sc; a1 *= sc; a2 *= sc; a3 *= sc;
                    }
                    u64 hp, lp; split4(a0, a1, a2, a3, hp, lp);
                    int sub = lane >> 4;
                    uint32_t sw = SWZ((uint32_t)(r0 * 128 + (lane & 15) * 8));
                    *(u64*)(smem + 1024 + 0 * PLSZ + sub * SUBSZ + sw) = hp;
                    *(u64*)(smem + 1024 + 1 * PLSZ + sub * SUBSZ + sw) = lp;
                    if (BYPROD && gr < n) {
                        *reinterpret_cast<u64*>(mH + (size_t)gr * 128 + lane * 4) = hp;
                        *reinterpret_cast<u64*>(mL + (size_t)gr * 128 + lane * 4) = lp;
                    }
                }
            } else {
                used_cp = true;
                const bf16* sh = (h == 0) ? AH : XH;
                const bf16* sl = (h == 0) ? AL : XL;
                constexpr int OPS = MTILE * 16 * 2;
#pragma unroll
                for (int it = 0; it < OPS / 512; it++) {
                    int u = tid + it * 512;
                    int plane = u / (MTILE * 16);
                    int rem = u % (MTILE * 16);
                    int r0 = rem >> 4;
                    int ch = rem & 15;
                    int sub = ch >> 3;
                    const bf16* src = plane ? sl : sh;
                    int gr = tt * MTILE + r0;
                    uint32_t dst = sb + 1024 + plane * PLSZ + sub * SUBSZ +
                                   SWZ((uint32_t)(r0 * 128 + (ch & 7) * 16));
                    const void* gp = src + (size_t)gr * 128 + ch * 8;
                    cp16(dst, gp, (gr < n) ? 16 : 0);
                }
            }
            if (used_cp) CP_WAIT();
            __syncthreads();

#pragma unroll
            for (int cc = 0; cc < 2; cc++) {
#pragma unroll
                for (int ksl = 0; ksl < 4; ksl++) {
                    const int ks = h * 8 + cc * 4 + ksl;
                    uint32_t ah[4], al[4];
                    {
                        int arow = warpM + (lane & 15);
                        int colb = ksl * 32 + ((lane >> 4) << 4);
                        uint32_t o = cc * SUBSZ + SWZ((uint32_t)(arow * 128 + colb));
                        ldm4(sb + 1024 + o, ah);
                        ldm4(sb + 1024 + PLSZ + o, al);
                    }
                    uint4 Bq[4];
                    {
                        size_t base = (size_t)BOFF +
                            ((size_t)(ks * NF2 + g * 4) * 32 + lane) * 16;
#pragma unroll
                        for (int p = 0; p < 4; p++)
                            Bq[p] = *reinterpret_cast<const uint4*>(smem + base + p * 512);
                    }
#pragma unroll
                    for (int nf = 0; nf < 8; nf++) {
                        uint32_t b0 = (nf & 1) ? Bq[nf >> 1].z : Bq[nf >> 1].x;
                        uint32_t b1 = (nf & 1) ? Bq[nf >> 1].w : Bq[nf >> 1].y;
                        mma16816(acc[nf], ah, b0, b1);
                    }
#pragma unroll
                    for (int nf = 0; nf < 8; nf++) {
                        uint32_t b0 = (nf & 1) ? Bq[nf >> 1].z : Bq[nf >> 1].x;
                        uint32_t b1 = (nf & 1) ? Bq[nf >> 1].w : Bq[nf >> 1].y;
                        mma16816(acc[nf], al, b0, b1);
                    }
                    {
                        size_t base = (size_t)BOFF + BSPLIT +
                            ((size_t)(ks * NF2 + g * 4) * 32 + lane) * 16;
#pragma unroll
                        for (int p = 0; p < 4; p++)
                            Bq[p] = *reinterpret_cast<const uint4*>(smem + base + p * 512);
                    }
#pragma unroll
                    for (int nf = 0; nf < 8; nf++) {
                        uint32_t b0 = (nf & 1) ? Bq[nf >> 1].z : Bq[nf >> 1].x;
                        uint32_t b1 = (nf & 1) ? Bq[nf >> 1].w : Bq[nf >> 1].y;
                        mma16816(acc[nf], ah, b0, b1);
                    }
                }
            }
        }

        // epilogue: 16 rows per warp
        {
            int rbase = tt * MTILE + warpM + (lane >> 2);
#pragma unroll
            for (int nf = 0; nf < 8; nf++) {
                int col = g * 64 + nf * 8 + (lane & 3) * 2;
#pragma unroll
                for (int hh = 0; hh < 2; hh++) {
                    int row = rbase + hh * 8;
                    if (row < n) {
                        float ox = acc[nf][hh * 2 + 0] + bs[col];
                        float oy = acc[nf][hh * 2 + 1] + bs[col + 1];
                        if (RELU) { ox = fmaxf(ox, 0.f); oy = fmaxf(oy, 0.f); }
                        if (OUT_PLANES) {
                            unsigned short h0, l0, h1, l1;
                            split1(ox, h0, l0); split1(oy, h1, l1);
                            *reinterpret_cast<uint32_t*>(outH + (size_t)row * N_OUT + col) =
                                (uint32_t)h0 | ((uint32_t)h1 << 16);
                            *reinterpret_cast<uint32_t*>(outL + (size_t)row * N_OUT + col) =
                                (uint32_t)l0 | ((uint32_t)l1 << 16);
                        } else {
                            *reinterpret_cast<float2*>(outF + (size_t)row * N_OUT + col) =
                                make_float2(ox, oy);
                        }
                    }
                }
            }
        }
    }
}

// ---------------------------------------------------------------------------
// SIMT decoder (f32x2 FMAs)
// ---------------------------------------------------------------------------
__launch_bounds__(512, 1)
__global__ void decoder_kernel(const float* __restrict__ zc, const float* __restrict__ zp,
                               const int* __restrict__ row, const int* __restrict__ col,
                               const float* __restrict__ W1, const float* __restrict__ b1,
                               const float* __restrict__ w2, const float* __restrict__ b2,
                               float* __restrict__ out, int nE) {
    constexpr int NOP = 68;
    constexpr int R = 8;
    extern __shared__ float smemf[];
    float* Ws = smemf;
    float* stage = smemf + 128 * NOP;

    int tid = threadIdx.x;
    for (int i = tid; i < 64 * 128; i += 512) {
        int o = i >> 7, k = i & 127;
        Ws[k * NOP + o] = W1[i];
    }
    __syncthreads();

    const int w = tid >> 5, lane = tid & 31;
    float* Zs = stage + w * (R * 128);

    float2 b1v = __ldg(reinterpret_cast<const float2*>(b1 + lane * 2));
    u64 bofs = pack2(b1v.x, b1v.y);
    float w20 = __ldg(w2 + lane * 2), w21 = __ldg(w2 + lane * 2 + 1);
    float b2v = __ldg(b2);

    for (int base = (blockIdx.x * 16 + w) * R; base < nE; base += gridDim.x * 16 * R) {
#pragma unroll
        for (int r = 0; r < R; r++) {
            int e = base + r;
            float4 v = make_float4(0.f, 0.f, 0.f, 0.f);
            if (e < nE) {
                if (lane < 16) {
                    int ri = __ldg(row + e);
                    v = *reinterpret_cast<const float4*>(zc + (size_t)ri * DOUT + lane * 4);
                } else {
                    int ci = __ldg(col + e);
                    v = *reinterpret_cast<const float4*>(zp + (size_t)ci * DOUT + (lane - 16) * 4);
                }
            }
            *reinterpret_cast<float4*>(Zs + r * 128 + lane * 4) = v;
        }
        __syncwarp();

        u64 acc[R];
#pragma unroll
        for (int r = 0; r < R; r++) acc[r] = bofs;

        for (int k0 = 0; k0 < 128; k0 += 4) {
            float4 z4[R];
#pragma unroll
            for (int r = 0; r < R; r++)
                z4[r] = *reinterpret_cast<const float4*>(Zs + r * 128 + k0);
#pragma unroll
            for (int kk = 0; kk < 4; kk++) {
                u64 wv = *reinterpret_cast<const u64*>(Ws + (k0 + kk) * NOP + lane * 2);
#pragma unroll
                for (int r = 0; r < R; r++) {
                    float z = (kk == 0) ? z4[r].x : (kk == 1) ? z4[r].y : (kk == 2) ? z4[r].z : z4[r].w;
                    u64 zd = dup2(z);
                    fma2(acc[r], zd, wv);
                }
            }
        }

#pragma unroll
        for (int r = 0; r < R; r++) {
            float h0, h1;
            unpack2(acc[r], h0, h1);
            h0 = fmaxf(h0, 0.f); h1 = fmaxf(h1, 0.f);
            float p = h0 * w20 + h1 * w21;
#pragma unroll
            for (int o = 16; o > 0; o >>= 1) p += __shfl_xor_sync(0xffffffff, p, o);
            if (lane == 0 && base + r < nE) out[base + r] = p + b2v;
        }
        __syncwarp();
    }
}

// ---------------------------------------------------------------------------
// Host orchestration
// ---------------------------------------------------------------------------
extern "C" void kernel_launch(void* const* d_in, const int* in_sizes, int n_in,
                              void* d_out, int out_size) {
    const float* x_prod = (const float*)d_in[0];
    const float* x_cust = (const float*)d_in[1];
    const int* pp = (const int*)d_in[2];
    const int* pc = (const int*)d_in[3];
    const int* eli = (const int*)d_in[4];

    bool sig = (in_sizes[6] == HID);
    const float* it_W1l = (const float*)d_in[5];
    const float* it_W1r = (const float*)d_in[sig ? 7 : 6];
    const float* it_b1  = (const float*)d_in[sig ? 6 : 7];
    const float* it_W2l = (const float*)d_in[8];
    const float* it_W2r = (const float*)d_in[sig ? 10 : 9];
    const float* it_b2  = (const float*)d_in[sig ? 9 : 10];
    const float* it_Wlin = (const float*)d_in[11];
    const float* it_blin = (const float*)d_in[12];
    const float* us_W1l = (const float*)d_in[13];
    const float* us_W1r = (const float*)d_in[sig ? 15 : 14];
    const float* us_b1  = (const float*)d_in[sig ? 14 : 15];
    const float* us_W2l = (const float*)d_in[16];
    const float* us_W2r = (const float*)d_in[sig ? 18 : 17];
    const float* us_b2  = (const float*)d_in[sig ? 17 : 18];
    const float* us_W3l = (const float*)d_in[19];
    const float* us_W3r = (const float*)d_in[sig ? 21 : 20];
    const float* us_b3  = (const float*)d_in[sig ? 20 : 21];
    const float* us_Wlin = (const float*)d_in[22];
    const float* us_blin = (const float*)d_in[23];
    const float* de_W1 = (const float*)d_in[24];
    const float* de_b1 = (const float*)d_in[25];
    const float* de_W2 = (const float*)d_in[26];
    const float* de_b2 = (const float*)d_in[27];

#define GETP(var, sym, T) T* var; cudaGetSymbolAddress((void**)&var, sym)
    GETP(xPH, g_xPH, bf16); GETP(xPL, g_xPL, bf16);
    GETP(xCH, g_xCH, bf16); GETP(xCL, g_xCL, bf16);
    GETP(M0H, g_M0H, bf16); GETP(M0L, g_M0L, bf16);
    GETP(P1H, g_P1H, bf16); GETP(P1L, g_P1L, bf16);
    GETP(P2H, g_P2H, bf16); GETP(P2L, g_P2L, bf16);
    GETP(P3H, g_P3H, bf16); GETP(P3L, g_P3L, bf16);
    GETP(C1H, g_C1H, bf16); GETP(C1L, g_C1L, bf16);
    GETP(C2H, g_C2H, bf16); GETP(C2L, g_C2L, bf16);
    GETP(zprod, g_zprod, float); GETP(zcust, g_zcust, float);
    GETP(offP, g_offP, int); GETP(csrP, g_csrP, int);
    GETP(offC, g_offC, int); GETP(csrC, g_csrC, int);
#undef GETP

    constexpr int SM_DUAL = 1024 + 2 * (2 * 128 * 128) + 2 * (16 * 8 * 32 * 16); // 197632
    constexpr int SM_SNGL = 1024 + 2 * (2 * 256 * 128) + 2 * (8 * 4 * 32 * 16);  // 164864
    constexpr int SM_DEC  = (128 * 68 + 16 * 8 * 128) * 4;

#define SETSM(K) cudaFuncSetAttribute(K, cudaFuncAttributeMaxDynamicSharedMemorySize, SM_DUAL)
    SETSM((hmma_gemm<128, 256, 1, true,  true, true>));
    SETSM((hmma_gemm<128, 256, 0, false, true, true>));
    SETSM((hmma_gemm<128, 256, 2, false, true, true>));
    SETSM((hmma_gemm<128, 256, 1, false, true, true>));
#undef SETSM
    cudaFuncSetAttribute((hmma_gemm<64, 128, 0, false, false, false>),
                         cudaFuncAttributeMaxDynamicSharedMemorySize, SM_SNGL);
    cudaFuncSetAttribute(decoder_kernel,
                         cudaFuncAttributeMaxDynamicSharedMemorySize, SM_DEC);

    const int nbP = (N_PROD + 1023) / 1024;
    const int nbC = (N_CUST + 1023) / 1024;
    const int PRE_ITEMS = (N_PROD + N_CUST) * HID / 4 + E_PP + E_PC;

    // 0-2: convert + counts, scans, fills
    k_pre<<<(PRE_ITEMS + 255) / 256, 256>>>(x_prod, x_cust, pp + E_PP, pc + E_PC);
    k_scan2x<<<nbP + nbC, 1024>>>();
    k_fill2x<<<(E_PP + E_PC + 255) / 256, 256>>>(pp, pc);

    // 3: G1 (PROFILED) it layer1: A = mean_pp(x) fused (fp32 gather, byproduct), X = x
    hmma_gemm<128, 256, 1, true, true, true><<<148, 512, SM_DUAL>>>(
        x_prod, nullptr, nullptr, xPH, xPL, offP, csrP, E_PP,
        it_W1l, it_W1r, it_b1, nullptr, P1H, P1L, M0H, M0L, N_PROD);
    // 4: G2 us layer1: A = mean planes (byproduct), X = x
    hmma_gemm<128, 256, 0, false, true, true><<<148, 512, SM_DUAL>>>(
        nullptr, M0H, M0L, xPH, xPL, nullptr, nullptr, 0,
        us_W1l, us_W1r, us_b1, nullptr, P2H, P2L, nullptr, nullptr, N_PROD);
    // 5: G3 it layer2: A = mean_pp(P1) fused (plane gather), X = P1
    hmma_gemm<128, 256, 2, false, true, true><<<148, 512, SM_DUAL>>>(
        nullptr, P1H, P1L, P1H, P1L, offP, csrP, E_PP,
        it_W2l, it_W2r, it_b2, nullptr, P3H, P3L, nullptr, nullptr, N_PROD);
    // 6: G4 it linear -> zprod
    hmma_gemm<64, 128, 0, false, false, false><<<148, 512, SM_SNGL>>>(
        nullptr, P3H, P3L, nullptr, nullptr, nullptr, nullptr, 0,
        it_Wlin, nullptr, it_blin, zprod, nullptr, nullptr, nullptr, nullptr, N_PROD);
    // 7: G5 us layer2: A = mean_pc(x_prod) fused (fp32 gather), X = x_cust
    hmma_gemm<128, 256, 1, false, true, true><<<148, 512, SM_DUAL>>>(
        x_prod, nullptr, nullptr, xCH, xCL, offC, csrC, E_PC,
        us_W2l, us_W2r, us_b2, nullptr, C1H, C1L, nullptr, nullptr, N_CUST);
    // 8: G6 us layer3: A = mean_pc(P2) fused (plane gather), X = C1
    hmma_gemm<128, 256, 2, false, true, true><<<148, 512, SM_DUAL>>>(
        nullptr, P2H, P2L, C1H, C1L, offC, csrC, E_PC,
        us_W3l, us_W3r, us_b3, nullptr, C2H, C2L, nullptr, nullptr, N_CUST);
    // 9: G7 us linear -> zcust
    hmma_gemm<64, 128, 0, false, false, false><<<148, 512, SM_SNGL>>>(
        nullptr, C2H, C2L, nullptr, nullptr, nullptr, nullptr, 0,
        us_Wlin, nullptr, us_blin, zcust, nullptr, nullptr, nullptr, nullptr, N_CUST);

    // 10: decoder
    decoder_kernel<<<296, 512, SM_DEC>>>(zcust, zprod, eli, eli + E_LB,
                                         de_W1, de_b1, de_W2, de_b2,
                                         (float*)d_out, E_LB);

    // 11: restore zero invariant
    k_tail_zero<<<(N_PROD + 255) / 256, 256>>>();
}

// round 7
// speedup vs baseline: 1.1483x; 1.1483x over previous
#include <cuda_runtime.h>
#include <cuda_bf16.h>
#include <cstdint>

#define N_PROD 100000
#define N_CUST 50000
#define HID    128
#define DOUT   64
#define E_PP   800000
#define E_PC   800000
#define E_LB   400000

typedef unsigned long long u64;
typedef __nv_bfloat16 bf16;

#define SWZ(x) ((x) ^ (((x) >> 3) & 0x70))

__device__ __forceinline__ uint32_t smem_u32(const void* p) {
    uint32_t a;
    asm("{ .reg .u64 t; cvta.to.shared.u64 t, %1; cvt.u32.u64 %0, t; }" : "=r"(a) : "l"(p));
    return a;
}
__device__ __forceinline__ void cp16(uint32_t dst, const void* src, int sz) {
    asm volatile("cp.async.cg.shared.global [%0],[%1],16,%2;"
                 :: "r"(dst), "l"(src), "r"(sz));
}
#define CP_COMMIT() asm volatile("cp.async.commit_group;" ::: "memory")
#define CP_WAIT1()  asm volatile("cp.async.wait_group 1;" ::: "memory")
#define CP_WAIT0()  asm volatile("cp.async.wait_group 0;" ::: "memory")

__device__ __forceinline__ void ldm4(uint32_t addr, uint32_t* r) {
    asm volatile("ldmatrix.sync.aligned.m8n8.x4.shared.b16 {%0,%1,%2,%3},[%4];"
                 : "=r"(r[0]), "=r"(r[1]), "=r"(r[2]), "=r"(r[3]) : "r"(addr));
}
__device__ __forceinline__ void mma16816(float* d, const uint32_t* a,
                                         uint32_t b0, uint32_t b1) {
    asm volatile(
        "mma.sync.aligned.m16n8k16.row.col.f32.bf16.bf16.f32 "
        "{%0,%1,%2,%3},{%4,%5,%6,%7},{%8,%9},{%0,%1,%2,%3};"
        : "+f"(d[0]), "+f"(d[1]), "+f"(d[2]), "+f"(d[3])
        : "r"(a[0]), "r"(a[1]), "r"(a[2]), "r"(a[3]), "r"(b0), "r"(b1));
}
__device__ __forceinline__ void split1(float w, unsigned short& h, unsigned short& l) {
    bf16 hb = __float2bfloat16_rn(w);
    bf16 lb = __float2bfloat16_rn(w - __bfloat162float(hb));
    h = __bfloat16_as_ushort(hb);
    l = __bfloat16_as_ushort(lb);
}
__device__ __forceinline__ void split4(float a0, float a1, float a2, float a3,
                                       u64& hp, u64& lp) {
    unsigned short h0, l0, h1, l1, h2, l2, h3, l3;
    split1(a0, h0, l0); split1(a1, h1, l1);
    split1(a2, h2, l2); split1(a3, h3, l3);
    hp = (u64)h0 | ((u64)h1 << 16) | ((u64)h2 << 32) | ((u64)h3 << 48);
    lp = (u64)l0 | ((u64)l1 << 16) | ((u64)l2 << 32) | ((u64)l3 << 48);
}
// f32x2 helpers (decoder)
__device__ __forceinline__ u64 pack2(float lo, float hi) {
    u64 r; asm("mov.b64 %0,{%1,%2};" : "=l"(r) : "f"(lo), "f"(hi)); return r;
}
__device__ __forceinline__ u64 dup2(float a) {
    u64 r; asm("mov.b64 %0,{%1,%1};" : "=l"(r) : "f"(a)); return r;
}
__device__ __forceinline__ void fma2(u64& d, u64 a, u64 b) {
    asm("fma.rn.f32x2 %0,%1,%2,%0;" : "+l"(d) : "l"(a), "l"(b));
}
__device__ __forceinline__ void unpack2(u64 v, float& lo, float& hi) {
    asm("mov.b64 {%0,%1},%2;" : "=f"(lo), "=f"(hi) : "l"(v));
}

// ---------------------------------------------------------------------------
// Scratch planes
// ---------------------------------------------------------------------------
__device__ bf16 g_xPH[(size_t)N_PROD * HID];
__device__ bf16 g_xPL[(size_t)N_PROD * HID];
__device__ bf16 g_xCH[(size_t)N_CUST * HID];
__device__ bf16 g_xCL[(size_t)N_CUST * HID];
__device__ bf16 g_M0H[(size_t)N_PROD * HID];   // current mean (reused)
__device__ bf16 g_M0L[(size_t)N_PROD * HID];
__device__ bf16 g_P1H[(size_t)N_PROD * HID];
__device__ bf16 g_P1L[(size_t)N_PROD * HID];
__device__ bf16 g_P2H[(size_t)N_PROD * HID];
__device__ bf16 g_P2L[(size_t)N_PROD * HID];
__device__ bf16 g_P3H[(size_t)N_PROD * HID];
__device__ bf16 g_P3L[(size_t)N_PROD * HID];
__device__ bf16 g_C1H[(size_t)N_CUST * HID];
__device__ bf16 g_C1L[(size_t)N_CUST * HID];
__device__ bf16 g_C2H[(size_t)N_CUST * HID];
__device__ bf16 g_C2L[(size_t)N_CUST * HID];
__device__ float g_zprod[(size_t)N_PROD * DOUT];
__device__ float g_zcust[(size_t)N_CUST * DOUT];

__device__ int g_cntP[N_PROD];
__device__ int g_cntC[N_CUST];
__device__ int g_offP[N_PROD];
__device__ int g_curP[N_PROD];
__device__ int g_csrP[E_PP];
__device__ int g_offC[N_CUST];
__device__ int g_curC[N_CUST];
__device__ int g_csrC[E_PC];
__device__ u64 g_lbP[128];
__device__ u64 g_lbC[64];

// ---------------------------------------------------------------------------
// Launch 0: convert x -> planes AND count both edge histograms
// ---------------------------------------------------------------------------
__global__ void k_pre(const float* __restrict__ xp, const float* __restrict__ xc,
                      const int* __restrict__ dstP, const int* __restrict__ dstC) {
    const int NP4 = N_PROD * HID / 4;
    const int NC4 = N_CUST * HID / 4;
    int i = blockIdx.x * blockDim.x + threadIdx.x;
    if (i < NP4 + NC4) {
        const float* src; bf16 *dh, *dl; int o;
        if (i < NP4) { src = xp; dh = g_xPH; dl = g_xPL; o = i; }
        else { src = xc; dh = g_xCH; dl = g_xCL; o = i - NP4; }
        float4 v = *reinterpret_cast<const float4*>(src + (size_t)o * 4);
        u64 hp, lp; split4(v.x, v.y, v.z, v.w, hp, lp);
        *reinterpret_cast<u64*>(dh + (size_t)o * 4) = hp;
        *reinterpret_cast<u64*>(dl + (size_t)o * 4) = lp;
        return;
    }
    int j = i - (NP4 + NC4);
    if (j < E_PP) { atomicAdd(&g_cntP[dstP[j]], 1); return; }
    j -= E_PP;
    if (j < E_PC) atomicAdd(&g_cntC[dstC[j]], 1);
}

// ---------------------------------------------------------------------------
// Launch 1: decoupled-lookback scan (P and C segments)
// ---------------------------------------------------------------------------
__device__ void scan_seg(const int* __restrict__ cnt, int n,
                         int* __restrict__ off, int* __restrict__ cur,
                         u64* __restrict__ st, int bid) {
    __shared__ int s[1024];
    __shared__ int s_prefix;
    int tx = threadIdx.x;
    int gid = bid * 1024 + tx;
    int v = (gid < n) ? cnt[gid] : 0;
    s[tx] = v;
    __syncthreads();
#pragma unroll
    for (int d = 1; d < 1024; d <<= 1) {
        int t = (tx >= d) ? s[tx - d] : 0;
        __syncthreads();
        s[tx] += t;
        __syncthreads();
    }
    int incl = s[tx];
    int total = s[1023];
    if (tx == 0) {
        if (bid == 0) {
            s_prefix = 0;
            atomicExch(st, ((u64)(unsigned)total << 32) | 2ULL);
        } else {
            atomicExch(st + bid, ((u64)(unsigned)total << 32) | 1ULL);
            int run = 0, j = bid - 1;
            while (true) {
                u64 x;
                do { x = atomicAdd(st + j, 0ULL); } while ((x & 3ULL) == 0ULL);
                run += (int)(unsigned)(x >> 32);
                if ((x & 3ULL) == 2ULL) break;
                j--;
            }
            s_prefix = run;
            atomicExch(st + bid, ((u64)(unsigned)(run + total) << 32) | 2ULL);
        }
    }
    __syncthreads();
    if (gid < n) {
        int e = s_prefix + incl - v;
        off[gid] = e;
        cur[gid] = e;
    }
}

__global__ void k_scan2x() {
    const int nbP = (N_PROD + 1023) / 1024;
    if ((int)blockIdx.x < nbP)
        scan_seg(g_cntP, N_PROD, g_offP, g_curP, g_lbP, blockIdx.x);
    else
        scan_seg(g_cntC, N_CUST, g_offC, g_curC, g_lbC, blockIdx.x - nbP);
}

__global__ void k_fill2x(const int* __restrict__ eP, const int* __restrict__ eC) {
    int e = blockIdx.x * blockDim.x + threadIdx.x;
    if (e < E_PP) {
        int d = eP[E_PP + e];
        int p = atomicAdd(&g_curP[d], 1);
        g_csrP[p] = eP[e];
    } else if (e < E_PP + E_PC) {
        int j = e - E_PP;
        int d = eC[E_PC + j];
        int p = atomicAdd(&g_curC[d], 1);
        g_csrC[p] = eC[j];
    }
}

__global__ void k_tail_zero() {
    int i = blockIdx.x * blockDim.x + threadIdx.x;
    if (i < N_PROD) g_cntP[i] = 0;
    if (i < N_CUST) g_cntC[i] = 0;
    if (i < 128) g_lbP[i] = 0;
    if (i < 64) g_lbC[i] = 0;
}

// ---------------------------------------------------------------------------
// Standalone mean aggregation: one warp per node, planes out
// ---------------------------------------------------------------------------
template <bool IN_PLANES>
__global__ void agg_mean(const float* __restrict__ xf,
                         const bf16* __restrict__ xh, const bf16* __restrict__ xl,
                         const int* __restrict__ off, const int* __restrict__ csr,
                         bf16* __restrict__ oh, bf16* __restrict__ ol,
                         int n, int E) {
    int w = (blockIdx.x * blockDim.x + threadIdx.x) >> 5;
    int lane = threadIdx.x & 31;
    if (w >= n) return;
    int beg = off[w];
    int end = (w + 1 < n) ? off[w + 1] : E;
    float a0 = 0.f, a1 = 0.f, a2 = 0.f, a3 = 0.f;
    for (int j = beg; j < end; j++) {
        int s0 = csr[j];
        if (IN_PLANES) {
            u64 hp = __ldg(reinterpret_cast<const u64*>(xh + (size_t)s0 * HID + lane * 4));
            u64 lp = __ldg(reinterpret_cast<const u64*>(xl + (size_t)s0 * HID + lane * 4));
            ushort4 hu = *reinterpret_cast<ushort4*>(&hp);
            ushort4 lu = *reinterpret_cast<ushort4*>(&lp);
            a0 += __bfloat162float(__ushort_as_bfloat16(hu.x)) + __bfloat162float(__ushort_as_bfloat16(lu.x));
            a1 += __bfloat162float(__ushort_as_bfloat16(hu.y)) + __bfloat162float(__ushort_as_bfloat16(lu.y));
            a2 += __bfloat162float(__ushort_as_bfloat16(hu.z)) + __bfloat162float(__ushort_as_bfloat16(lu.z));
            a3 += __bfloat162float(__ushort_as_bfloat16(hu.w)) + __bfloat162float(__ushort_as_bfloat16(lu.w));
        } else {
            float4 v = __ldg(reinterpret_cast<const float4*>(xf + (size_t)s0 * HID + lane * 4));
            a0 += v.x; a1 += v.y; a2 += v.z; a3 += v.w;
        }
    }
    float sc = (end > beg) ? 1.0f / (float)(end - beg) : 0.f;
    a0 *= sc; a1 *= sc; a2 *= sc; a3 *= sc;
    u64 hp, lp; split4(a0, a1, a2, a3, hp, lp);
    *reinterpret_cast<u64*>(oh + (size_t)w * HID + lane * 4) = hp;
    *reinterpret_cast<u64*>(ol + (size_t)w * HID + lane * 4) = lp;
}

// ---------------------------------------------------------------------------
// HMMA bf16x3 GEMM — plane inputs, double-buffered cp.async chunk pipeline.
//   DUAL (K_TOT=256): A half then X half ; MTILE=128
//   single (K_TOT=128): A only ; MTILE=256
// 512 threads = 16 warps, warp tile 16(M) x 64(N).
// Chunk = 64 K-cols; SMEM: bias | A bufs[2][2 planes][MTILE*128B] | B frags
// ---------------------------------------------------------------------------
template <int N_OUT, int K_TOT, bool RELU, bool OUT_PLANES>
__global__ __launch_bounds__(512, 1) void hmma_gemm(
    const bf16* __restrict__ AH, const bf16* __restrict__ AL,
    const bf16* __restrict__ XH, const bf16* __restrict__ XL,
    const float* __restrict__ Wl, const float* __restrict__ Wr,
    const float* __restrict__ bias,
    float* __restrict__ outF, bf16* __restrict__ outH, bf16* __restrict__ outL,
    int n)
{
    constexpr bool DUAL   = (K_TOT == 256);
    constexpr int KSTEPS  = K_TOT / 16;
    constexpr int NF2     = (N_OUT / 8) / 2;
    constexpr int MTILE   = DUAL ? 128 : 256;
    constexpr int CHUNKB  = MTILE * 128;      // bytes, one plane of one chunk
    constexpr int BUFB    = 2 * CHUNKB;       // both planes
    constexpr int BOFF    = 1024 + 2 * BUFB;
    constexpr int BSPLIT  = KSTEPS * NF2 * 32 * 16;
    constexpr int NCHUNK  = K_TOT / 64;
    constexpr int CPOPS   = MTILE * 8 * 2;    // 16B ops per chunk (both planes)

    extern __shared__ char smem[];
    const uint32_t sb = smem_u32(smem);
    const int tid = threadIdx.x;
    const int w = tid >> 5, lane = tid & 31;
    const int g     = (N_OUT == 128) ? (w & 1) : 0;
    const int warpM = (N_OUT == 128) ? (w >> 1) * 16 : w * 16;

    float* bs = (float*)smem;
    if (tid < N_OUT) bs[tid] = bias[tid];

    // W preload in fragment order (hi then lo)
    for (int idx = tid; idx < 2 * KSTEPS * NF2 * 32; idx += 512) {
        int l = idx & 31;
        int rest = idx >> 5;
        int nfp = rest % NF2;
        int rest2 = rest / NF2;
        int ks = rest2 % KSTEPS;
        int s = rest2 / KSTEPS;
        uint32_t vals[4];
#pragma unroll
        for (int e = 0; e < 2; e++) {
            int nf = nfp * 2 + e;
            int nn = nf * 8 + (l >> 2);
            int k0 = ks * 16 + (l & 3) * 2;
            const float* wp = Wl;
            int kk = k0;
            if (DUAL && k0 >= 128) { wp = Wr; kk = k0 - 128; }
            float2 wa = *reinterpret_cast<const float2*>(wp + nn * 128 + kk);
            float2 wb = *reinterpret_cast<const float2*>(wp + nn * 128 + kk + 8);
            unsigned short h, lo, r00, r01, r10, r11;
            split1(wa.x, h, lo); r00 = s ? lo : h;
            split1(wa.y, h, lo); r01 = s ? lo : h;
            split1(wb.x, h, lo); r10 = s ? lo : h;
            split1(wb.y, h, lo); r11 = s ? lo : h;
            vals[e * 2 + 0] = (uint32_t)r00 | ((uint32_t)r01 << 16);
            vals[e * 2 + 1] = (uint32_t)r10 | ((uint32_t)r11 << 16);
        }
        *reinterpret_cast<uint4*>(smem + BOFF + (size_t)idx * 16) =
            make_uint4(vals[0], vals[1], vals[2], vals[3]);
    }
    __syncthreads();

    const int ntiles = (n + MTILE - 1) / MTILE;

    for (int tt = blockIdx.x; tt < ntiles; tt += gridDim.x) {
        float acc[8][4];
#pragma unroll
        for (int nf = 0; nf < 8; nf++)
#pragma unroll
            for (int q = 0; q < 4; q++) acc[nf][q] = 0.f;

        // --- stage helper (lambda): chunk c -> buffer b ---
        auto stage = [&](int c, int b) {
            const bf16* sh = (DUAL && c >= 2) ? XH : AH;
            const bf16* sl = (DUAL && c >= 2) ? XL : AL;
            const int colbase = (c & 1) * 64;
#pragma unroll
            for (int it = 0; it < CPOPS / 512; it++) {
                int u = tid + it * 512;
                int plane = u / (MTILE * 8);
                int rem = u % (MTILE * 8);
                int r0 = rem >> 3;
                int ch = rem & 7;
                const bf16* src = plane ? sl : sh;
                int gr = tt * MTILE + r0;
                uint32_t dst = sb + 1024 + b * BUFB + plane * CHUNKB +
                               SWZ((uint32_t)(r0 * 128 + ch * 16));
                const void* gp = src + (size_t)gr * 128 + colbase + ch * 8;
                cp16(dst, gp, (gr < n) ? 16 : 0);
            }
            CP_COMMIT();
        };

        stage(0, 0);

        for (int c = 0; c < NCHUNK; c++) {
            if (c + 1 < NCHUNK) { stage(c + 1, (c + 1) & 1); CP_WAIT1(); }
            else CP_WAIT0();
            __syncthreads();

            const uint32_t abase = sb + 1024 + (c & 1) * BUFB;
#pragma unroll
            for (int ksl = 0; ksl < 4; ksl++) {
                const int ks = c * 4 + ksl;
                uint32_t ah[4], al[4];
                {
                    int arow = warpM + (lane & 15);
                    int colb = ksl * 32 + ((lane >> 4) << 4);
                    uint32_t o = SWZ((uint32_t)(arow * 128 + colb));
                    ldm4(abase + o, ah);
                    ldm4(abase + CHUNKB + o, al);
                }
                uint4 Bq[4];
                {
                    size_t base = (size_t)BOFF +
                        ((size_t)(ks * NF2 + g * 4) * 32 + lane) * 16;
#pragma unroll
                    for (int p = 0; p < 4; p++)
                        Bq[p] = *reinterpret_cast<const uint4*>(smem + base + p * 512);
                }
#pragma unroll
                for (int nf = 0; nf < 8; nf++) {
                    uint32_t b0 = (nf & 1) ? Bq[nf >> 1].z : Bq[nf >> 1].x;
                    uint32_t b1 = (nf & 1) ? Bq[nf >> 1].w : Bq[nf >> 1].y;
                    mma16816(acc[nf], ah, b0, b1);
                }
#pragma unroll
                for (int nf = 0; nf < 8; nf++) {
                    uint32_t b0 = (nf & 1) ? Bq[nf >> 1].z : Bq[nf >> 1].x;
                    uint32_t b1 = (nf & 1) ? Bq[nf >> 1].w : Bq[nf >> 1].y;
                    mma16816(acc[nf], al, b0, b1);
                }
                {
                    size_t base = (size_t)BOFF + BSPLIT +
                        ((size_t)(ks * NF2 + g * 4) * 32 + lane) * 16;
#pragma unroll
                    for (int p = 0; p < 4; p++)
                        Bq[p] = *reinterpret_cast<const uint4*>(smem + base + p * 512);
                }
#pragma unroll
                for (int nf = 0; nf < 8; nf++) {
                    uint32_t b0 = (nf & 1) ? Bq[nf >> 1].z : Bq[nf >> 1].x;
                    uint32_t b1 = (nf & 1) ? Bq[nf >> 1].w : Bq[nf >> 1].y;
                    mma16816(acc[nf], ah, b0, b1);
                }
            }
            __syncthreads();
        }

        // epilogue: 16 rows per warp
        {
            int rbase = tt * MTILE + warpM + (lane >> 2);
#pragma unroll
            for (int nf = 0; nf < 8; nf++) {
                int col = g * 64 + nf * 8 + (lane & 3) * 2;
#pragma unroll
                for (int hh = 0; hh < 2; hh++) {
                    int row = rbase + hh * 8;
                    if (row < n) {
                        float ox = acc[nf][hh * 2 + 0] + bs[col];
                        float oy = acc[nf][hh * 2 + 1] + bs[col + 1];
                        if (RELU) { ox = fmaxf(ox, 0.f); oy = fmaxf(oy, 0.f); }
                        if (OUT_PLANES) {
                            unsigned short h0, l0, h1, l1;
                            split1(ox, h0, l0); split1(oy, h1, l1);
                            *reinterpret_cast<uint32_t*>(outH + (size_t)row * N_OUT + col) =
                                (uint32_t)h0 | ((uint32_t)h1 << 16);
                            *reinterpret_cast<uint32_t*>(outL + (size_t)row * N_OUT + col) =
                                (uint32_t)l0 | ((uint32_t)l1 << 16);
                        } else {
                            *reinterpret_cast<float2*>(outF + (size_t)row * N_OUT + col) =
                                make_float2(ox, oy);
                        }
                    }
                }
            }
        }
    }
}

// ---------------------------------------------------------------------------
// SIMT decoder (f32x2 FMAs)
// ---------------------------------------------------------------------------
__launch_bounds__(512, 1)
__global__ void decoder_kernel(const float* __restrict__ zc, const float* __restrict__ zp,
                               const int* __restrict__ row, const int* __restrict__ col,
                               const float* __restrict__ W1, const float* __restrict__ b1,
                               const float* __restrict__ w2, const float* __restrict__ b2,
                               float* __restrict__ out, int nE) {
    constexpr int NOP = 68;
    constexpr int R = 8;
    extern __shared__ float smemf[];
    float* Ws = smemf;
    float* stage = smemf + 128 * NOP;

    int tid = threadIdx.x;
    for (int i = tid; i < 64 * 128; i += 512) {
        int o = i >> 7, k = i & 127;
        Ws[k * NOP + o] = W1[i];
    }
    __syncthreads();

    const int w = tid >> 5, lane = tid & 31;
    float* Zs = stage + w * (R * 128);

    float2 b1v = __ldg(reinterpret_cast<const float2*>(b1 + lane * 2));
    u64 bofs = pack2(b1v.x, b1v.y);
    float w20 = __ldg(w2 + lane * 2), w21 = __ldg(w2 + lane * 2 + 1);
    float b2v = __ldg(b2);

    for (int base = (blockIdx.x * 16 + w) * R; base < nE; base += gridDim.x * 16 * R) {
#pragma unroll
        for (int r = 0; r < R; r++) {
            int e = base + r;
            float4 v = make_float4(0.f, 0.f, 0.f, 0.f);
            if (e < nE) {
                if (lane < 16) {
                    int ri = __ldg(row + e);
                    v = *reinterpret_cast<const float4*>(zc + (size_t)ri * DOUT + lane * 4);
                } else {
                    int ci = __ldg(col + e);
                    v = *reinterpret_cast<const float4*>(zp + (size_t)ci * DOUT + (lane - 16) * 4);
                }
            }
            *reinterpret_cast<float4*>(Zs + r * 128 + lane * 4) = v;
        }
        __syncwarp();

        u64 acc[R];
#pragma unroll
        for (int r = 0; r < R; r++) acc[r] = bofs;

        for (int k0 = 0; k0 < 128; k0 += 4) {
            float4 z4[R];
#pragma unroll
            for (int r = 0; r < R; r++)
                z4[r] = *reinterpret_cast<const float4*>(Zs + r * 128 + k0);
#pragma unroll
            for (int kk = 0; kk < 4; kk++) {
                u64 wv = *reinterpret_cast<const u64*>(Ws + (k0 + kk) * NOP + lane * 2);
#pragma unroll
                for (int r = 0; r < R; r++) {
                    float z = (kk == 0) ? z4[r].x : (kk == 1) ? z4[r].y : (kk == 2) ? z4[r].z : z4[r].w;
                    u64 zd = dup2(z);
                    fma2(acc[r], zd, wv);
                }
            }
        }

#pragma unroll
        for (int r = 0; r < R; r++) {
            float h0, h1;
            unpack2(acc[r], h0, h1);
            h0 = fmaxf(h0, 0.f); h1 = fmaxf(h1, 0.f);
            float p = h0 * w20 + h1 * w21;
#pragma unroll
            for (int o = 16; o > 0; o >>= 1) p += __shfl_xor_sync(0xffffffff, p, o);
            if (lane == 0 && base + r < nE) out[base + r] = p + b2v;
        }
        __syncwarp();
    }
}

// ---------------------------------------------------------------------------
// Host orchestration
// ---------------------------------------------------------------------------
extern "C" void kernel_launch(void* const* d_in, const int* in_sizes, int n_in,
                              void* d_out, int out_size) {
    const float* x_prod = (const float*)d_in[0];
    const float* x_cust = (const float*)d_in[1];
    const int* pp = (const int*)d_in[2];
    const int* pc = (const int*)d_in[3];
    const int* eli = (const int*)d_in[4];

    bool sig = (in_sizes[6] == HID);
    const float* it_W1l = (const float*)d_in[5];
    const float* it_W1r = (const float*)d_in[sig ? 7 : 6];
    const float* it_b1  = (const float*)d_in[sig ? 6 : 7];
    const float* it_W2l = (const float*)d_in[8];
    const float* it_W2r = (const float*)d_in[sig ? 10 : 9];
    const float* it_b2  = (const float*)d_in[sig ? 9 : 10];
    const float* it_Wlin = (const float*)d_in[11];
    const float* it_blin = (const float*)d_in[12];
    const float* us_W1l = (const float*)d_in[13];
    const float* us_W1r = (const float*)d_in[sig ? 15 : 14];
    const float* us_b1  = (const float*)d_in[sig ? 14 : 15];
    const float* us_W2l = (const float*)d_in[16];
    const float* us_W2r = (const float*)d_in[sig ? 18 : 17];
    const float* us_b2  = (const float*)d_in[sig ? 17 : 18];
    const float* us_W3l = (const float*)d_in[19];
    const float* us_W3r = (const float*)d_in[sig ? 21 : 20];
    const float* us_b3  = (const float*)d_in[sig ? 20 : 21];
    const float* us_Wlin = (const float*)d_in[22];
    const float* us_blin = (const float*)d_in[23];
    const float* de_W1 = (const float*)d_in[24];
    const float* de_b1 = (const float*)d_in[25];
    const float* de_W2 = (const float*)d_in[26];
    const float* de_b2 = (const float*)d_in[27];

#define GETP(var, sym, T) T* var; cudaGetSymbolAddress((void**)&var, sym)
    GETP(xPH, g_xPH, bf16); GETP(xPL, g_xPL, bf16);
    GETP(xCH, g_xCH, bf16); GETP(xCL, g_xCL, bf16);
    GETP(M0H, g_M0H, bf16); GETP(M0L, g_M0L, bf16);
    GETP(P1H, g_P1H, bf16); GETP(P1L, g_P1L, bf16);
    GETP(P2H, g_P2H, bf16); GETP(P2L, g_P2L, bf16);
    GETP(P3H, g_P3H, bf16); GETP(P3L, g_P3L, bf16);
    GETP(C1H, g_C1H, bf16); GETP(C1L, g_C1L, bf16);
    GETP(C2H, g_C2H, bf16); GETP(C2L, g_C2L, bf16);
    GETP(zprod, g_zprod, float); GETP(zcust, g_zcust, float);
    GETP(offP, g_offP, int); GETP(csrP, g_csrP, int);
    GETP(offC, g_offC, int); GETP(csrC, g_csrC, int);
#undef GETP

    // SMEM: dual = 1024 + 2*(2*128*128) + 2*(16*8*32*16) = 197632
    //       single = 1024 + 2*(2*256*128) + 2*(8*4*32*16) = 164864
    constexpr int SM_DUAL = 1024 + 2 * (2 * 128 * 128) + 2 * (16 * 8 * 32 * 16);
    constexpr int SM_SNGL = 1024 + 2 * (2 * 256 * 128) + 2 * (8 * 4 * 32 * 16);
    constexpr int SM_DEC  = (128 * 68 + 16 * 8 * 128) * 4;
    cudaFuncSetAttribute((hmma_gemm<128, 256, true, true>),
                         cudaFuncAttributeMaxDynamicSharedMemorySize, SM_DUAL);
    cudaFuncSetAttribute((hmma_gemm<64, 128, false, false>),
                         cudaFuncAttributeMaxDynamicSharedMemorySize, SM_SNGL);
    cudaFuncSetAttribute(decoder_kernel,
                         cudaFuncAttributeMaxDynamicSharedMemorySize, SM_DEC);

    const int nbP = (N_PROD + 1023) / 1024;
    const int nbC = (N_CUST + 1023) / 1024;
    const int PRE_ITEMS = (N_PROD + N_CUST) * HID / 4 + E_PP + E_PC;
    const int aggP_grid = (N_PROD * 32 + 255) / 256;
    const int aggC_grid = (N_CUST * 32 + 255) / 256;

    // 0-2: convert + counts, scans, fills
    k_pre<<<(PRE_ITEMS + 255) / 256, 256>>>(x_prod, x_cust, pp + E_PP, pc + E_PC);
    k_scan2x<<<nbP + nbC, 1024>>>();
    k_fill2x<<<(E_PP + E_PC + 255) / 256, 256>>>(pp, pc);

    // 3: M0 = mean_pp(x_prod)
    agg_mean<false><<<aggP_grid, 256>>>(x_prod, nullptr, nullptr, offP, csrP,
                                        M0H, M0L, N_PROD, E_PP);
    // 4: G1 it layer1 -> P1
    hmma_gemm<128, 256, true, true><<<148, 512, SM_DUAL>>>(
        M0H, M0L, xPH, xPL, it_W1l, it_W1r, it_b1, nullptr, P1H, P1L, N_PROD);
    // 5: G2 us layer1 -> P2
    hmma_gemm<128, 256, true, true><<<148, 512, SM_DUAL>>>(
        M0H, M0L, xPH, xPL, us_W1l, us_W1r, us_b1, nullptr, P2H, P2L, N_PROD);
    // 6: M0 = mean_pp(P1)
    agg_mean<true><<<aggP_grid, 256>>>(nullptr, P1H, P1L, offP, csrP,
                                       M0H, M0L, N_PROD, E_PP);
    // 7: G3 it layer2 -> P3
    hmma_gemm<128, 256, true, true><<<148, 512, SM_DUAL>>>(
        M0H, M0L, P1H, P1L, it_W2l, it_W2r, it_b2, nullptr, P3H, P3L, N_PROD);
    // 8: G4 it linear -> zprod
    hmma_gemm<64, 128, false, false><<<148, 512, SM_SNGL>>>(
        P3H, P3L, nullptr, nullptr, it_Wlin, nullptr, it_blin, zprod, nullptr, nullptr, N_PROD);
    // 9: M0 = mean_pc(x_prod)
    agg_mean<false><<<aggC_grid, 256>>>(x_prod, nullptr, nullptr, offC, csrC,
                                        M0H, M0L, N_CUST, E_PC);
    // 10: G5 us layer2 -> C1
    hmma_gemm<128, 256, true, true><<<148, 512, SM_DUAL>>>(
        M0H, M0L, xCH, xCL, us_W2l, us_W2r, us_b2, nullptr, C1H, C1L, N_CUST);
    // 11: M0 = mean_pc(P2)
    agg_mean<true><<<aggC_grid, 256>>>(nullptr, P2H, P2L, offC, csrC,
                                       M0H, M0L, N_CUST, E_PC);
    // 12: G6 us layer3 -> C2
    hmma_gemm<128, 256, true, true><<<148, 512, SM_DUAL>>>(
        M0H, M0L, C1H, C1L, us_W3l, us_W3r, us_b3, nullptr, C2H, C2L, N_CUST);
    // 13: G7 us linear -> zcust
    hmma_gemm<64, 128, false, false><<<148, 512, SM_SNGL>>>(
        C2H, C2L, nullptr, nullptr, us_Wlin, nullptr, us_blin, zcust, nullptr, nullptr, N_CUST);

    // 14: decoder
    decoder_kernel<<<296, 512, SM_DEC>>>(zcust, zprod, eli, eli + E_LB,
                                         de_W1, de_b1, de_W2, de_b2,
                                         (float*)d_out, E_LB);

    // 15: restore zero invariant
    k_tail_zero<<<(N_PROD + 255) / 256, 256>>>();
}

// round 8
// speedup vs baseline: 1.2340x; 1.0746x over previous
#include <cuda_runtime.h>
#include <cuda_bf16.h>
#include <cstdint>

#define N_PROD 100000
#define N_CUST 50000
#define HID    128
#define DOUT   64
#define E_PP   800000
#define E_PC   800000
#define E_LB   400000

typedef unsigned long long u64;
typedef __nv_bfloat16 bf16;

#define SWZ(x) ((x) ^ (((x) >> 3) & 0x70))

__device__ __forceinline__ uint32_t smem_u32(const void* p) {
    uint32_t a;
    asm("{ .reg .u64 t; cvta.to.shared.u64 t, %1; cvt.u32.u64 %0, t; }" : "=r"(a) : "l"(p));
    return a;
}
__device__ __forceinline__ void cp16(uint32_t dst, const void* src, int sz) {
    asm volatile("cp.async.cg.shared.global [%0],[%1],16,%2;"
                 :: "r"(dst), "l"(src), "r"(sz));
}
#define CP_COMMIT() asm volatile("cp.async.commit_group;" ::: "memory")
#define CP_WAIT1()  asm volatile("cp.async.wait_group 1;" ::: "memory")
#define CP_WAIT0()  asm volatile("cp.async.wait_group 0;" ::: "memory")

__device__ __forceinline__ void ldm4(uint32_t addr, uint32_t* r) {
    asm volatile("ldmatrix.sync.aligned.m8n8.x4.shared.b16 {%0,%1,%2,%3},[%4];"
                 : "=r"(r[0]), "=r"(r[1]), "=r"(r[2]), "=r"(r[3]) : "r"(addr));
}
__device__ __forceinline__ void mma16816(float* d, const uint32_t* a,
                                         uint32_t b0, uint32_t b1) {
    asm volatile(
        "mma.sync.aligned.m16n8k16.row.col.f32.bf16.bf16.f32 "
        "{%0,%1,%2,%3},{%4,%5,%6,%7},{%8,%9},{%0,%1,%2,%3};"
        : "+f"(d[0]), "+f"(d[1]), "+f"(d[2]), "+f"(d[3])
        : "r"(a[0]), "r"(a[1]), "r"(a[2]), "r"(a[3]), "r"(b0), "r"(b1));
}
__device__ __forceinline__ void split1(float w, unsigned short& h, unsigned short& l) {
    bf16 hb = __float2bfloat16_rn(w);
    bf16 lb = __float2bfloat16_rn(w - __bfloat162float(hb));
    h = __bfloat16_as_ushort(hb);
    l = __bfloat16_as_ushort(lb);
}
__device__ __forceinline__ void split4(float a0, float a1, float a2, float a3,
                                       u64& hp, u64& lp) {
    unsigned short h0, l0, h1, l1, h2, l2, h3, l3;
    split1(a0, h0, l0); split1(a1, h1, l1);
    split1(a2, h2, l2); split1(a3, h3, l3);
    hp = (u64)h0 | ((u64)h1 << 16) | ((u64)h2 << 32) | ((u64)h3 << 48);
    lp = (u64)l0 | ((u64)l1 << 16) | ((u64)l2 << 32) | ((u64)l3 << 48);
}
// f32x2 helpers (decoder)
__device__ __forceinline__ u64 pack2(float lo, float hi) {
    u64 r; asm("mov.b64 %0,{%1,%2};" : "=l"(r) : "f"(lo), "f"(hi)); return r;
}
__device__ __forceinline__ u64 dup2(float a) {
    u64 r; asm("mov.b64 %0,{%1,%1};" : "=l"(r) : "f"(a)); return r;
}
__device__ __forceinline__ void fma2(u64& d, u64 a, u64 b) {
    asm("fma.rn.f32x2 %0,%1,%2,%0;" : "+l"(d) : "l"(a), "l"(b));
}
__device__ __forceinline__ void unpack2(u64 v, float& lo, float& hi) {
    asm("mov.b64 {%0,%1},%2;" : "=f"(lo), "=f"(hi) : "l"(v));
}

// ---------------------------------------------------------------------------
// Scratch planes
// ---------------------------------------------------------------------------
__device__ bf16 g_xPH[(size_t)N_PROD * HID];
__device__ bf16 g_xPL[(size_t)N_PROD * HID];
__device__ bf16 g_xCH[(size_t)N_CUST * HID];
__device__ bf16 g_xCL[(size_t)N_CUST * HID];
__device__ bf16 g_M0H[(size_t)N_PROD * HID];   // current mean (reused)
__device__ bf16 g_M0L[(size_t)N_PROD * HID];
__device__ bf16 g_P1H[(size_t)N_PROD * HID];
__device__ bf16 g_P1L[(size_t)N_PROD * HID];
__device__ bf16 g_P2H[(size_t)N_PROD * HID];
__device__ bf16 g_P2L[(size_t)N_PROD * HID];
__device__ bf16 g_C1H[(size_t)N_CUST * HID];
__device__ bf16 g_C1L[(size_t)N_CUST * HID];
__device__ float g_zprod[(size_t)N_PROD * DOUT];
__device__ float g_zcust[(size_t)N_CUST * DOUT];

__device__ int g_cntP[N_PROD];
__device__ int g_cntC[N_CUST];
__device__ int g_offP[N_PROD];
__device__ int g_curP[N_PROD];
__device__ int g_csrP[E_PP];
__device__ int g_offC[N_CUST];
__device__ int g_curC[N_CUST];
__device__ int g_csrC[E_PC];
__device__ u64 g_lbP[128];
__device__ u64 g_lbC[64];

// ---------------------------------------------------------------------------
// Launch 0: convert x -> planes AND count both edge histograms
// ---------------------------------------------------------------------------
__global__ void k_pre(const float* __restrict__ xp, const float* __restrict__ xc,
                      const int* __restrict__ dstP, const int* __restrict__ dstC) {
    const int NP4 = N_PROD * HID / 4;
    const int NC4 = N_CUST * HID / 4;
    int i = blockIdx.x * blockDim.x + threadIdx.x;
    if (i < NP4 + NC4) {
        const float* src; bf16 *dh, *dl; int o;
        if (i < NP4) { src = xp; dh = g_xPH; dl = g_xPL; o = i; }
        else { src = xc; dh = g_xCH; dl = g_xCL; o = i - NP4; }
        float4 v = *reinterpret_cast<const float4*>(src + (size_t)o * 4);
        u64 hp, lp; split4(v.x, v.y, v.z, v.w, hp, lp);
        *reinterpret_cast<u64*>(dh + (size_t)o * 4) = hp;
        *reinterpret_cast<u64*>(dl + (size_t)o * 4) = lp;
        return;
    }
    int j = i - (NP4 + NC4);
    if (j < E_PP) { atomicAdd(&g_cntP[dstP[j]], 1); return; }
    j -= E_PP;
    if (j < E_PC) atomicAdd(&g_cntC[dstC[j]], 1);
}

// ---------------------------------------------------------------------------
// Launch 1: decoupled-lookback scan (P and C segments)
// ---------------------------------------------------------------------------
__device__ void scan_seg(const int* __restrict__ cnt, int n,
                         int* __restrict__ off, int* __restrict__ cur,
                         u64* __restrict__ st, int bid) {
    __shared__ int s[1024];
    __shared__ int s_prefix;
    int tx = threadIdx.x;
    int gid = bid * 1024 + tx;
    int v = (gid < n) ? cnt[gid] : 0;
    s[tx] = v;
    __syncthreads();
#pragma unroll
    for (int d = 1; d < 1024; d <<= 1) {
        int t = (tx >= d) ? s[tx - d] : 0;
        __syncthreads();
        s[tx] += t;
        __syncthreads();
    }
    int incl = s[tx];
    int total = s[1023];
    if (tx == 0) {
        if (bid == 0) {
            s_prefix = 0;
            atomicExch(st, ((u64)(unsigned)total << 32) | 2ULL);
        } else {
            atomicExch(st + bid, ((u64)(unsigned)total << 32) | 1ULL);
            int run = 0, j = bid - 1;
            while (true) {
                u64 x;
                do { x = atomicAdd(st + j, 0ULL); } while ((x & 3ULL) == 0ULL);
                run += (int)(unsigned)(x >> 32);
                if ((x & 3ULL) == 2ULL) break;
                j--;
            }
            s_prefix = run;
            atomicExch(st + bid, ((u64)(unsigned)(run + total) << 32) | 2ULL);
        }
    }
    __syncthreads();
    if (gid < n) {
        int e = s_prefix + incl - v;
        off[gid] = e;
        cur[gid] = e;
    }
}

__global__ void k_scan2x() {
    const int nbP = (N_PROD + 1023) / 1024;
    if ((int)blockIdx.x < nbP)
        scan_seg(g_cntP, N_PROD, g_offP, g_curP, g_lbP, blockIdx.x);
    else
        scan_seg(g_cntC, N_CUST, g_offC, g_curC, g_lbC, blockIdx.x - nbP);
}

__global__ void k_fill2x(const int* __restrict__ eP, const int* __restrict__ eC) {
    int e = blockIdx.x * blockDim.x + threadIdx.x;
    if (e < E_PP) {
        int d = eP[E_PP + e];
        int p = atomicAdd(&g_curP[d], 1);
        g_csrP[p] = eP[e];
    } else if (e < E_PP + E_PC) {
        int j = e - E_PP;
        int d = eC[E_PC + j];
        int p = atomicAdd(&g_curC[d], 1);
        g_csrC[p] = eC[j];
    }
}

__global__ void k_tail_zero() {
    int i = blockIdx.x * blockDim.x + threadIdx.x;
    if (i < N_PROD) g_cntP[i] = 0;
    if (i < N_CUST) g_cntC[i] = 0;
    if (i < 128) g_lbP[i] = 0;
    if (i < 64) g_lbC[i] = 0;
}

// ---------------------------------------------------------------------------
// Standalone mean aggregation: one warp per node, unroll x4 for MLP
// ---------------------------------------------------------------------------
template <bool IN_PLANES>
__global__ void agg_mean(const float* __restrict__ xf,
                         const bf16* __restrict__ xh, const bf16* __restrict__ xl,
                         const int* __restrict__ off, const int* __restrict__ csr,
                         bf16* __restrict__ oh, bf16* __restrict__ ol,
                         int n, int E) {
    int w = (blockIdx.x * blockDim.x + threadIdx.x) >> 5;
    int lane = threadIdx.x & 31;
    if (w >= n) return;
    int beg = off[w];
    int end = (w + 1 < n) ? off[w + 1] : E;
    float a0 = 0.f, a1 = 0.f, a2 = 0.f, a3 = 0.f;
    int j = beg;
    if (IN_PLANES) {
        for (; j + 3 < end; j += 4) {
            int s0 = csr[j], s1 = csr[j + 1], s2 = csr[j + 2], s3 = csr[j + 3];
            u64 h0 = __ldg(reinterpret_cast<const u64*>(xh + (size_t)s0 * HID + lane * 4));
            u64 h1 = __ldg(reinterpret_cast<const u64*>(xh + (size_t)s1 * HID + lane * 4));
            u64 h2 = __ldg(reinterpret_cast<const u64*>(xh + (size_t)s2 * HID + lane * 4));
            u64 h3 = __ldg(reinterpret_cast<const u64*>(xh + (size_t)s3 * HID + lane * 4));
            u64 l0 = __ldg(reinterpret_cast<const u64*>(xl + (size_t)s0 * HID + lane * 4));
            u64 l1 = __ldg(reinterpret_cast<const u64*>(xl + (size_t)s1 * HID + lane * 4));
            u64 l2 = __ldg(reinterpret_cast<const u64*>(xl + (size_t)s2 * HID + lane * 4));
            u64 l3 = __ldg(reinterpret_cast<const u64*>(xl + (size_t)s3 * HID + lane * 4));
#define ACCP(hp, lp) do { \
            ushort4 hu = *reinterpret_cast<ushort4*>(&hp); \
            ushort4 lu = *reinterpret_cast<ushort4*>(&lp); \
            a0 += __bfloat162float(__ushort_as_bfloat16(hu.x)) + __bfloat162float(__ushort_as_bfloat16(lu.x)); \
            a1 += __bfloat162float(__ushort_as_bfloat16(hu.y)) + __bfloat162float(__ushort_as_bfloat16(lu.y)); \
            a2 += __bfloat162float(__ushort_as_bfloat16(hu.z)) + __bfloat162float(__ushort_as_bfloat16(lu.z)); \
            a3 += __bfloat162float(__ushort_as_bfloat16(hu.w)) + __bfloat162float(__ushort_as_bfloat16(lu.w)); \
        } while (0)
            ACCP(h0, l0); ACCP(h1, l1); ACCP(h2, l2); ACCP(h3, l3);
        }
        for (; j < end; j++) {
            int s0 = csr[j];
            u64 hp = __ldg(reinterpret_cast<const u64*>(xh + (size_t)s0 * HID + lane * 4));
            u64 lp = __ldg(reinterpret_cast<const u64*>(xl + (size_t)s0 * HID + lane * 4));
            ACCP(hp, lp);
        }
#undef ACCP
    } else {
        for (; j + 3 < end; j += 4) {
            int s0 = csr[j], s1 = csr[j + 1], s2 = csr[j + 2], s3 = csr[j + 3];
            float4 v0 = __ldg(reinterpret_cast<const float4*>(xf + (size_t)s0 * HID + lane * 4));
            float4 v1 = __ldg(reinterpret_cast<const float4*>(xf + (size_t)s1 * HID + lane * 4));
            float4 v2 = __ldg(reinterpret_cast<const float4*>(xf + (size_t)s2 * HID + lane * 4));
            float4 v3 = __ldg(reinterpret_cast<const float4*>(xf + (size_t)s3 * HID + lane * 4));
            a0 += (v0.x + v1.x) + (v2.x + v3.x);
            a1 += (v0.y + v1.y) + (v2.y + v3.y);
            a2 += (v0.z + v1.z) + (v2.z + v3.z);
            a3 += (v0.w + v1.w) + (v2.w + v3.w);
        }
        for (; j < end; j++) {
            int s0 = csr[j];
            float4 v = __ldg(reinterpret_cast<const float4*>(xf + (size_t)s0 * HID + lane * 4));
            a0 += v.x; a1 += v.y; a2 += v.z; a3 += v.w;
        }
    }
    float sc = (end > beg) ? 1.0f / (float)(end - beg) : 0.f;
    a0 *= sc; a1 *= sc; a2 *= sc; a3 *= sc;
    u64 hp, lp; split4(a0, a1, a2, a3, hp, lp);
    *reinterpret_cast<u64*>(oh + (size_t)w * HID + lane * 4) = hp;
    *reinterpret_cast<u64*>(ol + (size_t)w * HID + lane * 4) = lp;
}

// ---------------------------------------------------------------------------
// Dual HMMA bf16x3 GEMM, K=256, N=128, MTILE=128, relu.
//   FUSE2=false: write bf16 hi/lo planes.
//   FUSE2=true : restage relu'd tile into SMEM and run second GEMM
//                (K2=128 -> N2=64 with W2,b2), write fp32 out2. No intermediate.
// SMEM map (bytes):
//   [0..512)      bias1 (128 f32)      [512..768) bias2 (64 f32)
//   [1024..66560) A bufs: 2 x { hi[16384], lo[16384] }
//   [66560..197632) B1 frags (hi 65536 | lo 65536)
//   [197632..230400) B2 frags (hi 16384 | lo 16384)   (FUSE2 only)
// ---------------------------------------------------------------------------
template <bool FUSE2>
__global__ __launch_bounds__(512, 1) void hmma_dual(
    const bf16* __restrict__ AH, const bf16* __restrict__ AL,
    const bf16* __restrict__ XH, const bf16* __restrict__ XL,
    const float* __restrict__ Wl, const float* __restrict__ Wr,
    const float* __restrict__ bias,
    const float* __restrict__ W2, const float* __restrict__ b2,
    bf16* __restrict__ outH, bf16* __restrict__ outL,
    float* __restrict__ out2,
    int n)
{
    constexpr int KSTEPS = 16;
    constexpr int NF2    = 8;
    constexpr int MTILE  = 128;
    constexpr int CHUNKB = MTILE * 128;     // 16384
    constexpr int BUFB   = 2 * CHUNKB;      // 32768
    constexpr int BOFF   = 1024 + 2 * BUFB; // 66560
    constexpr int BSPLIT = KSTEPS * NF2 * 32 * 16;  // 65536
    constexpr int BOFF2  = BOFF + 2 * BSPLIT;       // 197632
    constexpr int BSPLIT2 = 8 * 4 * 32 * 16;        // 16384
    constexpr int NCHUNK = 4;
    constexpr int CPOPS  = MTILE * 8 * 2;   // 2048

    extern __shared__ char smem[];
    const uint32_t sb = smem_u32(smem);
    const int tid = threadIdx.x;
    const int w = tid >> 5, lane = tid & 31;
    const int g     = w & 1;
    const int warpM = (w >> 1) * 16;

    float* bs = (float*)smem;
    float* bs2 = (float*)(smem + 512);
    if (tid < 128) bs[tid] = bias[tid];
    if (FUSE2 && tid >= 128 && tid < 192) bs2[tid - 128] = b2[tid - 128];

    // B1 preload in fragment order (hi then lo)
    for (int idx = tid; idx < 2 * KSTEPS * NF2 * 32; idx += 512) {
        int l = idx & 31;
        int rest = idx >> 5;
        int nfp = rest % NF2;
        int rest2 = rest / NF2;
        int ks = rest2 % KSTEPS;
        int s = rest2 / KSTEPS;
        uint32_t vals[4];
#pragma unroll
        for (int e = 0; e < 2; e++) {
            int nf = nfp * 2 + e;
            int nn = nf * 8 + (l >> 2);
            int k0 = ks * 16 + (l & 3) * 2;
            const float* wp = Wl;
            int kk = k0;
            if (k0 >= 128) { wp = Wr; kk = k0 - 128; }
            float2 wa = *reinterpret_cast<const float2*>(wp + nn * 128 + kk);
            float2 wb = *reinterpret_cast<const float2*>(wp + nn * 128 + kk + 8);
            unsigned short h, lo, r00, r01, r10, r11;
            split1(wa.x, h, lo); r00 = s ? lo : h;
            split1(wa.y, h, lo); r01 = s ? lo : h;
            split1(wb.x, h, lo); r10 = s ? lo : h;
            split1(wb.y, h, lo); r11 = s ? lo : h;
            vals[e * 2 + 0] = (uint32_t)r00 | ((uint32_t)r01 << 16);
            vals[e * 2 + 1] = (uint32_t)r10 | ((uint32_t)r11 << 16);
        }
        *reinterpret_cast<uint4*>(smem + BOFF + (size_t)idx * 16) =
            make_uint4(vals[0], vals[1], vals[2], vals[3]);
    }
    // B2 preload (FUSE2): 64x128 weight, KSTEPS2=8, NF2_2=4
    if (FUSE2) {
        for (int idx = tid; idx < 2 * 8 * 4 * 32; idx += 512) {
            int l = idx & 31;
            int rest = idx >> 5;
            int nfp = rest % 4;
            int rest2 = rest / 4;
            int ks = rest2 % 8;
            int s = rest2 / 8;
            uint32_t vals[4];
#pragma unroll
            for (int e = 0; e < 2; e++) {
                int nf = nfp * 2 + e;
                int nn = nf * 8 + (l >> 2);
                int k0 = ks * 16 + (l & 3) * 2;
                float2 wa = *reinterpret_cast<const float2*>(W2 + nn * 128 + k0);
                float2 wb = *reinterpret_cast<const float2*>(W2 + nn * 128 + k0 + 8);
                unsigned short h, lo, r00, r01, r10, r11;
                split1(wa.x, h, lo); r00 = s ? lo : h;
                split1(wa.y, h, lo); r01 = s ? lo : h;
                split1(wb.x, h, lo); r10 = s ? lo : h;
                split1(wb.y, h, lo); r11 = s ? lo : h;
                vals[e * 2 + 0] = (uint32_t)r00 | ((uint32_t)r01 << 16);
                vals[e * 2 + 1] = (uint32_t)r10 | ((uint32_t)r11 << 16);
            }
            *reinterpret_cast<uint4*>(smem + BOFF2 + (size_t)idx * 16) =
                make_uint4(vals[0], vals[1], vals[2], vals[3]);
        }
    }
    __syncthreads();

    const int ntiles = (n + MTILE - 1) / MTILE;

    for (int tt = blockIdx.x; tt < ntiles; tt += gridDim.x) {
        float acc[8][4];
#pragma unroll
        for (int nf = 0; nf < 8; nf++)
#pragma unroll
            for (int q = 0; q < 4; q++) acc[nf][q] = 0.f;

        auto stage = [&](int c, int b) {
            const bf16* sh = (c >= 2) ? XH : AH;
            const bf16* sl = (c >= 2) ? XL : AL;
            const int colbase = (c & 1) * 64;
#pragma unroll
            for (int it = 0; it < CPOPS / 512; it++) {
                int u = tid + it * 512;
                int plane = u / (MTILE * 8);
                int rem = u % (MTILE * 8);
                int r0 = rem >> 3;
                int ch = rem & 7;
                const bf16* src = plane ? sl : sh;
                int gr = tt * MTILE + r0;
                uint32_t dst = sb + 1024 + b * BUFB + plane * CHUNKB +
                               SWZ((uint32_t)(r0 * 128 + ch * 16));
                const void* gp = src + (size_t)gr * 128 + colbase + ch * 8;
                cp16(dst, gp, (gr < n) ? 16 : 0);
            }
            CP_COMMIT();
        };

        stage(0, 0);

        for (int c = 0; c < NCHUNK; c++) {
            if (c + 1 < NCHUNK) { stage(c + 1, (c + 1) & 1); CP_WAIT1(); }
            else CP_WAIT0();
            __syncthreads();

            const uint32_t abase = sb + 1024 + (c & 1) * BUFB;
#pragma unroll
            for (int ksl = 0; ksl < 4; ksl++) {
                const int ks = c * 4 + ksl;
                uint32_t ah[4], al[4];
                {
                    int arow = warpM + (lane & 15);
                    int colb = ksl * 32 + ((lane >> 4) << 4);
                    uint32_t o = SWZ((uint32_t)(arow * 128 + colb));
                    ldm4(abase + o, ah);
                    ldm4(abase + CHUNKB + o, al);
                }
                uint4 Bq[4];
                {
                    size_t base = (size_t)BOFF +
                        ((size_t)(ks * NF2 + g * 4) * 32 + lane) * 16;
#pragma unroll
                    for (int p = 0; p < 4; p++)
                        Bq[p] = *reinterpret_cast<const uint4*>(smem + base + p * 512);
                }
#pragma unroll
                for (int nf = 0; nf < 8; nf++) {
                    uint32_t b0 = (nf & 1) ? Bq[nf >> 1].z : Bq[nf >> 1].x;
                    uint32_t b1 = (nf & 1) ? Bq[nf >> 1].w : Bq[nf >> 1].y;
                    mma16816(acc[nf], ah, b0, b1);
                }
#pragma unroll
                for (int nf = 0; nf < 8; nf++) {
                    uint32_t b0 = (nf & 1) ? Bq[nf >> 1].z : Bq[nf >> 1].x;
                    uint32_t b1 = (nf & 1) ? Bq[nf >> 1].w : Bq[nf >> 1].y;
                    mma16816(acc[nf], al, b0, b1);
                }
                {
                    size_t base = (size_t)BOFF + BSPLIT +
                        ((size_t)(ks * NF2 + g * 4) * 32 + lane) * 16;
#pragma unroll
                    for (int p = 0; p < 4; p++)
                        Bq[p] = *reinterpret_cast<const uint4*>(smem + base + p * 512);
                }
#pragma unroll
                for (int nf = 0; nf < 8; nf++) {
                    uint32_t b0 = (nf & 1) ? Bq[nf >> 1].z : Bq[nf >> 1].x;
                    uint32_t b1 = (nf & 1) ? Bq[nf >> 1].w : Bq[nf >> 1].y;
                    mma16816(acc[nf], ah, b0, b1);
                }
            }
            __syncthreads();
        }

        if (!FUSE2) {
            // epilogue: relu + split -> plane gmem
            int rbase = tt * MTILE + warpM + (lane >> 2);
#pragma unroll
            for (int nf = 0; nf < 8; nf++) {
                int col = g * 64 + nf * 8 + (lane & 3) * 2;
#pragma unroll
                for (int hh = 0; hh < 2; hh++) {
                    int row = rbase + hh * 8;
                    if (row < n) {
                        float ox = fmaxf(acc[nf][hh * 2 + 0] + bs[col], 0.f);
                        float oy = fmaxf(acc[nf][hh * 2 + 1] + bs[col + 1], 0.f);
                        unsigned short h0, l0, h1, l1;
                        split1(ox, h0, l0); split1(oy, h1, l1);
                        *reinterpret_cast<uint32_t*>(outH + (size_t)row * 128 + col) =
                            (uint32_t)h0 | ((uint32_t)h1 << 16);
                        *reinterpret_cast<uint32_t*>(outL + (size_t)row * 128 + col) =
                            (uint32_t)l0 | ((uint32_t)l1 << 16);
                    }
                }
            }
        } else {
            // restage relu'd tile into A buffers as full-K (128) planes:
            // cols 0-63 -> buf0, cols 64-127 -> buf1
            {
                int rl = warpM + (lane >> 2);
#pragma unroll
                for (int nf = 0; nf < 8; nf++) {
                    int col = g * 64 + nf * 8 + (lane & 3) * 2;
#pragma unroll
                    for (int hh = 0; hh < 2; hh++) {
                        int r = rl + hh * 8;
                        float ox = fmaxf(acc[nf][hh * 2 + 0] + bs[col], 0.f);
                        float oy = fmaxf(acc[nf][hh * 2 + 1] + bs[col + 1], 0.f);
                        unsigned short h0, l0, h1, l1;
                        split1(ox, h0, l0); split1(oy, h1, l1);
                        uint32_t off = SWZ((uint32_t)(r * 128 + (col & 63) * 2));
                        *reinterpret_cast<uint32_t*>(smem + 1024 + g * BUFB + off) =
                            (uint32_t)h0 | ((uint32_t)h1 << 16);
                        *reinterpret_cast<uint32_t*>(smem + 1024 + g * BUFB + CHUNKB + off) =
                            (uint32_t)l0 | ((uint32_t)l1 << 16);
                    }
                }
            }
            __syncthreads();

            // second GEMM: K2=128 (resident), N2=64; warp tile 16 x 32
            float acc2[4][4];
#pragma unroll
            for (int nf = 0; nf < 4; nf++)
#pragma unroll
                for (int q = 0; q < 4; q++) acc2[nf][q] = 0.f;

#pragma unroll
            for (int ks2 = 0; ks2 < 8; ks2++) {
                const int chunk = ks2 >> 2, ksl2 = ks2 & 3;
                const uint32_t abase2 = sb + 1024 + chunk * BUFB;
                uint32_t ah2[4], al2[4];
                {
                    int arow = warpM + (lane & 15);
                    int colb = ksl2 * 32 + ((lane >> 4) << 4);
                    uint32_t o = SWZ((uint32_t)(arow * 128 + colb));
                    ldm4(abase2 + o, ah2);
                    ldm4(abase2 + CHUNKB + o, al2);
                }
                uint4 Bq[2];
                {
                    size_t base = (size_t)BOFF2 +
                        ((size_t)(ks2 * 4 + g * 2) * 32 + lane) * 16;
                    Bq[0] = *reinterpret_cast<const uint4*>(smem + base);
                    Bq[1] = *reinterpret_cast<const uint4*>(smem + base + 512);
                }
#pragma unroll
                for (int nf = 0; nf < 4; nf++) {
                    uint32_t b0 = (nf & 1) ? Bq[nf >> 1].z : Bq[nf >> 1].x;
                    uint32_t b1 = (nf & 1) ? Bq[nf >> 1].w : Bq[nf >> 1].y;
                    mma16816(acc2[nf], ah2, b0, b1);
                }
#pragma unroll
                for (int nf = 0; nf < 4; nf++) {
                    uint32_t b0 = (nf & 1) ? Bq[nf >> 1].z : Bq[nf >> 1].x;
                    uint32_t b1 = (nf & 1) ? Bq[nf >> 1].w : Bq[nf >> 1].y;
                    mma16816(acc2[nf], al2, b0, b1);
                }
                {
                    size_t base = (size_t)BOFF2 + BSPLIT2 +
                        ((size_t)(ks2 * 4 + g * 2) * 32 + lane) * 16;
                    Bq[0] = *reinterpret_cast<const uint4*>(smem + base);
                    Bq[1] = *reinterpret_cast<const uint4*>(smem + base + 512);
                }
#pragma unroll
                for (int nf = 0; nf < 4; nf++) {
                    uint32_t b0 = (nf & 1) ? Bq[nf >> 1].z : Bq[nf >> 1].x;
                    uint32_t b1 = (nf & 1) ? Bq[nf >> 1].w : Bq[nf >> 1].y;
                    mma16816(acc2[nf], ah2, b0, b1);
                }
            }

            // epilogue2: fp32 z output
            {
                int rbase = tt * MTILE + warpM + (lane >> 2);
#pragma unroll
                for (int nf = 0; nf < 4; nf++) {
                    int col = g * 32 + nf * 8 + (lane & 3) * 2;
#pragma unroll
                    for (int hh = 0; hh < 2; hh++) {
                        int row = rbase + hh * 8;
                        if (row < n) {
                            float2 o;
                            o.x = acc2[nf][hh * 2 + 0] + bs2[col];
                            o.y = acc2[nf][hh * 2 + 1] + bs2[col + 1];
                            *reinterpret_cast<float2*>(out2 + (size_t)row * 64 + col) = o;
                        }
                    }
                }
            }
            __syncthreads();   // protect A buffers before next tile's staging
        }
    }
}

// ---------------------------------------------------------------------------
// SIMT decoder (f32x2 FMAs)
// ---------------------------------------------------------------------------
__launch_bounds__(512, 1)
__global__ void decoder_kernel(const float* __restrict__ zc, const float* __restrict__ zp,
                               const int* __restrict__ row, const int* __restrict__ col,
                               const float* __restrict__ W1, const float* __restrict__ b1,
                               const float* __restrict__ w2, const float* __restrict__ b2,
                               float* __restrict__ out, int nE) {
    constexpr int NOP = 68;
    constexpr int R = 8;
    extern __shared__ float smemf[];
    float* Ws = smemf;
    float* stage = smemf + 128 * NOP;

    int tid = threadIdx.x;
    for (int i = tid; i < 64 * 128; i += 512) {
        int o = i >> 7, k = i & 127;
        Ws[k * NOP + o] = W1[i];
    }
    __syncthreads();

    const int w = tid >> 5, lane = tid & 31;
    float* Zs = stage + w * (R * 128);

    float2 b1v = __ldg(reinterpret_cast<const float2*>(b1 + lane * 2));
    u64 bofs = pack2(b1v.x, b1v.y);
    float w20 = __ldg(w2 + lane * 2), w21 = __ldg(w2 + lane * 2 + 1);
    float b2v = __ldg(b2);

    for (int base = (blockIdx.x * 16 + w) * R; base < nE; base += gridDim.x * 16 * R) {
#pragma unroll
        for (int r = 0; r < R; r++) {
            int e = base + r;
            float4 v = make_float4(0.f, 0.f, 0.f, 0.f);
            if (e < nE) {
                if (lane < 16) {
                    int ri = __ldg(row + e);
                    v = *reinterpret_cast<const float4*>(zc + (size_t)ri * DOUT + lane * 4);
                } else {
                    int ci = __ldg(col + e);
                    v = *reinterpret_cast<const float4*>(zp + (size_t)ci * DOUT + (lane - 16) * 4);
                }
            }
            *reinterpret_cast<float4*>(Zs + r * 128 + lane * 4) = v;
        }
        __syncwarp();

        u64 acc[R];
#pragma unroll
        for (int r = 0; r < R; r++) acc[r] = bofs;

        for (int k0 = 0; k0 < 128; k0 += 4) {
            float4 z4[R];
#pragma unroll
            for (int r = 0; r < R; r++)
                z4[r] = *reinterpret_cast<const float4*>(Zs + r * 128 + k0);
#pragma unroll
            for (int kk = 0; kk < 4; kk++) {
                u64 wv = *reinterpret_cast<const u64*>(Ws + (k0 + kk) * NOP + lane * 2);
#pragma unroll
                for (int r = 0; r < R; r++) {
                    float z = (kk == 0) ? z4[r].x : (kk == 1) ? z4[r].y : (kk == 2) ? z4[r].z : z4[r].w;
                    u64 zd = dup2(z);
                    fma2(acc[r], zd, wv);
                }
            }
        }

#pragma unroll
        for (int r = 0; r < R; r++) {
            float h0, h1;
            unpack2(acc[r], h0, h1);
            h0 = fmaxf(h0, 0.f); h1 = fmaxf(h1, 0.f);
            float p = h0 * w20 + h1 * w21;
#pragma unroll
            for (int o = 16; o > 0; o >>= 1) p += __shfl_xor_sync(0xffffffff, p, o);
            if (lane == 0 && base + r < nE) out[base + r] = p + b2v;
        }
        __syncwarp();
    }
}

// ---------------------------------------------------------------------------
// Host orchestration
// ---------------------------------------------------------------------------
extern "C" void kernel_launch(void* const* d_in, const int* in_sizes, int n_in,
                              void* d_out, int out_size) {
    const float* x_prod = (const float*)d_in[0];
    const float* x_cust = (const float*)d_in[1];
    const int* pp = (const int*)d_in[2];
    const int* pc = (const int*)d_in[3];
    const int* eli = (const int*)d_in[4];

    bool sig = (in_sizes[6] == HID);
    const float* it_W1l = (const float*)d_in[5];
    const float* it_W1r = (const float*)d_in[sig ? 7 : 6];
    const float* it_b1  = (const float*)d_in[sig ? 6 : 7];
    const float* it_W2l = (const float*)d_in[8];
    const float* it_W2r = (const float*)d_in[sig ? 10 : 9];
    const float* it_b2  = (const float*)d_in[sig ? 9 : 10];
    const float* it_Wlin = (const float*)d_in[11];
    const float* it_blin = (const float*)d_in[12];
    const float* us_W1l = (const float*)d_in[13];
    const float* us_W1r = (const float*)d_in[sig ? 15 : 14];
    const float* us_b1  = (const float*)d_in[sig ? 14 : 15];
    const float* us_W2l = (const float*)d_in[16];
    const float* us_W2r = (const float*)d_in[sig ? 18 : 17];
    const float* us_b2  = (const float*)d_in[sig ? 17 : 18];
    const float* us_W3l = (const float*)d_in[19];
    const float* us_W3r = (const float*)d_in[sig ? 21 : 20];
    const float* us_b3  = (const float*)d_in[sig ? 20 : 21];
    const float* us_Wlin = (const float*)d_in[22];
    const float* us_blin = (const float*)d_in[23];
    const float* de_W1 = (const float*)d_in[24];
    const float* de_b1 = (const float*)d_in[25];
    const float* de_W2 = (const float*)d_in[26];
    const float* de_b2 = (const float*)d_in[27];

#define GETP(var, sym, T) T* var; cudaGetSymbolAddress((void**)&var, sym)
    GETP(xPH, g_xPH, bf16); GETP(xPL, g_xPL, bf16);
    GETP(xCH, g_xCH, bf16); GETP(xCL, g_xCL, bf16);
    GETP(M0H, g_M0H, bf16); GETP(M0L, g_M0L, bf16);
    GETP(P1H, g_P1H, bf16); GETP(P1L, g_P1L, bf16);
    GETP(P2H, g_P2H, bf16); GETP(P2L, g_P2L, bf16);
    GETP(C1H, g_C1H, bf16); GETP(C1L, g_C1L, bf16);
    GETP(zprod, g_zprod, float); GETP(zcust, g_zcust, float);
    GETP(offP, g_offP, int); GETP(csrP, g_csrP, int);
    GETP(offC, g_offC, int); GETP(csrC, g_csrC, int);
#undef GETP

    constexpr int SM_PLAIN = 1024 + 2 * 32768 + 2 * 65536;              // 197632
    constexpr int SM_FUSED = SM_PLAIN + 2 * 16384;                      // 230400
    constexpr int SM_DEC   = (128 * 68 + 16 * 8 * 128) * 4;
    cudaFuncSetAttribute((hmma_dual<false>),
                         cudaFuncAttributeMaxDynamicSharedMemorySize, SM_PLAIN);
    cudaFuncSetAttribute((hmma_dual<true>),
                         cudaFuncAttributeMaxDynamicSharedMemorySize, SM_FUSED);
    cudaFuncSetAttribute(decoder_kernel,
                         cudaFuncAttributeMaxDynamicSharedMemorySize, SM_DEC);

    const int nbP = (N_PROD + 1023) / 1024;
    const int nbC = (N_CUST + 1023) / 1024;
    const int PRE_ITEMS = (N_PROD + N_CUST) * HID / 4 + E_PP + E_PC;
    const int aggP_grid = (N_PROD * 32 + 255) / 256;
    const int aggC_grid = (N_CUST * 32 + 255) / 256;

    // 0-2: convert + counts, scans, fills
    k_pre<<<(PRE_ITEMS + 255) / 256, 256>>>(x_prod, x_cust, pp + E_PP, pc + E_PC);
    k_scan2x<<<nbP + nbC, 1024>>>();
    k_fill2x<<<(E_PP + E_PC + 255) / 256, 256>>>(pp, pc);

    // 3: M0 = mean_pp(x_prod)
    agg_mean<false><<<aggP_grid, 256>>>(x_prod, nullptr, nullptr, offP, csrP,
                                        M0H, M0L, N_PROD, E_PP);
    // 4: G1 it layer1 -> P1
    hmma_dual<false><<<148, 512, SM_PLAIN>>>(
        M0H, M0L, xPH, xPL, it_W1l, it_W1r, it_b1,
        nullptr, nullptr, P1H, P1L, nullptr, N_PROD);
    // 5: G2 us layer1 -> P2
    hmma_dual<false><<<148, 512, SM_PLAIN>>>(
        M0H, M0L, xPH, xPL, us_W1l, us_W1r, us_b1,
        nullptr, nullptr, P2H, P2L, nullptr, N_PROD);
    // 6: M0 = mean_pp(P1)
    agg_mean<true><<<aggP_grid, 256>>>(nullptr, P1H, P1L, offP, csrP,
                                       M0H, M0L, N_PROD, E_PP);
    // 7: G3+G4 fused: it layer2 + it linear -> zprod
    hmma_dual<true><<<148, 512, SM_FUSED>>>(
        M0H, M0L, P1H, P1L, it_W2l, it_W2r, it_b2,
        it_Wlin, it_blin, nullptr, nullptr, zprod, N_PROD);
    // 8: M0 = mean_pc(x_prod)
    agg_mean<false><<<aggC_grid, 256>>>(x_prod, nullptr, nullptr, offC, csrC,
                                        M0H, M0L, N_CUST, E_PC);
    // 9: G5 us layer2 -> C1
    hmma_dual<false><<<148, 512, SM_PLAIN>>>(
        M0H, M0L, xCH, xCL, us_W2l, us_W2r, us_b2,
        nullptr, nullptr, C1H, C1L, nullptr, N_CUST);
    // 10: M0 = mean_pc(P2)
    agg_mean<true><<<aggC_grid, 256>>>(nullptr, P2H, P2L, offC, csrC,
                                       M0H, M0L, N_CUST, E_PC);
    // 11: G6+G7 fused: us layer3 + us linear -> zcust
    hmma_dual<true><<<148, 512, SM_FUSED>>>(
        M0H, M0L, C1H, C1L, us_W3l, us_W3r, us_b3,
        us_Wlin, us_blin, nullptr, nullptr, zcust, N_CUST);

    // 12: decoder
    decoder_kernel<<<296, 512, SM_DEC>>>(zcust, zprod, eli, eli + E_LB,
                                         de_W1, de_b1, de_W2, de_b2,
                                         (float*)d_out, E_LB);

    // 13: restore zero invariant
    k_tail_zero<<<(N_PROD + 255) / 256, 256>>>();
}

// round 9
// speedup vs baseline: 1.6664x; 1.3504x over previous
#include <cuda_runtime.h>
#include <cuda_fp16.h>
#include <cstdint>

#define N_PROD 100000
#define N_CUST 50000
#define HID    128
#define DOUT   64
#define E_PP   800000
#define E_PC   800000
#define E_LB   400000

typedef unsigned long long u64;

#define SWZ(x) ((x) ^ (((x) >> 3) & 0x70))

__device__ __forceinline__ uint32_t smem_u32(const void* p) {
    uint32_t a;
    asm("{ .reg .u64 t; cvta.to.shared.u64 t, %1; cvt.u32.u64 %0, t; }" : "=r"(a) : "l"(p));
    return a;
}
__device__ __forceinline__ void cp16(uint32_t dst, const void* src, int sz) {
    asm volatile("cp.async.cg.shared.global [%0],[%1],16,%2;"
                 :: "r"(dst), "l"(src), "r"(sz));
}
#define CP_COMMIT() asm volatile("cp.async.commit_group;" ::: "memory")
#define CP_WAIT1()  asm volatile("cp.async.wait_group 1;" ::: "memory")
#define CP_WAIT0()  asm volatile("cp.async.wait_group 0;" ::: "memory")

__device__ __forceinline__ void ldm4(uint32_t addr, uint32_t* r) {
    asm volatile("ldmatrix.sync.aligned.m8n8.x4.shared.b16 {%0,%1,%2,%3},[%4];"
                 : "=r"(r[0]), "=r"(r[1]), "=r"(r[2]), "=r"(r[3]) : "r"(addr));
}
__device__ __forceinline__ void mma_f16(float* d, const uint32_t* a,
                                        uint32_t b0, uint32_t b1) {
    asm volatile(
        "mma.sync.aligned.m16n8k16.row.col.f32.f16.f16.f32 "
        "{%0,%1,%2,%3},{%4,%5,%6,%7},{%8,%9},{%0,%1,%2,%3};"
        : "+f"(d[0]), "+f"(d[1]), "+f"(d[2]), "+f"(d[3])
        : "r"(a[0]), "r"(a[1]), "r"(a[2]), "r"(a[3]), "r"(b0), "r"(b1));
}
// fp16 hi/lo weight split
__device__ __forceinline__ void split1h(float w, unsigned short& h, unsigned short& l) {
    __half hh = __float2half_rn(w);
    __half hl = __float2half_rn(w - __half2float(hh));
    h = __half_as_ushort(hh);
    l = __half_as_ushort(hl);
}
__device__ __forceinline__ u64 pack4h(float a0, float a1, float a2, float a3) {
    __half2 p0 = __floats2half2_rn(a0, a1);
    __half2 p1 = __floats2half2_rn(a2, a3);
    u64 r;
    asm("mov.b64 %0,{%1,%2};" : "=l"(r)
        : "r"(*reinterpret_cast<uint32_t*>(&p0)), "r"(*reinterpret_cast<uint32_t*>(&p1)));
    return r;
}
// f32x2 helpers (decoder)
__device__ __forceinline__ u64 pack2(float lo, float hi) {
    u64 r; asm("mov.b64 %0,{%1,%2};" : "=l"(r) : "f"(lo), "f"(hi)); return r;
}
__device__ __forceinline__ u64 dup2(float a) {
    u64 r; asm("mov.b64 %0,{%1,%1};" : "=l"(r) : "f"(a)); return r;
}
__device__ __forceinline__ void fma2(u64& d, u64 a, u64 b) {
    asm("fma.rn.f32x2 %0,%1,%2,%0;" : "+l"(d) : "l"(a), "l"(b));
}
__device__ __forceinline__ void unpack2(u64 v, float& lo, float& hi) {
    asm("mov.b64 {%0,%1},%2;" : "=f"(lo), "=f"(hi) : "l"(v));
}

// ---------------------------------------------------------------------------
// Scratch (fp16 activation planes)
// ---------------------------------------------------------------------------
__device__ __half g_xP[(size_t)N_PROD * HID];
__device__ __half g_xC[(size_t)N_CUST * HID];
__device__ __half g_M0[(size_t)N_PROD * HID];   // current mean (reused)
__device__ __half g_P1[(size_t)N_PROD * HID];
__device__ __half g_P2[(size_t)N_PROD * HID];
__device__ __half g_C1[(size_t)N_CUST * HID];
__device__ float g_zprod[(size_t)N_PROD * DOUT];
__device__ float g_zcust[(size_t)N_CUST * DOUT];

__device__ int g_cntP[N_PROD];
__device__ int g_cntC[N_CUST];
__device__ int g_offP[N_PROD];
__device__ int g_curP[N_PROD];
__device__ int g_csrP[E_PP];
__device__ int g_offC[N_CUST];
__device__ int g_curC[N_CUST];
__device__ int g_csrC[E_PC];
__device__ u64 g_lbP[128];
__device__ u64 g_lbC[64];

// ---------------------------------------------------------------------------
// Launch 0: convert x -> fp16 planes AND count both edge histograms
// ---------------------------------------------------------------------------
__global__ void k_pre(const float* __restrict__ xp, const float* __restrict__ xc,
                      const int* __restrict__ dstP, const int* __restrict__ dstC) {
    const int NP4 = N_PROD * HID / 4;
    const int NC4 = N_CUST * HID / 4;
    int i = blockIdx.x * blockDim.x + threadIdx.x;
    if (i < NP4 + NC4) {
        const float* src; __half* dh; int o;
        if (i < NP4) { src = xp; dh = g_xP; o = i; }
        else { src = xc; dh = g_xC; o = i - NP4; }
        float4 v = *reinterpret_cast<const float4*>(src + (size_t)o * 4);
        *reinterpret_cast<u64*>(dh + (size_t)o * 4) = pack4h(v.x, v.y, v.z, v.w);
        return;
    }
    int j = i - (NP4 + NC4);
    if (j < E_PP) { atomicAdd(&g_cntP[dstP[j]], 1); return; }
    j -= E_PP;
    if (j < E_PC) atomicAdd(&g_cntC[dstC[j]], 1);
}

// ---------------------------------------------------------------------------
// Launch 1: decoupled-lookback scan (P and C segments)
// ---------------------------------------------------------------------------
__device__ void scan_seg(const int* __restrict__ cnt, int n,
                         int* __restrict__ off, int* __restrict__ cur,
                         u64* __restrict__ st, int bid) {
    __shared__ int s[1024];
    __shared__ int s_prefix;
    int tx = threadIdx.x;
    int gid = bid * 1024 + tx;
    int v = (gid < n) ? cnt[gid] : 0;
    s[tx] = v;
    __syncthreads();
#pragma unroll
    for (int d = 1; d < 1024; d <<= 1) {
        int t = (tx >= d) ? s[tx - d] : 0;
        __syncthreads();
        s[tx] += t;
        __syncthreads();
    }
    int incl = s[tx];
    int total = s[1023];
    if (tx == 0) {
        if (bid == 0) {
            s_prefix = 0;
            atomicExch(st, ((u64)(unsigned)total << 32) | 2ULL);
        } else {
            atomicExch(st + bid, ((u64)(unsigned)total << 32) | 1ULL);
            int run = 0, j = bid - 1;
            while (true) {
                u64 x;
                do { x = atomicAdd(st + j, 0ULL); } while ((x & 3ULL) == 0ULL);
                run += (int)(unsigned)(x >> 32);
                if ((x & 3ULL) == 2ULL) break;
                j--;
            }
            s_prefix = run;
            atomicExch(st + bid, ((u64)(unsigned)(run + total) << 32) | 2ULL);
        }
    }
    __syncthreads();
    if (gid < n) {
        int e = s_prefix + incl - v;
        off[gid] = e;
        cur[gid] = e;
    }
}

__global__ void k_scan2x() {
    const int nbP = (N_PROD + 1023) / 1024;
    if ((int)blockIdx.x < nbP)
        scan_seg(g_cntP, N_PROD, g_offP, g_curP, g_lbP, blockIdx.x);
    else
        scan_seg(g_cntC, N_CUST, g_offC, g_curC, g_lbC, blockIdx.x - nbP);
}

__global__ void k_fill2x(const int* __restrict__ eP, const int* __restrict__ eC) {
    int e = blockIdx.x * blockDim.x + threadIdx.x;
    if (e < E_PP) {
        int d = eP[E_PP + e];
        int p = atomicAdd(&g_curP[d], 1);
        g_csrP[p] = eP[e];
    } else if (e < E_PP + E_PC) {
        int j = e - E_PP;
        int d = eC[E_PC + j];
        int p = atomicAdd(&g_curC[d], 1);
        g_csrC[p] = eC[j];
    }
}

__global__ void k_tail_zero() {
    int i = blockIdx.x * blockDim.x + threadIdx.x;
    if (i < N_PROD) g_cntP[i] = 0;
    if (i < N_CUST) g_cntC[i] = 0;
    if (i < 128) g_lbP[i] = 0;
    if (i < 64) g_lbC[i] = 0;
}

// ---------------------------------------------------------------------------
// Mean aggregation: fp16 in, fp16 out; one warp per node, unroll x4
// ---------------------------------------------------------------------------
__global__ void agg_mean(const __half* __restrict__ x,
                         const int* __restrict__ off, const int* __restrict__ csr,
                         __half* __restrict__ o, int n, int E) {
    int w = (blockIdx.x * blockDim.x + threadIdx.x) >> 5;
    int lane = threadIdx.x & 31;
    if (w >= n) return;
    int beg = off[w];
    int end = (w + 1 < n) ? off[w + 1] : E;
    float a0 = 0.f, a1 = 0.f, a2 = 0.f, a3 = 0.f;
    int j = beg;
#define ACCH(p) do { \
    uint2 uu = *reinterpret_cast<uint2*>(&p); \
    float2 f0 = __half22float2(*reinterpret_cast<__half2*>(&uu.x)); \
    float2 f1 = __half22float2(*reinterpret_cast<__half2*>(&uu.y)); \
    a0 += f0.x; a1 += f0.y; a2 += f1.x; a3 += f1.y; \
} while (0)
    for (; j + 3 < end; j += 4) {
        int s0 = csr[j], s1 = csr[j + 1], s2 = csr[j + 2], s3 = csr[j + 3];
        u64 p0 = __ldg(reinterpret_cast<const u64*>(x + (size_t)s0 * HID + lane * 4));
        u64 p1 = __ldg(reinterpret_cast<const u64*>(x + (size_t)s1 * HID + lane * 4));
        u64 p2 = __ldg(reinterpret_cast<const u64*>(x + (size_t)s2 * HID + lane * 4));
        u64 p3 = __ldg(reinterpret_cast<const u64*>(x + (size_t)s3 * HID + lane * 4));
        ACCH(p0); ACCH(p1); ACCH(p2); ACCH(p3);
    }
    for (; j < end; j++) {
        int s0 = csr[j];
        u64 p = __ldg(reinterpret_cast<const u64*>(x + (size_t)s0 * HID + lane * 4));
        ACCH(p);
    }
#undef ACCH
    float sc = (end > beg) ? 1.0f / (float)(end - beg) : 0.f;
    *reinterpret_cast<u64*>(o + (size_t)w * HID + lane * 4) =
        pack4h(a0 * sc, a1 * sc, a2 * sc, a3 * sc);
}

// ---------------------------------------------------------------------------
// Dual f16 GEMM (2-term: a*Wh + a*Wl), K=256, N=128, MTILE=256, relu.
//   FUSE2: restage relu'd tile (fp16) into A bufs and run second GEMM
//          (K2=128 -> N2=64 with W2,b2) -> fp32 out2.
// SMEM map (bytes):
//   [0..512) bias1 (128 f32)   [512..768) bias2 (64 f32)
//   [1024..66560)   A bufs: 2 x 32768 (256 rows x 128 B fp16)
//   [66560..197632) B1 frags (hi 65536 | lo 65536)
//   [197632..230400) B2 frags (hi 16384 | lo 16384)   (FUSE2)
// 512 threads, 16 warps; warp tile 32(M) x 64(N) (t=2 m-subtiles).
// ---------------------------------------------------------------------------
template <bool FUSE2>
__global__ __launch_bounds__(512, 1) void hmma_dual(
    const __half* __restrict__ A, const __half* __restrict__ X,
    const float* __restrict__ Wl, const float* __restrict__ Wr,
    const float* __restrict__ bias,
    const float* __restrict__ W2, const float* __restrict__ b2,
    __half* __restrict__ outP, float* __restrict__ out2,
    int n)
{
    constexpr int KSTEPS = 16;
    constexpr int NF2    = 8;
    constexpr int MTILE  = 256;
    constexpr int CHUNKB = MTILE * 128;     // 32768 (fp16, 64 cols)
    constexpr int BOFF   = 1024 + 2 * CHUNKB;       // 66560
    constexpr int BSPLIT = KSTEPS * NF2 * 32 * 16;  // 65536
    constexpr int BOFF2  = BOFF + 2 * BSPLIT;       // 197632
    constexpr int BSPLIT2 = 8 * 4 * 32 * 16;        // 16384
    constexpr int NCHUNK = 4;
    constexpr int CPOPS  = MTILE * 8;       // 2048 x 16B per chunk

    extern __shared__ char smem[];
    const uint32_t sb = smem_u32(smem);
    const int tid = threadIdx.x;
    const int w = tid >> 5, lane = tid & 31;
    const int g     = w & 1;
    const int warpM = (w >> 1) * 32;

    float* bs = (float*)smem;
    float* bs2 = (float*)(smem + 512);
    if (tid < 128) bs[tid] = bias[tid];
    if (FUSE2 && tid >= 128 && tid < 192) bs2[tid - 128] = b2[tid - 128];

    // B1 preload in fragment order (hi then lo), fp16
    for (int idx = tid; idx < 2 * KSTEPS * NF2 * 32; idx += 512) {
        int l = idx & 31;
        int rest = idx >> 5;
        int nfp = rest % NF2;
        int rest2 = rest / NF2;
        int ks = rest2 % KSTEPS;
        int s = rest2 / KSTEPS;
        uint32_t vals[4];
#pragma unroll
        for (int e = 0; e < 2; e++) {
            int nf = nfp * 2 + e;
            int nn = nf * 8 + (l >> 2);
            int k0 = ks * 16 + (l & 3) * 2;
            const float* wp = Wl;
            int kk = k0;
            if (k0 >= 128) { wp = Wr; kk = k0 - 128; }
            float2 wa = *reinterpret_cast<const float2*>(wp + nn * 128 + kk);
            float2 wb = *reinterpret_cast<const float2*>(wp + nn * 128 + kk + 8);
            unsigned short h, lo, r00, r01, r10, r11;
            split1h(wa.x, h, lo); r00 = s ? lo : h;
            split1h(wa.y, h, lo); r01 = s ? lo : h;
            split1h(wb.x, h, lo); r10 = s ? lo : h;
            split1h(wb.y, h, lo); r11 = s ? lo : h;
            vals[e * 2 + 0] = (uint32_t)r00 | ((uint32_t)r01 << 16);
            vals[e * 2 + 1] = (uint32_t)r10 | ((uint32_t)r11 << 16);
        }
        *reinterpret_cast<uint4*>(smem + BOFF + (size_t)idx * 16) =
            make_uint4(vals[0], vals[1], vals[2], vals[3]);
    }
    if (FUSE2) {
        for (int idx = tid; idx < 2 * 8 * 4 * 32; idx += 512) {
            int l = idx & 31;
            int rest = idx >> 5;
            int nfp = rest % 4;
            int rest2 = rest / 4;
            int ks = rest2 % 8;
            int s = rest2 / 8;
            uint32_t vals[4];
#pragma unroll
            for (int e = 0; e < 2; e++) {
                int nf = nfp * 2 + e;
                int nn = nf * 8 + (l >> 2);
                int k0 = ks * 16 + (l & 3) * 2;
                float2 wa = *reinterpret_cast<const float2*>(W2 + nn * 128 + k0);
                float2 wb = *reinterpret_cast<const float2*>(W2 + nn * 128 + k0 + 8);
                unsigned short h, lo, r00, r01, r10, r11;
                split1h(wa.x, h, lo); r00 = s ? lo : h;
                split1h(wa.y, h, lo); r01 = s ? lo : h;
                split1h(wb.x, h, lo); r10 = s ? lo : h;
                split1h(wb.y, h, lo); r11 = s ? lo : h;
                vals[e * 2 + 0] = (uint32_t)r00 | ((uint32_t)r01 << 16);
                vals[e * 2 + 1] = (uint32_t)r10 | ((uint32_t)r11 << 16);
            }
            *reinterpret_cast<uint4*>(smem + BOFF2 + (size_t)idx * 16) =
                make_uint4(vals[0], vals[1], vals[2], vals[3]);
        }
    }
    __syncthreads();

    const int ntiles = (n + MTILE - 1) / MTILE;

    for (int tt = blockIdx.x; tt < ntiles; tt += gridDim.x) {
        float acc[2][8][4];
#pragma unroll
        for (int t = 0; t < 2; t++)
#pragma unroll
            for (int nf = 0; nf < 8; nf++)
#pragma unroll
                for (int q = 0; q < 4; q++) acc[t][nf][q] = 0.f;

        auto stage = [&](int c, int b) {
            const __half* src = (c >= 2) ? X : A;
            const int colbase = (c & 1) * 64;
#pragma unroll
            for (int it = 0; it < CPOPS / 512; it++) {
                int u = tid + it * 512;
                int r0 = u >> 3;
                int ch = u & 7;
                int gr = tt * MTILE + r0;
                uint32_t dst = sb + 1024 + b * CHUNKB +
                               SWZ((uint32_t)(r0 * 128 + ch * 16));
                const void* gp = src + (size_t)gr * 128 + colbase + ch * 8;
                cp16(dst, gp, (gr < n) ? 16 : 0);
            }
            CP_COMMIT();
        };

        stage(0, 0);

        for (int c = 0; c < NCHUNK; c++) {
            if (c + 1 < NCHUNK) { stage(c + 1, (c + 1) & 1); CP_WAIT1(); }
            else CP_WAIT0();
            __syncthreads();

            const uint32_t abase = sb + 1024 + (c & 1) * CHUNKB;
#pragma unroll
            for (int ksl = 0; ksl < 4; ksl++) {
                const int ks = c * 4 + ksl;
                uint32_t ah[2][4];
#pragma unroll
                for (int t = 0; t < 2; t++) {
                    int arow = warpM + t * 16 + (lane & 15);
                    int colb = ksl * 32 + ((lane >> 4) << 4);
                    ldm4(abase + SWZ((uint32_t)(arow * 128 + colb)), ah[t]);
                }
                uint4 Bq[4];
                {
                    size_t base = (size_t)BOFF +
                        ((size_t)(ks * NF2 + g * 4) * 32 + lane) * 16;
#pragma unroll
                    for (int p = 0; p < 4; p++)
                        Bq[p] = *reinterpret_cast<const uint4*>(smem + base + p * 512);
                }
#pragma unroll
                for (int t = 0; t < 2; t++)
#pragma unroll
                    for (int nf = 0; nf < 8; nf++) {
                        uint32_t b0 = (nf & 1) ? Bq[nf >> 1].z : Bq[nf >> 1].x;
                        uint32_t b1 = (nf & 1) ? Bq[nf >> 1].w : Bq[nf >> 1].y;
                        mma_f16(acc[t][nf], ah[t], b0, b1);
                    }
                {
                    size_t base = (size_t)BOFF + BSPLIT +
                        ((size_t)(ks * NF2 + g * 4) * 32 + lane) * 16;
#pragma unroll
                    for (int p = 0; p < 4; p++)
                        Bq[p] = *reinterpret_cast<const uint4*>(smem + base + p * 512);
                }
#pragma unroll
                for (int t = 0; t < 2; t++)
#pragma unroll
                    for (int nf = 0; nf < 8; nf++) {
                        uint32_t b0 = (nf & 1) ? Bq[nf >> 1].z : Bq[nf >> 1].x;
                        uint32_t b1 = (nf & 1) ? Bq[nf >> 1].w : Bq[nf >> 1].y;
                        mma_f16(acc[t][nf], ah[t], b0, b1);
                    }
            }
            __syncthreads();
        }

        if (!FUSE2) {
            // epilogue: relu -> fp16 plane
#pragma unroll
            for (int t = 0; t < 2; t++) {
                int rbase = tt * MTILE + warpM + t * 16 + (lane >> 2);
#pragma unroll
                for (int nf = 0; nf < 8; nf++) {
                    int col = g * 64 + nf * 8 + (lane & 3) * 2;
#pragma unroll
                    for (int hh = 0; hh < 2; hh++) {
                        int row = rbase + hh * 8;
                        if (row < n) {
                            float ox = fmaxf(acc[t][nf][hh * 2 + 0] + bs[col], 0.f);
                            float oy = fmaxf(acc[t][nf][hh * 2 + 1] + bs[col + 1], 0.f);
                            __half2 hp = __floats2half2_rn(ox, oy);
                            *reinterpret_cast<uint32_t*>(outP + (size_t)row * 128 + col) =
                                *reinterpret_cast<uint32_t*>(&hp);
                        }
                    }
                }
            }
        } else {
            // restage relu'd tile (fp16) into A bufs: cols 0-63 -> buf0, 64-127 -> buf1
#pragma unroll
            for (int t = 0; t < 2; t++) {
                int rl = warpM + t * 16 + (lane >> 2);
#pragma unroll
                for (int nf = 0; nf < 8; nf++) {
                    int col = g * 64 + nf * 8 + (lane & 3) * 2;
#pragma unroll
                    for (int hh = 0; hh < 2; hh++) {
                        int r = rl + hh * 8;
                        float ox = fmaxf(acc[t][nf][hh * 2 + 0] + bs[col], 0.f);
                        float oy = fmaxf(acc[t][nf][hh * 2 + 1] + bs[col + 1], 0.f);
                        __half2 hp = __floats2half2_rn(ox, oy);
                        uint32_t off = SWZ((uint32_t)(r * 128 + (col & 63) * 2));
                        *reinterpret_cast<uint32_t*>(smem + 1024 + g * CHUNKB + off) =
                            *reinterpret_cast<uint32_t*>(&hp);
                    }
                }
            }
            __syncthreads();

            // second GEMM: K2=128 resident, N2=64; warp tile 32 x 32
            float acc2[2][4][4];
#pragma unroll
            for (int t = 0; t < 2; t++)
#pragma unroll
                for (int nf = 0; nf < 4; nf++)
#pragma unroll
                    for (int q = 0; q < 4; q++) acc2[t][nf][q] = 0.f;

#pragma unroll
            for (int ks2 = 0; ks2 < 8; ks2++) {
                const int chunk = ks2 >> 2, ksl2 = ks2 & 3;
                const uint32_t abase2 = sb + 1024 + chunk * CHUNKB;
                uint32_t ah2[2][4];
#pragma unroll
                for (int t = 0; t < 2; t++) {
                    int arow = warpM + t * 16 + (lane & 15);
                    int colb = ksl2 * 32 + ((lane >> 4) << 4);
                    ldm4(abase2 + SWZ((uint32_t)(arow * 128 + colb)), ah2[t]);
                }
                uint4 Bq[2];
                {
                    size_t base = (size_t)BOFF2 +
                        ((size_t)(ks2 * 4 + g * 2) * 32 + lane) * 16;
                    Bq[0] = *reinterpret_cast<const uint4*>(smem + base);
                    Bq[1] = *reinterpret_cast<const uint4*>(smem + base + 512);
                }
#pragma unroll
                for (int t = 0; t < 2; t++)
#pragma unroll
                    for (int nf = 0; nf < 4; nf++) {
                        uint32_t b0 = (nf & 1) ? Bq[nf >> 1].z : Bq[nf >> 1].x;
                        uint32_t b1 = (nf & 1) ? Bq[nf >> 1].w : Bq[nf >> 1].y;
                        mma_f16(acc2[t][nf], ah2[t], b0, b1);
                    }
                {
                    size_t base = (size_t)BOFF2 + BSPLIT2 +
                        ((size_t)(ks2 * 4 + g * 2) * 32 + lane) * 16;
                    Bq[0] = *reinterpret_cast<const uint4*>(smem + base);
                    Bq[1] = *reinterpret_cast<const uint4*>(smem + base + 512);
                }
#pragma unroll
                for (int t = 0; t < 2; t++)
#pragma unroll
                    for (int nf = 0; nf < 4; nf++) {
                        uint32_t b0 = (nf & 1) ? Bq[nf >> 1].z : Bq[nf >> 1].x;
                        uint32_t b1 = (nf & 1) ? Bq[nf >> 1].w : Bq[nf >> 1].y;
                        mma_f16(acc2[t][nf], ah2[t], b0, b1);
                    }
            }

#pragma unroll
            for (int t = 0; t < 2; t++) {
                int rbase = tt * MTILE + warpM + t * 16 + (lane >> 2);
#pragma unroll
                for (int nf = 0; nf < 4; nf++) {
                    int col = g * 32 + nf * 8 + (lane & 3) * 2;
#pragma unroll
                    for (int hh = 0; hh < 2; hh++) {
                        int row = rbase + hh * 8;
                        if (row < n) {
                            float2 o;
                            o.x = acc2[t][nf][hh * 2 + 0] + bs2[col];
                            o.y = acc2[t][nf][hh * 2 + 1] + bs2[col + 1];
                            *reinterpret_cast<float2*>(out2 + (size_t)row * 64 + col) = o;
                        }
                    }
                }
            }
            __syncthreads();
        }
    }
}

// ---------------------------------------------------------------------------
// SIMT decoder (f32x2 FMAs)
// ---------------------------------------------------------------------------
__launch_bounds__(512, 1)
__global__ void decoder_kernel(const float* __restrict__ zc, const float* __restrict__ zp,
                               const int* __restrict__ row, const int* __restrict__ col,
                               const float* __restrict__ W1, const float* __restrict__ b1,
                               const float* __restrict__ w2, const float* __restrict__ b2,
                               float* __restrict__ out, int nE) {
    constexpr int NOP = 68;
    constexpr int R = 8;
    extern __shared__ float smemf[];
    float* Ws = smemf;
    float* stage = smemf + 128 * NOP;

    int tid = threadIdx.x;
    for (int i = tid; i < 64 * 128; i += 512) {
        int o = i >> 7, k = i & 127;
        Ws[k * NOP + o] = W1[i];
    }
    __syncthreads();

    const int w = tid >> 5, lane = tid & 31;
    float* Zs = stage + w * (R * 128);

    float2 b1v = __ldg(reinterpret_cast<const float2*>(b1 + lane * 2));
    u64 bofs = pack2(b1v.x, b1v.y);
    float w20 = __ldg(w2 + lane * 2), w21 = __ldg(w2 + lane * 2 + 1);
    float b2v = __ldg(b2);

    for (int base = (blockIdx.x * 16 + w) * R; base < nE; base += gridDim.x * 16 * R) {
#pragma unroll
        for (int r = 0; r < R; r++) {
            int e = base + r;
            float4 v = make_float4(0.f, 0.f, 0.f, 0.f);
            if (e < nE) {
                if (lane < 16) {
                    int ri = __ldg(row + e);
                    v = *reinterpret_cast<const float4*>(zc + (size_t)ri * DOUT + lane * 4);
                } else {
                    int ci = __ldg(col + e);
                    v = *reinterpret_cast<const float4*>(zp + (size_t)ci * DOUT + (lane - 16) * 4);
                }
            }
            *reinterpret_cast<float4*>(Zs + r * 128 + lane * 4) = v;
        }
        __syncwarp();

        u64 acc[R];
#pragma unroll
        for (int r = 0; r < R; r++) acc[r] = bofs;

        for (int k0 = 0; k0 < 128; k0 += 4) {
            float4 z4[R];
#pragma unroll
            for (int r = 0; r < R; r++)
                z4[r] = *reinterpret_cast<const float4*>(Zs + r * 128 + k0);
#pragma unroll
            for (int kk = 0; kk < 4; kk++) {
                u64 wv = *reinterpret_cast<const u64*>(Ws + (k0 + kk) * NOP + lane * 2);
#pragma unroll
                for (int r = 0; r < R; r++) {
                    float z = (kk == 0) ? z4[r].x : (kk == 1) ? z4[r].y : (kk == 2) ? z4[r].z : z4[r].w;
                    u64 zd = dup2(z);
                    fma2(acc[r], zd, wv);
                }
            }
        }

#pragma unroll
        for (int r = 0; r < R; r++) {
            float h0, h1;
            unpack2(acc[r], h0, h1);
            h0 = fmaxf(h0, 0.f); h1 = fmaxf(h1, 0.f);
            float p = h0 * w20 + h1 * w21;
#pragma unroll
            for (int o = 16; o > 0; o >>= 1) p += __shfl_xor_sync(0xffffffff, p, o);
            if (lane == 0 && base + r < nE) out[base + r] = p + b2v;
        }
        __syncwarp();
    }
}

// ---------------------------------------------------------------------------
// Host orchestration
// ---------------------------------------------------------------------------
extern "C" void kernel_launch(void* const* d_in, const int* in_sizes, int n_in,
                              void* d_out, int out_size) {
    const float* x_prod = (const float*)d_in[0];
    const float* x_cust = (const float*)d_in[1];
    const int* pp = (const int*)d_in[2];
    const int* pc = (const int*)d_in[3];
    const int* eli = (const int*)d_in[4];

    bool sig = (in_sizes[6] == HID);
    const float* it_W1l = (const float*)d_in[5];
    const float* it_W1r = (const float*)d_in[sig ? 7 : 6];
    const float* it_b1  = (const float*)d_in[sig ? 6 : 7];
    const float* it_W2l = (const float*)d_in[8];
    const float* it_W2r = (const float*)d_in[sig ? 10 : 9];
    const float* it_b2  = (const float*)d_in[sig ? 9 : 10];
    const float* it_Wlin = (const float*)d_in[11];
    const float* it_blin = (const float*)d_in[12];
    const float* us_W1l = (const float*)d_in[13];
    const float* us_W1r = (const float*)d_in[sig ? 15 : 14];
    const float* us_b1  = (const float*)d_in[sig ? 14 : 15];
    const float* us_W2l = (const float*)d_in[16];
    const float* us_W2r = (const float*)d_in[sig ? 18 : 17];
    const float* us_b2  = (const float*)d_in[sig ? 17 : 18];
    const float* us_W3l = (const float*)d_in[19];
    const float* us_W3r = (const float*)d_in[sig ? 21 : 20];
    const float* us_b3  = (const float*)d_in[sig ? 20 : 21];
    const float* us_Wlin = (const float*)d_in[22];
    const float* us_blin = (const float*)d_in[23];
    const float* de_W1 = (const float*)d_in[24];
    const float* de_b1 = (const float*)d_in[25];
    const float* de_W2 = (const float*)d_in[26];
    const float* de_b2 = (const float*)d_in[27];

#define GETP(var, sym, T) T* var; cudaGetSymbolAddress((void**)&var, sym)
    GETP(xP, g_xP, __half); GETP(xC, g_xC, __half);
    GETP(M0, g_M0, __half);
    GETP(P1, g_P1, __half); GETP(P2, g_P2, __half);
    GETP(C1, g_C1, __half);
    GETP(zprod, g_zprod, float); GETP(zcust, g_zcust, float);
    GETP(offP, g_offP, int); GETP(csrP, g_csrP, int);
    GETP(offC, g_offC, int); GETP(csrC, g_csrC, int);
#undef GETP

    constexpr int SM_PLAIN = 1024 + 2 * 32768 + 2 * 65536;   // 197632
    constexpr int SM_FUSED = SM_PLAIN + 2 * 16384;           // 230400
    constexpr int SM_DEC   = (128 * 68 + 16 * 8 * 128) * 4;
    cudaFuncSetAttribute((hmma_dual<false>),
                         cudaFuncAttributeMaxDynamicSharedMemorySize, SM_PLAIN);
    cudaFuncSetAttribute((hmma_dual<true>),
                         cudaFuncAttributeMaxDynamicSharedMemorySize, SM_FUSED);
    cudaFuncSetAttribute(decoder_kernel,
                         cudaFuncAttributeMaxDynamicSharedMemorySize, SM_DEC);

    const int nbP = (N_PROD + 1023) / 1024;
    const int nbC = (N_CUST + 1023) / 1024;
    const int PRE_ITEMS = (N_PROD + N_CUST) * HID / 4 + E_PP + E_PC;
    const int aggP_grid = (N_PROD * 32 + 255) / 256;
    const int aggC_grid = (N_CUST * 32 + 255) / 256;

    // 0-2: convert + counts, scans, fills
    k_pre<<<(PRE_ITEMS + 255) / 256, 256>>>(x_prod, x_cust, pp + E_PP, pc + E_PC);
    k_scan2x<<<nbP + nbC, 1024>>>();
    k_fill2x<<<(E_PP + E_PC + 255) / 256, 256>>>(pp, pc);

    // 3: M0 = mean_pp(x)
    agg_mean<<<aggP_grid, 256>>>(xP, offP, csrP, M0, N_PROD, E_PP);
    // 4: G1 it layer1 -> P1
    hmma_dual<false><<<148, 512, SM_PLAIN>>>(
        M0, xP, it_W1l, it_W1r, it_b1, nullptr, nullptr, P1, nullptr, N_PROD);
    // 5: G2 us layer1 -> P2
    hmma_dual<false><<<148, 512, SM_PLAIN>>>(
        M0, xP, us_W1l, us_W1r, us_b1, nullptr, nullptr, P2, nullptr, N_PROD);
    // 6: M0 = mean_pp(P1)
    agg_mean<<<aggP_grid, 256>>>(P1, offP, csrP, M0, N_PROD, E_PP);
    // 7: fused it layer2 + it linear -> zprod
    hmma_dual<true><<<148, 512, SM_FUSED>>>(
        M0, P1, it_W2l, it_W2r, it_b2, it_Wlin, it_blin, nullptr, zprod, N_PROD);
    // 8: M0 = mean_pc(x)
    agg_mean<<<aggC_grid, 256>>>(xP, offC, csrC, M0, N_CUST, E_PC);
    // 9: G5 us layer2 -> C1
    hmma_dual<false><<<148, 512, SM_PLAIN>>>(
        M0, xC, us_W2l, us_W2r, us_b2, nullptr, nullptr, C1, nullptr, N_CUST);
    // 10: M0 = mean_pc(P2)
    agg_mean<<<aggC_grid, 256>>>(P2, offC, csrC, M0, N_CUST, E_PC);
    // 11: fused us layer3 + us linear -> zcust
    hmma_dual<true><<<148, 512, SM_FUSED>>>(
        M0, C1, us_W3l, us_W3r, us_b3, us_Wlin, us_blin, nullptr, zcust, N_CUST);

    // 12: decoder
    decoder_kernel<<<296, 512, SM_DEC>>>(zcust, zprod, eli, eli + E_LB,
                                         de_W1, de_b1, de_W2, de_b2,
                                         (float*)d_out, E_LB);

    // 13: restore zero invariant
    k_tail_zero<<<(N_PROD + 255) / 256, 256>>>();
}

// round 10
// speedup vs baseline: 2.2191x; 1.3317x over previous
#include <cuda_runtime.h>
#include <cuda_fp16.h>
#include <cstdint>

#define N_PROD 100000
#define N_CUST 50000
#define HID    128
#define DOUT   64
#define E_PP   800000
#define E_PC   800000
#define E_LB   400000

typedef unsigned long long u64;

#define SWZ(x) ((x) ^ (((x) >> 3) & 0x70))

__device__ __forceinline__ uint32_t smem_u32(const void* p) {
    uint32_t a;
    asm("{ .reg .u64 t; cvta.to.shared.u64 t, %1; cvt.u32.u64 %0, t; }" : "=r"(a) : "l"(p));
    return a;
}
__device__ __forceinline__ void cp16(uint32_t dst, const void* src, int sz) {
    asm volatile("cp.async.cg.shared.global [%0],[%1],16,%2;"
                 :: "r"(dst), "l"(src), "r"(sz));
}
#define CP_COMMIT() asm volatile("cp.async.commit_group;" ::: "memory")
#define CP_WAIT1()  asm volatile("cp.async.wait_group 1;" ::: "memory")
#define CP_WAIT0()  asm volatile("cp.async.wait_group 0;" ::: "memory")

__device__ __forceinline__ void ldm4(uint32_t addr, uint32_t* r) {
    asm volatile("ldmatrix.sync.aligned.m8n8.x4.shared.b16 {%0,%1,%2,%3},[%4];"
                 : "=r"(r[0]), "=r"(r[1]), "=r"(r[2]), "=r"(r[3]) : "r"(addr));
}
__device__ __forceinline__ void mma_f16(float* d, const uint32_t* a,
                                        uint32_t b0, uint32_t b1) {
    asm volatile(
        "mma.sync.aligned.m16n8k16.row.col.f32.f16.f16.f32 "
        "{%0,%1,%2,%3},{%4,%5,%6,%7},{%8,%9},{%0,%1,%2,%3};"
        : "+f"(d[0]), "+f"(d[1]), "+f"(d[2]), "+f"(d[3])
        : "r"(a[0]), "r"(a[1]), "r"(a[2]), "r"(a[3]), "r"(b0), "r"(b1));
}
__device__ __forceinline__ void split1h(float w, unsigned short& h, unsigned short& l) {
    __half hh = __float2half_rn(w);
    __half hl = __float2half_rn(w - __half2float(hh));
    h = __half_as_ushort(hh);
    l = __half_as_ushort(hl);
}
__device__ __forceinline__ u64 pack4h(float a0, float a1, float a2, float a3) {
    __half2 p0 = __floats2half2_rn(a0, a1);
    __half2 p1 = __floats2half2_rn(a2, a3);
    u64 r;
    asm("mov.b64 %0,{%1,%2};" : "=l"(r)
        : "r"(*reinterpret_cast<uint32_t*>(&p0)), "r"(*reinterpret_cast<uint32_t*>(&p1)));
    return r;
}

// ---------------------------------------------------------------------------
// Scratch (fp16 activation planes; fp16 z)
// ---------------------------------------------------------------------------
__device__ __half g_xP[(size_t)N_PROD * HID];
__device__ __half g_xC[(size_t)N_CUST * HID];
__device__ __half g_M0[(size_t)N_PROD * HID];
__device__ __half g_P1[(size_t)N_PROD * HID];
__device__ __half g_P2[(size_t)N_PROD * HID];
__device__ __half g_C1[(size_t)N_CUST * HID];
__device__ __half g_zprod[(size_t)N_PROD * DOUT];
__device__ __half g_zcust[(size_t)N_CUST * DOUT];

__device__ int g_cntP[N_PROD];
__device__ int g_cntC[N_CUST];
__device__ int g_offP[N_PROD];
__device__ int g_curP[N_PROD];
__device__ int g_csrP[E_PP];
__device__ int g_offC[N_CUST];
__device__ int g_curC[N_CUST];
__device__ int g_csrC[E_PC];
__device__ u64 g_lbP[128];
__device__ u64 g_lbC[64];

// ---------------------------------------------------------------------------
// Launch 0: convert x -> fp16 planes AND count both edge histograms
// ---------------------------------------------------------------------------
__global__ void k_pre(const float* __restrict__ xp, const float* __restrict__ xc,
                      const int* __restrict__ dstP, const int* __restrict__ dstC) {
    const int NP4 = N_PROD * HID / 4;
    const int NC4 = N_CUST * HID / 4;
    int i = blockIdx.x * blockDim.x + threadIdx.x;
    if (i < NP4 + NC4) {
        const float* src; __half* dh; int o;
        if (i < NP4) { src = xp; dh = g_xP; o = i; }
        else { src = xc; dh = g_xC; o = i - NP4; }
        float4 v = *reinterpret_cast<const float4*>(src + (size_t)o * 4);
        *reinterpret_cast<u64*>(dh + (size_t)o * 4) = pack4h(v.x, v.y, v.z, v.w);
        return;
    }
    int j = i - (NP4 + NC4);
    if (j < E_PP) { atomicAdd(&g_cntP[dstP[j]], 1); return; }
    j -= E_PP;
    if (j < E_PC) atomicAdd(&g_cntC[dstC[j]], 1);
}

// ---------------------------------------------------------------------------
// Launch 1: decoupled-lookback scan (P and C segments)
// ---------------------------------------------------------------------------
__device__ void scan_seg(const int* __restrict__ cnt, int n,
                         int* __restrict__ off, int* __restrict__ cur,
                         u64* __restrict__ st, int bid) {
    __shared__ int s[1024];
    __shared__ int s_prefix;
    int tx = threadIdx.x;
    int gid = bid * 1024 + tx;
    int v = (gid < n) ? cnt[gid] : 0;
    s[tx] = v;
    __syncthreads();
#pragma unroll
    for (int d = 1; d < 1024; d <<= 1) {
        int t = (tx >= d) ? s[tx - d] : 0;
        __syncthreads();
        s[tx] += t;
        __syncthreads();
    }
    int incl = s[tx];
    int total = s[1023];
    if (tx == 0) {
        if (bid == 0) {
            s_prefix = 0;
            atomicExch(st, ((u64)(unsigned)total << 32) | 2ULL);
        } else {
            atomicExch(st + bid, ((u64)(unsigned)total << 32) | 1ULL);
            int run = 0, j = bid - 1;
            while (true) {
                u64 x;
                do { x = atomicAdd(st + j, 0ULL); } while ((x & 3ULL) == 0ULL);
                run += (int)(unsigned)(x >> 32);
                if ((x & 3ULL) == 2ULL) break;
                j--;
            }
            s_prefix = run;
            atomicExch(st + bid, ((u64)(unsigned)(run + total) << 32) | 2ULL);
        }
    }
    __syncthreads();
    if (gid < n) {
        int e = s_prefix + incl - v;
        off[gid] = e;
        cur[gid] = e;
    }
}

__global__ void k_scan2x() {
    const int nbP = (N_PROD + 1023) / 1024;
    if ((int)blockIdx.x < nbP)
        scan_seg(g_cntP, N_PROD, g_offP, g_curP, g_lbP, blockIdx.x);
    else
        scan_seg(g_cntC, N_CUST, g_offC, g_curC, g_lbC, blockIdx.x - nbP);
}

__global__ void k_fill2x(const int* __restrict__ eP, const int* __restrict__ eC) {
    int e = blockIdx.x * blockDim.x + threadIdx.x;
    if (e < E_PP) {
        int d = eP[E_PP + e];
        int p = atomicAdd(&g_curP[d], 1);
        g_csrP[p] = eP[e];
    } else if (e < E_PP + E_PC) {
        int j = e - E_PP;
        int d = eC[E_PC + j];
        int p = atomicAdd(&g_curC[d], 1);
        g_csrC[p] = eC[j];
    }
}

__global__ void k_tail_zero() {
    int i = blockIdx.x * blockDim.x + threadIdx.x;
    if (i < N_PROD) g_cntP[i] = 0;
    if (i < N_CUST) g_cntC[i] = 0;
    if (i < 128) g_lbP[i] = 0;
    if (i < 64) g_lbC[i] = 0;
}

// ---------------------------------------------------------------------------
// Mean aggregation: fp16 in, fp16 out; one warp per node, unroll x4
// ---------------------------------------------------------------------------
__global__ void agg_mean(const __half* __restrict__ x,
                         const int* __restrict__ off, const int* __restrict__ csr,
                         __half* __restrict__ o, int n, int E) {
    int w = (blockIdx.x * blockDim.x + threadIdx.x) >> 5;
    int lane = threadIdx.x & 31;
    if (w >= n) return;
    int beg = off[w];
    int end = (w + 1 < n) ? off[w + 1] : E;
    float a0 = 0.f, a1 = 0.f, a2 = 0.f, a3 = 0.f;
    int j = beg;
#define ACCH(p) do { \
    uint2 uu = *reinterpret_cast<uint2*>(&p); \
    float2 f0 = __half22float2(*reinterpret_cast<__half2*>(&uu.x)); \
    float2 f1 = __half22float2(*reinterpret_cast<__half2*>(&uu.y)); \
    a0 += f0.x; a1 += f0.y; a2 += f1.x; a3 += f1.y; \
} while (0)
    for (; j + 3 < end; j += 4) {
        int s0 = csr[j], s1 = csr[j + 1], s2 = csr[j + 2], s3 = csr[j + 3];
        u64 p0 = __ldg(reinterpret_cast<const u64*>(x + (size_t)s0 * HID + lane * 4));
        u64 p1 = __ldg(reinterpret_cast<const u64*>(x + (size_t)s1 * HID + lane * 4));
        u64 p2 = __ldg(reinterpret_cast<const u64*>(x + (size_t)s2 * HID + lane * 4));
        u64 p3 = __ldg(reinterpret_cast<const u64*>(x + (size_t)s3 * HID + lane * 4));
        ACCH(p0); ACCH(p1); ACCH(p2); ACCH(p3);
    }
    for (; j < end; j++) {
        int s0 = csr[j];
        u64 p = __ldg(reinterpret_cast<const u64*>(x + (size_t)s0 * HID + lane * 4));
        ACCH(p);
    }
#undef ACCH
    float sc = (end > beg) ? 1.0f / (float)(end - beg) : 0.f;
    *reinterpret_cast<u64*>(o + (size_t)w * HID + lane * 4) =
        pack4h(a0 * sc, a1 * sc, a2 * sc, a3 * sc);
}

// ---------------------------------------------------------------------------
// Dual f16 GEMM (2-term weight split), K=256, N=128, MTILE=256, relu.
//   FUSE2: restage relu'd tile and run second GEMM (128->64), write fp16 z.
// ---------------------------------------------------------------------------
template <bool FUSE2>
__global__ __launch_bounds__(512, 1) void hmma_dual(
    const __half* __restrict__ A, const __half* __restrict__ X,
    const float* __restrict__ Wl, const float* __restrict__ Wr,
    const float* __restrict__ bias,
    const float* __restrict__ W2, const float* __restrict__ b2,
    __half* __restrict__ outP, __half* __restrict__ out2,
    int n)
{
    constexpr int KSTEPS = 16;
    constexpr int NF2    = 8;
    constexpr int MTILE  = 256;
    constexpr int CHUNKB = MTILE * 128;
    constexpr int BOFF   = 1024 + 2 * CHUNKB;
    constexpr int BSPLIT = KSTEPS * NF2 * 32 * 16;
    constexpr int BOFF2  = BOFF + 2 * BSPLIT;
    constexpr int BSPLIT2 = 8 * 4 * 32 * 16;
    constexpr int NCHUNK = 4;
    constexpr int CPOPS  = MTILE * 8;

    extern __shared__ char smem[];
    const uint32_t sb = smem_u32(smem);
    const int tid = threadIdx.x;
    const int w = tid >> 5, lane = tid & 31;
    const int g     = w & 1;
    const int warpM = (w >> 1) * 32;

    float* bs = (float*)smem;
    float* bs2 = (float*)(smem + 512);
    if (tid < 128) bs[tid] = bias[tid];
    if (FUSE2 && tid >= 128 && tid < 192) bs2[tid - 128] = b2[tid - 128];

    for (int idx = tid; idx < 2 * KSTEPS * NF2 * 32; idx += 512) {
        int l = idx & 31;
        int rest = idx >> 5;
        int nfp = rest % NF2;
        int rest2 = rest / NF2;
        int ks = rest2 % KSTEPS;
        int s = rest2 / KSTEPS;
        uint32_t vals[4];
#pragma unroll
        for (int e = 0; e < 2; e++) {
            int nf = nfp * 2 + e;
            int nn = nf * 8 + (l >> 2);
            int k0 = ks * 16 + (l & 3) * 2;
            const float* wp = Wl;
            int kk = k0;
            if (k0 >= 128) { wp = Wr; kk = k0 - 128; }
            float2 wa = *reinterpret_cast<const float2*>(wp + nn * 128 + kk);
            float2 wb = *reinterpret_cast<const float2*>(wp + nn * 128 + kk + 8);
            unsigned short h, lo, r00, r01, r10, r11;
            split1h(wa.x, h, lo); r00 = s ? lo : h;
            split1h(wa.y, h, lo); r01 = s ? lo : h;
            split1h(wb.x, h, lo); r10 = s ? lo : h;
            split1h(wb.y, h, lo); r11 = s ? lo : h;
            vals[e * 2 + 0] = (uint32_t)r00 | ((uint32_t)r01 << 16);
            vals[e * 2 + 1] = (uint32_t)r10 | ((uint32_t)r11 << 16);
        }
        *reinterpret_cast<uint4*>(smem + BOFF + (size_t)idx * 16) =
            make_uint4(vals[0], vals[1], vals[2], vals[3]);
    }
    if (FUSE2) {
        for (int idx = tid; idx < 2 * 8 * 4 * 32; idx += 512) {
            int l = idx & 31;
            int rest = idx >> 5;
            int nfp = rest % 4;
            int rest2 = rest / 4;
            int ks = rest2 % 8;
            int s = rest2 / 8;
            uint32_t vals[4];
#pragma unroll
            for (int e = 0; e < 2; e++) {
                int nf = nfp * 2 + e;
                int nn = nf * 8 + (l >> 2);
                int k0 = ks * 16 + (l & 3) * 2;
                float2 wa = *reinterpret_cast<const float2*>(W2 + nn * 128 + k0);
                float2 wb = *reinterpret_cast<const float2*>(W2 + nn * 128 + k0 + 8);
                unsigned short h, lo, r00, r01, r10, r11;
                split1h(wa.x, h, lo); r00 = s ? lo : h;
                split1h(wa.y, h, lo); r01 = s ? lo : h;
                split1h(wb.x, h, lo); r10 = s ? lo : h;
                split1h(wb.y, h, lo); r11 = s ? lo : h;
                vals[e * 2 + 0] = (uint32_t)r00 | ((uint32_t)r01 << 16);
                vals[e * 2 + 1] = (uint32_t)r10 | ((uint32_t)r11 << 16);
            }
            *reinterpret_cast<uint4*>(smem + BOFF2 + (size_t)idx * 16) =
                make_uint4(vals[0], vals[1], vals[2], vals[3]);
        }
    }
    __syncthreads();

    const int ntiles = (n + MTILE - 1) / MTILE;

    for (int tt = blockIdx.x; tt < ntiles; tt += gridDim.x) {
        float acc[2][8][4];
#pragma unroll
        for (int t = 0; t < 2; t++)
#pragma unroll
            for (int nf = 0; nf < 8; nf++)
#pragma unroll
                for (int q = 0; q < 4; q++) acc[t][nf][q] = 0.f;

        auto stage = [&](int c, int b) {
            const __half* src = (c >= 2) ? X : A;
            const int colbase = (c & 1) * 64;
#pragma unroll
            for (int it = 0; it < CPOPS / 512; it++) {
                int u = tid + it * 512;
                int r0 = u >> 3;
                int ch = u & 7;
                int gr = tt * MTILE + r0;
                uint32_t dst = sb + 1024 + b * CHUNKB +
                               SWZ((uint32_t)(r0 * 128 + ch * 16));
                const void* gp = src + (size_t)gr * 128 + colbase + ch * 8;
                cp16(dst, gp, (gr < n) ? 16 : 0);
            }
            CP_COMMIT();
        };

        stage(0, 0);

        for (int c = 0; c < NCHUNK; c++) {
            if (c + 1 < NCHUNK) { stage(c + 1, (c + 1) & 1); CP_WAIT1(); }
            else CP_WAIT0();
            __syncthreads();

            const uint32_t abase = sb + 1024 + (c & 1) * CHUNKB;
#pragma unroll
            for (int ksl = 0; ksl < 4; ksl++) {
                const int ks = c * 4 + ksl;
                uint32_t ah[2][4];
#pragma unroll
                for (int t = 0; t < 2; t++) {
                    int arow = warpM + t * 16 + (lane & 15);
                    int colb = ksl * 32 + ((lane >> 4) << 4);
                    ldm4(abase + SWZ((uint32_t)(arow * 128 + colb)), ah[t]);
                }
                uint4 Bq[4];
                {
                    size_t base = (size_t)BOFF +
                        ((size_t)(ks * NF2 + g * 4) * 32 + lane) * 16;
#pragma unroll
                    for (int p = 0; p < 4; p++)
                        Bq[p] = *reinterpret_cast<const uint4*>(smem + base + p * 512);
                }
#pragma unroll
                for (int t = 0; t < 2; t++)
#pragma unroll
                    for (int nf = 0; nf < 8; nf++) {
                        uint32_t b0 = (nf & 1) ? Bq[nf >> 1].z : Bq[nf >> 1].x;
                        uint32_t b1 = (nf & 1) ? Bq[nf >> 1].w : Bq[nf >> 1].y;
                        mma_f16(acc[t][nf], ah[t], b0, b1);
                    }
                {
                    size_t base = (size_t)BOFF + BSPLIT +
                        ((size_t)(ks * NF2 + g * 4) * 32 + lane) * 16;
#pragma unroll
                    for (int p = 0; p < 4; p++)
                        Bq[p] = *reinterpret_cast<const uint4*>(smem + base + p * 512);
                }
#pragma unroll
                for (int t = 0; t < 2; t++)
#pragma unroll
                    for (int nf = 0; nf < 8; nf++) {
                        uint32_t b0 = (nf & 1) ? Bq[nf >> 1].z : Bq[nf >> 1].x;
                        uint32_t b1 = (nf & 1) ? Bq[nf >> 1].w : Bq[nf >> 1].y;
                        mma_f16(acc[t][nf], ah[t], b0, b1);
                    }
            }
            __syncthreads();
        }

        if (!FUSE2) {
#pragma unroll
            for (int t = 0; t < 2; t++) {
                int rbase = tt * MTILE + warpM + t * 16 + (lane >> 2);
#pragma unroll
                for (int nf = 0; nf < 8; nf++) {
                    int col = g * 64 + nf * 8 + (lane & 3) * 2;
#pragma unroll
                    for (int hh = 0; hh < 2; hh++) {
                        int row = rbase + hh * 8;
                        if (row < n) {
                            float ox = fmaxf(acc[t][nf][hh * 2 + 0] + bs[col], 0.f);
                            float oy = fmaxf(acc[t][nf][hh * 2 + 1] + bs[col + 1], 0.f);
                            __half2 hp = __floats2half2_rn(ox, oy);
                            *reinterpret_cast<uint32_t*>(outP + (size_t)row * 128 + col) =
                                *reinterpret_cast<uint32_t*>(&hp);
                        }
                    }
                }
            }
        } else {
#pragma unroll
            for (int t = 0; t < 2; t++) {
                int rl = warpM + t * 16 + (lane >> 2);
#pragma unroll
                for (int nf = 0; nf < 8; nf++) {
                    int col = g * 64 + nf * 8 + (lane & 3) * 2;
#pragma unroll
                    for (int hh = 0; hh < 2; hh++) {
                        int r = rl + hh * 8;
                        float ox = fmaxf(acc[t][nf][hh * 2 + 0] + bs[col], 0.f);
                        float oy = fmaxf(acc[t][nf][hh * 2 + 1] + bs[col + 1], 0.f);
                        __half2 hp = __floats2half2_rn(ox, oy);
                        uint32_t off = SWZ((uint32_t)(r * 128 + (col & 63) * 2));
                        *reinterpret_cast<uint32_t*>(smem + 1024 + g * CHUNKB + off) =
                            *reinterpret_cast<uint32_t*>(&hp);
                    }
                }
            }
            __syncthreads();

            float acc2[2][4][4];
#pragma unroll
            for (int t = 0; t < 2; t++)
#pragma unroll
                for (int nf = 0; nf < 4; nf++)
#pragma unroll
                    for (int q = 0; q < 4; q++) acc2[t][nf][q] = 0.f;

#pragma unroll
            for (int ks2 = 0; ks2 < 8; ks2++) {
                const int chunk = ks2 >> 2, ksl2 = ks2 & 3;
                const uint32_t abase2 = sb + 1024 + chunk * CHUNKB;
                uint32_t ah2[2][4];
#pragma unroll
                for (int t = 0; t < 2; t++) {
                    int arow = warpM + t * 16 + (lane & 15);
                    int colb = ksl2 * 32 + ((lane >> 4) << 4);
                    ldm4(abase2 + SWZ((uint32_t)(arow * 128 + colb)), ah2[t]);
                }
                uint4 Bq[2];
                {
                    size_t base = (size_t)BOFF2 +
                        ((size_t)(ks2 * 4 + g * 2) * 32 + lane) * 16;
                    Bq[0] = *reinterpret_cast<const uint4*>(smem + base);
                    Bq[1] = *reinterpret_cast<const uint4*>(smem + base + 512);
                }
#pragma unroll
                for (int t = 0; t < 2; t++)
#pragma unroll
                    for (int nf = 0; nf < 4; nf++) {
                        uint32_t b0 = (nf & 1) ? Bq[nf >> 1].z : Bq[nf >> 1].x;
                        uint32_t b1 = (nf & 1) ? Bq[nf >> 1].w : Bq[nf >> 1].y;
                        mma_f16(acc2[t][nf], ah2[t], b0, b1);
                    }
                {
                    size_t base = (size_t)BOFF2 + BSPLIT2 +
                        ((size_t)(ks2 * 4 + g * 2) * 32 + lane) * 16;
                    Bq[0] = *reinterpret_cast<const uint4*>(smem + base);
                    Bq[1] = *reinterpret_cast<const uint4*>(smem + base + 512);
                }
#pragma unroll
                for (int t = 0; t < 2; t++)
#pragma unroll
                    for (int nf = 0; nf < 4; nf++) {
                        uint32_t b0 = (nf & 1) ? Bq[nf >> 1].z : Bq[nf >> 1].x;
                        uint32_t b1 = (nf & 1) ? Bq[nf >> 1].w : Bq[nf >> 1].y;
                        mma_f16(acc2[t][nf], ah2[t], b0, b1);
                    }
            }

#pragma unroll
            for (int t = 0; t < 2; t++) {
                int rbase = tt * MTILE + warpM + t * 16 + (lane >> 2);
#pragma unroll
                for (int nf = 0; nf < 4; nf++) {
                    int col = g * 32 + nf * 8 + (lane & 3) * 2;
#pragma unroll
                    for (int hh = 0; hh < 2; hh++) {
                        int row = rbase + hh * 8;
                        if (row < n) {
                            __half2 hp = __floats2half2_rn(
                                acc2[t][nf][hh * 2 + 0] + bs2[col],
                                acc2[t][nf][hh * 2 + 1] + bs2[col + 1]);
                            *reinterpret_cast<uint32_t*>(out2 + (size_t)row * 64 + col) =
                                *reinterpret_cast<uint32_t*>(&hp);
                        }
                    }
                }
            }
            __syncthreads();
        }
    }
}

// ---------------------------------------------------------------------------
// HMMA decoder: per 256-edge tile, gather zc[row]->chunk0, zp[col]->chunk1,
// 2-term f16 GEMM vs W1 (64x128), fused relu + (64->1) linear in epilogue.
// SMEM: [0..256) b1, [256..512) w2, [512..516) b2,
//       [1024..66560) A bufs 2x32768, [66560..99328) B frags (hi|lo 16384 each)
// 512 threads, 16 warps; warp tile 16(M) x 64(N).
// ---------------------------------------------------------------------------
__global__ __launch_bounds__(512, 1) void decoder_hmma(
    const __half* __restrict__ zc, const __half* __restrict__ zp,
    const int* __restrict__ rowIdx, const int* __restrict__ colIdx,
    const float* __restrict__ W1, const float* __restrict__ b1,
    const float* __restrict__ w2, const float* __restrict__ b2,
    float* __restrict__ out, int nE)
{
    constexpr int MTILE  = 256;
    constexpr int CHUNKB = MTILE * 128;             // 32768
    constexpr int BOFF   = 1024 + 2 * CHUNKB;       // 66560
    constexpr int BSPLIT = 8 * 4 * 32 * 16;         // 16384

    extern __shared__ char smem[];
    const uint32_t sb = smem_u32(smem);
    const int tid = threadIdx.x;
    const int w = tid >> 5, lane = tid & 31;
    const int warpM = w * 16;

    float* ps = (float*)smem;   // [0..63] b1, [64..127] w2, [128] b2
    if (tid < 64) ps[tid] = b1[tid];
    else if (tid < 128) ps[tid] = w2[tid - 64];
    else if (tid == 128) ps[128] = b2[0];

    // W1 fragments (hi then lo): KSTEPS=8, NF2=4
    for (int idx = tid; idx < 2 * 8 * 4 * 32; idx += 512) {
        int l = idx & 31;
        int rest = idx >> 5;
        int nfp = rest % 4;
        int rest2 = rest / 4;
        int ks = rest2 % 8;
        int s = rest2 / 8;
        uint32_t vals[4];
#pragma unroll
        for (int e = 0; e < 2; e++) {
            int nf = nfp * 2 + e;
            int nn = nf * 8 + (l >> 2);
            int k0 = ks * 16 + (l & 3) * 2;
            float2 wa = *reinterpret_cast<const float2*>(W1 + nn * 128 + k0);
            float2 wb = *reinterpret_cast<const float2*>(W1 + nn * 128 + k0 + 8);
            unsigned short h, lo, r00, r01, r10, r11;
            split1h(wa.x, h, lo); r00 = s ? lo : h;
            split1h(wa.y, h, lo); r01 = s ? lo : h;
            split1h(wb.x, h, lo); r10 = s ? lo : h;
            split1h(wb.y, h, lo); r11 = s ? lo : h;
            vals[e * 2 + 0] = (uint32_t)r00 | ((uint32_t)r01 << 16);
            vals[e * 2 + 1] = (uint32_t)r10 | ((uint32_t)r11 << 16);
        }
        *reinterpret_cast<uint4*>(smem + BOFF + (size_t)idx * 16) =
            make_uint4(vals[0], vals[1], vals[2], vals[3]);
    }
    __syncthreads();

    const int ntiles = (nE + MTILE - 1) / MTILE;

    for (int tt = blockIdx.x; tt < ntiles; tt += gridDim.x) {
        float acc[8][4];
#pragma unroll
        for (int nf = 0; nf < 8; nf++)
#pragma unroll
            for (int q = 0; q < 4; q++) acc[nf][q] = 0.f;

        auto stage = [&](int c, int b) {
            const __half* src = (c == 0) ? zc : zp;
            const int* idxp = (c == 0) ? rowIdx : colIdx;
#pragma unroll
            for (int it = 0; it < 4; it++) {
                int u = tid + it * 512;
                int r0 = u >> 3;
                int ch = u & 7;
                int e = tt * MTILE + r0;
                int idx = (e < nE) ? __ldg(idxp + e) : -1;
                uint32_t dst = sb + 1024 + b * CHUNKB +
                               SWZ((uint32_t)(r0 * 128 + ch * 16));
                const void* gp = src + (size_t)(idx < 0 ? 0 : idx) * 64 + ch * 8;
                cp16(dst, gp, (idx >= 0) ? 16 : 0);
            }
            CP_COMMIT();
        };

        stage(0, 0);

        for (int c = 0; c < 2; c++) {
            if (c == 0) { stage(1, 1); CP_WAIT1(); }
            else CP_WAIT0();
            __syncthreads();

            const uint32_t abase = sb + 1024 + c * CHUNKB;
#pragma unroll
            for (int ksl = 0; ksl < 4; ksl++) {
                const int ks = c * 4 + ksl;
                uint32_t ah[4];
                {
                    int arow = warpM + (lane & 15);
                    int colb = ksl * 32 + ((lane >> 4) << 4);
                    ldm4(abase + SWZ((uint32_t)(arow * 128 + colb)), ah);
                }
                uint4 Bq[4];
                {
                    size_t base = (size_t)BOFF + ((size_t)(ks * 4) * 32 + lane) * 16;
#pragma unroll
                    for (int p = 0; p < 4; p++)
                        Bq[p] = *reinterpret_cast<const uint4*>(smem + base + p * 512);
                }
#pragma unroll
                for (int nf = 0; nf < 8; nf++) {
                    uint32_t b0 = (nf & 1) ? Bq[nf >> 1].z : Bq[nf >> 1].x;
                    uint32_t b1v = (nf & 1) ? Bq[nf >> 1].w : Bq[nf >> 1].y;
                    mma_f16(acc[nf], ah, b0, b1v);
                }
                {
                    size_t base = (size_t)BOFF + BSPLIT + ((size_t)(ks * 4) * 32 + lane) * 16;
#pragma unroll
                    for (int p = 0; p < 4; p++)
                        Bq[p] = *reinterpret_cast<const uint4*>(smem + base + p * 512);
                }
#pragma unroll
                for (int nf = 0; nf < 8; nf++) {
                    uint32_t b0 = (nf & 1) ? Bq[nf >> 1].z : Bq[nf >> 1].x;
                    uint32_t b1v = (nf & 1) ? Bq[nf >> 1].w : Bq[nf >> 1].y;
                    mma_f16(acc[nf], ah, b0, b1v);
                }
            }
            __syncthreads();
        }

        // epilogue: h = relu(acc + b1); p = sum(h * w2); quad-reduce; + b2
        {
            float p0 = 0.f, p1 = 0.f;
#pragma unroll
            for (int nf = 0; nf < 8; nf++) {
                int col = nf * 8 + (lane & 3) * 2;
                float w20 = ps[64 + col], w21 = ps[64 + col + 1];
                float bb0 = ps[col], bb1 = ps[col + 1];
                p0 += fmaxf(acc[nf][0] + bb0, 0.f) * w20 +
                      fmaxf(acc[nf][1] + bb1, 0.f) * w21;
                p1 += fmaxf(acc[nf][2] + bb0, 0.f) * w20 +
                      fmaxf(acc[nf][3] + bb1, 0.f) * w21;
            }
            p0 += __shfl_xor_sync(0xffffffff, p0, 1);
            p0 += __shfl_xor_sync(0xffffffff, p0, 2);
            p1 += __shfl_xor_sync(0xffffffff, p1, 1);
            p1 += __shfl_xor_sync(0xffffffff, p1, 2);
            if ((lane & 3) == 0) {
                int e0 = tt * MTILE + warpM + (lane >> 2);
                if (e0 < nE) out[e0] = p0 + ps[128];
                if (e0 + 8 < nE) out[e0 + 8] = p1 + ps[128];
            }
        }
    }
}

// ---------------------------------------------------------------------------
// Host orchestration
// ---------------------------------------------------------------------------
extern "C" void kernel_launch(void* const* d_in, const int* in_sizes, int n_in,
                              void* d_out, int out_size) {
    const float* x_prod = (const float*)d_in[0];
    const float* x_cust = (const float*)d_in[1];
    const int* pp = (const int*)d_in[2];
    const int* pc = (const int*)d_in[3];
    const int* eli = (const int*)d_in[4];

    bool sig = (in_sizes[6] == HID);
    const float* it_W1l = (const float*)d_in[5];
    const float* it_W1r = (const float*)d_in[sig ? 7 : 6];
    const float* it_b1  = (const float*)d_in[sig ? 6 : 7];
    const float* it_W2l = (const float*)d_in[8];
    const float* it_W2r = (const float*)d_in[sig ? 10 : 9];
    const float* it_b2  = (const float*)d_in[sig ? 9 : 10];
    const float* it_Wlin = (const float*)d_in[11];
    const float* it_blin = (const float*)d_in[12];
    const float* us_W1l = (const float*)d_in[13];
    const float* us_W1r = (const float*)d_in[sig ? 15 : 14];
    const float* us_b1  = (const float*)d_in[sig ? 14 : 15];
    const float* us_W2l = (const float*)d_in[16];
    const float* us_W2r = (const float*)d_in[sig ? 18 : 17];
    const float* us_b2  = (const float*)d_in[sig ? 17 : 18];
    const float* us_W3l = (const float*)d_in[19];
    const float* us_W3r = (const float*)d_in[sig ? 21 : 20];
    const float* us_b3  = (const float*)d_in[sig ? 20 : 21];
    const float* us_Wlin = (const float*)d_in[22];
    const float* us_blin = (const float*)d_in[23];
    const float* de_W1 = (const float*)d_in[24];
    const float* de_b1 = (const float*)d_in[25];
    const float* de_W2 = (const float*)d_in[26];
    const float* de_b2 = (const float*)d_in[27];

#define GETP(var, sym, T) T* var; cudaGetSymbolAddress((void**)&var, sym)
    GETP(xP, g_xP, __half); GETP(xC, g_xC, __half);
    GETP(M0, g_M0, __half);
    GETP(P1, g_P1, __half); GETP(P2, g_P2, __half);
    GETP(C1, g_C1, __half);
    GETP(zprod, g_zprod, __half); GETP(zcust, g_zcust, __half);
    GETP(offP, g_offP, int); GETP(csrP, g_csrP, int);
    GETP(offC, g_offC, int); GETP(csrC, g_csrC, int);
#undef GETP

    constexpr int SM_PLAIN = 1024 + 2 * 32768 + 2 * 65536;   // 197632
    constexpr int SM_FUSED = SM_PLAIN + 2 * 16384;           // 230400
    constexpr int SM_DEC   = 1024 + 2 * 32768 + 2 * 16384;   // 99328
    cudaFuncSetAttribute((hmma_dual<false>),
                         cudaFuncAttributeMaxDynamicSharedMemorySize, SM_PLAIN);
    cudaFuncSetAttribute((hmma_dual<true>),
                         cudaFuncAttributeMaxDynamicSharedMemorySize, SM_FUSED);
    cudaFuncSetAttribute(decoder_hmma,
                         cudaFuncAttributeMaxDynamicSharedMemorySize, SM_DEC);

    const int nbP = (N_PROD + 1023) / 1024;
    const int nbC = (N_CUST + 1023) / 1024;
    const int PRE_ITEMS = (N_PROD + N_CUST) * HID / 4 + E_PP + E_PC;
    const int aggP_grid = (N_PROD * 32 + 255) / 256;
    const int aggC_grid = (N_CUST * 32 + 255) / 256;

    // 0-2: convert + counts, scans, fills
    k_pre<<<(PRE_ITEMS + 255) / 256, 256>>>(x_prod, x_cust, pp + E_PP, pc + E_PC);
    k_scan2x<<<nbP + nbC, 1024>>>();
    k_fill2x<<<(E_PP + E_PC + 255) / 256, 256>>>(pp, pc);

    // 3: M0 = mean_pp(x)
    agg_mean<<<aggP_grid, 256>>>(xP, offP, csrP, M0, N_PROD, E_PP);
    // 4: it layer1 -> P1
    hmma_dual<false><<<148, 512, SM_PLAIN>>>(
        M0, xP, it_W1l, it_W1r, it_b1, nullptr, nullptr, P1, nullptr, N_PROD);
    // 5: us layer1 -> P2
    hmma_dual<false><<<148, 512, SM_PLAIN>>>(
        M0, xP, us_W1l, us_W1r, us_b1, nullptr, nullptr, P2, nullptr, N_PROD);
    // 6: M0 = mean_pp(P1)
    agg_mean<<<aggP_grid, 256>>>(P1, offP, csrP, M0, N_PROD, E_PP);
    // 7: fused it layer2 + it linear -> zprod (fp16)
    hmma_dual<true><<<148, 512, SM_FUSED>>>(
        M0, P1, it_W2l, it_W2r, it_b2, it_Wlin, it_blin, nullptr, zprod, N_PROD);
    // 8: M0 = mean_pc(x)
    agg_mean<<<aggC_grid, 256>>>(xP, offC, csrC, M0, N_CUST, E_PC);
    // 9: us layer2 -> C1
    hmma_dual<false><<<148, 512, SM_PLAIN>>>(
        M0, xC, us_W2l, us_W2r, us_b2, nullptr, nullptr, C1, nullptr, N_CUST);
    // 10: M0 = mean_pc(P2)
    agg_mean<<<aggC_grid, 256>>>(P2, offC, csrC, M0, N_CUST, E_PC);
    // 11: fused us layer3 + us linear -> zcust (fp16)
    hmma_dual<true><<<148, 512, SM_FUSED>>>(
        M0, C1, us_W3l, us_W3r, us_b3, us_Wlin, us_blin, nullptr, zcust, N_CUST);

    // 12: HMMA decoder
    decoder_hmma<<<148, 512, SM_DEC>>>(zcust, zprod, eli, eli + E_LB,
                                       de_W1, de_b1, de_W2, de_b2,
                                       (float*)d_out, E_LB);

    // 13: restore zero invariant
    k_tail_zero<<<(N_PROD + 255) / 256, 256>>>();
}

// round 11
// speedup vs baseline: 2.3107x; 1.0413x over previous
#include <cuda_runtime.h>
#include <cuda_fp16.h>
#include <cstdint>

#define N_PROD 100000
#define N_CUST 50000
#define HID    128
#define DOUT   64
#define E_PP   800000
#define E_PC   800000
#define E_LB   400000

typedef unsigned long long u64;

#define SWZ(x) ((x) ^ (((x) >> 3) & 0x70))
#define TRIGGER_DEPENDENTS() asm volatile("griddepcontrol.launch_dependents;" ::: "memory")

__device__ __forceinline__ uint32_t smem_u32(const void* p) {
    uint32_t a;
    asm("{ .reg .u64 t; cvta.to.shared.u64 t, %1; cvt.u32.u64 %0, t; }" : "=r"(a) : "l"(p));
    return a;
}
__device__ __forceinline__ void cp16(uint32_t dst, const void* src, int sz) {
    asm volatile("cp.async.cg.shared.global [%0],[%1],16,%2;"
                 :: "r"(dst), "l"(src), "r"(sz));
}
#define CP_COMMIT() asm volatile("cp.async.commit_group;" ::: "memory")
#define CP_WAIT1()  asm volatile("cp.async.wait_group 1;" ::: "memory")
#define CP_WAIT0()  asm volatile("cp.async.wait_group 0;" ::: "memory")

__device__ __forceinline__ void ldm4(uint32_t addr, uint32_t* r) {
    asm volatile("ldmatrix.sync.aligned.m8n8.x4.shared.b16 {%0,%1,%2,%3},[%4];"
                 : "=r"(r[0]), "=r"(r[1]), "=r"(r[2]), "=r"(r[3]) : "r"(addr));
}
__device__ __forceinline__ void mma_f16(float* d, const uint32_t* a,
                                        uint32_t b0, uint32_t b1) {
    asm volatile(
        "mma.sync.aligned.m16n8k16.row.col.f32.f16.f16.f32 "
        "{%0,%1,%2,%3},{%4,%5,%6,%7},{%8,%9},{%0,%1,%2,%3};"
        : "+f"(d[0]), "+f"(d[1]), "+f"(d[2]), "+f"(d[3])
        : "r"(a[0]), "r"(a[1]), "r"(a[2]), "r"(a[3]), "r"(b0), "r"(b1));
}
__device__ __forceinline__ void split1h(float w, unsigned short& h, unsigned short& l) {
    __half hh = __float2half_rn(w);
    __half hl = __float2half_rn(w - __half2float(hh));
    h = __half_as_ushort(hh);
    l = __half_as_ushort(hl);
}
__device__ __forceinline__ u64 pack4h(float a0, float a1, float a2, float a3) {
    __half2 p0 = __floats2half2_rn(a0, a1);
    __half2 p1 = __floats2half2_rn(a2, a3);
    u64 r;
    asm("mov.b64 %0,{%1,%2};" : "=l"(r)
        : "r"(*reinterpret_cast<uint32_t*>(&p0)), "r"(*reinterpret_cast<uint32_t*>(&p1)));
    return r;
}

// ---------------------------------------------------------------------------
// Scratch (fp16 activation planes; fp16 z)
// ---------------------------------------------------------------------------
__device__ __half g_xP[(size_t)N_PROD * HID];
__device__ __half g_xC[(size_t)N_CUST * HID];
__device__ __half g_M0[(size_t)N_PROD * HID];    // product-side mean (reused)
__device__ __half g_M0C[(size_t)N_CUST * HID];   // customer-side mean (reused)
__device__ __half g_P1[(size_t)N_PROD * HID];
__device__ __half g_P2[(size_t)N_PROD * HID];
__device__ __half g_C1[(size_t)N_CUST * HID];
__device__ __half g_zprod[(size_t)N_PROD * DOUT];
__device__ __half g_zcust[(size_t)N_CUST * DOUT];

__device__ int g_cntP[N_PROD];
__device__ int g_cntC[N_CUST];
__device__ int g_offP[N_PROD];
__device__ int g_curP[N_PROD];
__device__ int g_csrP[E_PP];
__device__ int g_offC[N_CUST];
__device__ int g_curC[N_CUST];
__device__ int g_csrC[E_PC];
__device__ u64 g_lbP[128];
__device__ u64 g_lbC[64];

// ---------------------------------------------------------------------------
// Launch 0: convert x -> fp16 planes AND count both edge histograms
// ---------------------------------------------------------------------------
__global__ void k_pre(const float* __restrict__ xp, const float* __restrict__ xc,
                      const int* __restrict__ dstP, const int* __restrict__ dstC) {
    const int NP4 = N_PROD * HID / 4;
    const int NC4 = N_CUST * HID / 4;
    int i = blockIdx.x * blockDim.x + threadIdx.x;
    if (i < NP4 + NC4) {
        const float* src; __half* dh; int o;
        if (i < NP4) { src = xp; dh = g_xP; o = i; }
        else { src = xc; dh = g_xC; o = i - NP4; }
        float4 v = *reinterpret_cast<const float4*>(src + (size_t)o * 4);
        *reinterpret_cast<u64*>(dh + (size_t)o * 4) = pack4h(v.x, v.y, v.z, v.w);
        return;
    }
    int j = i - (NP4 + NC4);
    if (j < E_PP) { atomicAdd(&g_cntP[dstP[j]], 1); return; }
    j -= E_PP;
    if (j < E_PC) atomicAdd(&g_cntC[dstC[j]], 1);
}

// ---------------------------------------------------------------------------
// Launch 1: decoupled-lookback scan (P and C segments)
// ---------------------------------------------------------------------------
__device__ void scan_seg(const int* __restrict__ cnt, int n,
                         int* __restrict__ off, int* __restrict__ cur,
                         u64* __restrict__ st, int bid) {
    __shared__ int s[1024];
    __shared__ int s_prefix;
    int tx = threadIdx.x;
    int gid = bid * 1024 + tx;
    int v = (gid < n) ? cnt[gid] : 0;
    s[tx] = v;
    __syncthreads();
#pragma unroll
    for (int d = 1; d < 1024; d <<= 1) {
        int t = (tx >= d) ? s[tx - d] : 0;
        __syncthreads();
        s[tx] += t;
        __syncthreads();
    }
    int incl = s[tx];
    int total = s[1023];
    if (tx == 0) {
        if (bid == 0) {
            s_prefix = 0;
            atomicExch(st, ((u64)(unsigned)total << 32) | 2ULL);
        } else {
            atomicExch(st + bid, ((u64)(unsigned)total << 32) | 1ULL);
            int run = 0, j = bid - 1;
            while (true) {
                u64 x;
                do { x = atomicAdd(st + j, 0ULL); } while ((x & 3ULL) == 0ULL);
                run += (int)(unsigned)(x >> 32);
                if ((x & 3ULL) == 2ULL) break;
                j--;
            }
            s_prefix = run;
            atomicExch(st + bid, ((u64)(unsigned)(run + total) << 32) | 2ULL);
        }
    }
    __syncthreads();
    if (gid < n) {
        int e = s_prefix + incl - v;
        off[gid] = e;
        cur[gid] = e;
    }
}

__global__ void k_scan2x() {
    const int nbP = (N_PROD + 1023) / 1024;
    if ((int)blockIdx.x < nbP)
        scan_seg(g_cntP, N_PROD, g_offP, g_curP, g_lbP, blockIdx.x);
    else
        scan_seg(g_cntC, N_CUST, g_offC, g_curC, g_lbC, blockIdx.x - nbP);
}

__global__ void k_fill2x(const int* __restrict__ eP, const int* __restrict__ eC) {
    int e = blockIdx.x * blockDim.x + threadIdx.x;
    if (e < E_PP) {
        int d = eP[E_PP + e];
        int p = atomicAdd(&g_curP[d], 1);
        g_csrP[p] = eP[e];
    } else if (e < E_PP + E_PC) {
        int j = e - E_PP;
        int d = eC[E_PC + j];
        int p = atomicAdd(&g_curC[d], 1);
        g_csrC[p] = eC[j];
    }
}

// ---------------------------------------------------------------------------
// Mean aggregation body: one warp per node, fp16 in/out, unroll x4
// ---------------------------------------------------------------------------
__device__ __forceinline__ void agg_body(const __half* __restrict__ x,
                                         const int* __restrict__ off,
                                         const int* __restrict__ csr,
                                         __half* __restrict__ o,
                                         int w, int n, int E, int lane) {
    int beg = off[w];
    int end = (w + 1 < n) ? off[w + 1] : E;
    float a0 = 0.f, a1 = 0.f, a2 = 0.f, a3 = 0.f;
    int j = beg;
#define ACCH(p) do { \
    uint2 uu = *reinterpret_cast<uint2*>(&p); \
    float2 f0 = __half22float2(*reinterpret_cast<__half2*>(&uu.x)); \
    float2 f1 = __half22float2(*reinterpret_cast<__half2*>(&uu.y)); \
    a0 += f0.x; a1 += f0.y; a2 += f1.x; a3 += f1.y; \
} while (0)
    for (; j + 3 < end; j += 4) {
        int s0 = csr[j], s1 = csr[j + 1], s2 = csr[j + 2], s3 = csr[j + 3];
        u64 p0 = __ldg(reinterpret_cast<const u64*>(x + (size_t)s0 * HID + lane * 4));
        u64 p1 = __ldg(reinterpret_cast<const u64*>(x + (size_t)s1 * HID + lane * 4));
        u64 p2 = __ldg(reinterpret_cast<const u64*>(x + (size_t)s2 * HID + lane * 4));
        u64 p3 = __ldg(reinterpret_cast<const u64*>(x + (size_t)s3 * HID + lane * 4));
        ACCH(p0); ACCH(p1); ACCH(p2); ACCH(p3);
    }
    for (; j < end; j++) {
        int s0 = csr[j];
        u64 p = __ldg(reinterpret_cast<const u64*>(x + (size_t)s0 * HID + lane * 4));
        ACCH(p);
    }
#undef ACCH
    float sc = (end > beg) ? 1.0f / (float)(end - beg) : 0.f;
    *reinterpret_cast<u64*>(o + (size_t)w * HID + lane * 4) =
        pack4h(a0 * sc, a1 * sc, a2 * sc, a3 * sc);
}

// Both x-aggregations in one launch: warps [0,N_PROD) -> mean_pp(x)->M0,
// warps [N_PROD, N_PROD+N_CUST) -> mean_pc(x)->M0C
__global__ void agg2x() {
    int w = (blockIdx.x * blockDim.x + threadIdx.x) >> 5;
    int lane = threadIdx.x & 31;
    if (w < N_PROD)
        agg_body(g_xP, g_offP, g_csrP, g_M0, w, N_PROD, E_PP, lane);
    else if (w < N_PROD + N_CUST)
        agg_body(g_xP, g_offC, g_csrC, g_M0C, w - N_PROD, N_CUST, E_PC, lane);
}

// Single aggregation with optional early dependent-launch trigger
__global__ void agg_mean(const __half* __restrict__ x,
                         const int* __restrict__ off, const int* __restrict__ csr,
                         __half* __restrict__ o, int n, int E, int trig) {
    if (trig) TRIGGER_DEPENDENTS();
    int w = (blockIdx.x * blockDim.x + threadIdx.x) >> 5;
    int lane = threadIdx.x & 31;
    if (w < n) agg_body(x, off, csr, o, w, n, E, lane);
}

// ---------------------------------------------------------------------------
// Dual f16 GEMM (2-term weight split), K=256, N=128, MTILE=256, relu.
//   FUSE2: restage relu'd tile and run second GEMM (128->64), write fp16 z.
// ---------------------------------------------------------------------------
template <bool FUSE2>
__global__ __launch_bounds__(512, 1) void hmma_dual(
    const __half* __restrict__ A, const __half* __restrict__ X,
    const float* __restrict__ Wl, const float* __restrict__ Wr,
    const float* __restrict__ bias,
    const float* __restrict__ W2, const float* __restrict__ b2,
    __half* __restrict__ outP, __half* __restrict__ out2,
    int n, int trig)
{
    if (trig) TRIGGER_DEPENDENTS();
    constexpr int KSTEPS = 16;
    constexpr int NF2    = 8;
    constexpr int MTILE  = 256;
    constexpr int CHUNKB = MTILE * 128;
    constexpr int BOFF   = 1024 + 2 * CHUNKB;
    constexpr int BSPLIT = KSTEPS * NF2 * 32 * 16;
    constexpr int BOFF2  = BOFF + 2 * BSPLIT;
    constexpr int BSPLIT2 = 8 * 4 * 32 * 16;
    constexpr int NCHUNK = 4;
    constexpr int CPOPS  = MTILE * 8;

    extern __shared__ char smem[];
    const uint32_t sb = smem_u32(smem);
    const int tid = threadIdx.x;
    const int w = tid >> 5, lane = tid & 31;
    const int g     = w & 1;
    const int warpM = (w >> 1) * 32;

    float* bs = (float*)smem;
    float* bs2 = (float*)(smem + 512);
    if (tid < 128) bs[tid] = bias[tid];
    if (FUSE2 && tid >= 128 && tid < 192) bs2[tid - 128] = b2[tid - 128];

    for (int idx = tid; idx < 2 * KSTEPS * NF2 * 32; idx += 512) {
        int l = idx & 31;
        int rest = idx >> 5;
        int nfp = rest % NF2;
        int rest2 = rest / NF2;
        int ks = rest2 % KSTEPS;
        int s = rest2 / KSTEPS;
        uint32_t vals[4];
#pragma unroll
        for (int e = 0; e < 2; e++) {
            int nf = nfp * 2 + e;
            int nn = nf * 8 + (l >> 2);
            int k0 = ks * 16 + (l & 3) * 2;
            const float* wp = Wl;
            int kk = k0;
            if (k0 >= 128) { wp = Wr; kk = k0 - 128; }
            float2 wa = *reinterpret_cast<const float2*>(wp + nn * 128 + kk);
            float2 wb = *reinterpret_cast<const float2*>(wp + nn * 128 + kk + 8);
            unsigned short h, lo, r00, r01, r10, r11;
            split1h(wa.x, h, lo); r00 = s ? lo : h;
            split1h(wa.y, h, lo); r01 = s ? lo : h;
            split1h(wb.x, h, lo); r10 = s ? lo : h;
            split1h(wb.y, h, lo); r11 = s ? lo : h;
            vals[e * 2 + 0] = (uint32_t)r00 | ((uint32_t)r01 << 16);
            vals[e * 2 + 1] = (uint32_t)r10 | ((uint32_t)r11 << 16);
        }
        *reinterpret_cast<uint4*>(smem + BOFF + (size_t)idx * 16) =
            make_uint4(vals[0], vals[1], vals[2], vals[3]);
    }
    if (FUSE2) {
        for (int idx = tid; idx < 2 * 8 * 4 * 32; idx += 512) {
            int l = idx & 31;
            int rest = idx >> 5;
            int nfp = rest % 4;
            int rest2 = rest / 4;
            int ks = rest2 % 8;
            int s = rest2 / 8;
            uint32_t vals[4];
#pragma unroll
            for (int e = 0; e < 2; e++) {
                int nf = nfp * 2 + e;
                int nn = nf * 8 + (l >> 2);
                int k0 = ks * 16 + (l & 3) * 2;
                float2 wa = *reinterpret_cast<const float2*>(W2 + nn * 128 + k0);
                float2 wb = *reinterpret_cast<const float2*>(W2 + nn * 128 + k0 + 8);
                unsigned short h, lo, r00, r01, r10, r11;
                split1h(wa.x, h, lo); r00 = s ? lo : h;
                split1h(wa.y, h, lo); r01 = s ? lo : h;
                split1h(wb.x, h, lo); r10 = s ? lo : h;
                split1h(wb.y, h, lo); r11 = s ? lo : h;
                vals[e * 2 + 0] = (uint32_t)r00 | ((uint32_t)r01 << 16);
                vals[e * 2 + 1] = (uint32_t)r10 | ((uint32_t)r11 << 16);
            }
            *reinterpret_cast<uint4*>(smem + BOFF2 + (size_t)idx * 16) =
                make_uint4(vals[0], vals[1], vals[2], vals[3]);
        }
    }
    __syncthreads();

    const int ntiles = (n + MTILE - 1) / MTILE;

    for (int tt = blockIdx.x; tt < ntiles; tt += gridDim.x) {
        float acc[2][8][4];
#pragma unroll
        for (int t = 0; t < 2; t++)
#pragma unroll
            for (int nf = 0; nf < 8; nf++)
#pragma unroll
                for (int q = 0; q < 4; q++) acc[t][nf][q] = 0.f;

        auto stage = [&](int c, int b) {
            const __half* src = (c >= 2) ? X : A;
            const int colbase = (c & 1) * 64;
#pragma unroll
            for (int it = 0; it < CPOPS / 512; it++) {
                int u = tid + it * 512;
                int r0 = u >> 3;
                int ch = u & 7;
                int gr = tt * MTILE + r0;
                uint32_t dst = sb + 1024 + b * CHUNKB +
                               SWZ((uint32_t)(r0 * 128 + ch * 16));
                const void* gp = src + (size_t)gr * 128 + colbase + ch * 8;
                cp16(dst, gp, (gr < n) ? 16 : 0);
            }
            CP_COMMIT();
        };

        stage(0, 0);

        for (int c = 0; c < NCHUNK; c++) {
            if (c + 1 < NCHUNK) { stage(c + 1, (c + 1) & 1); CP_WAIT1(); }
            else CP_WAIT0();
            __syncthreads();

            const uint32_t abase = sb + 1024 + (c & 1) * CHUNKB;
#pragma unroll
            for (int ksl = 0; ksl < 4; ksl++) {
                const int ks = c * 4 + ksl;
                uint32_t ah[2][4];
#pragma unroll
                for (int t = 0; t < 2; t++) {
                    int arow = warpM + t * 16 + (lane & 15);
                    int colb = ksl * 32 + ((lane >> 4) << 4);
                    ldm4(abase + SWZ((uint32_t)(arow * 128 + colb)), ah[t]);
                }
                uint4 Bq[4];
                {
                    size_t base = (size_t)BOFF +
                        ((size_t)(ks * NF2 + g * 4) * 32 + lane) * 16;
#pragma unroll
                    for (int p = 0; p < 4; p++)
                        Bq[p] = *reinterpret_cast<const uint4*>(smem + base + p * 512);
                }
#pragma unroll
                for (int t = 0; t < 2; t++)
#pragma unroll
                    for (int nf = 0; nf < 8; nf++) {
                        uint32_t b0 = (nf & 1) ? Bq[nf >> 1].z : Bq[nf >> 1].x;
                        uint32_t b1 = (nf & 1) ? Bq[nf >> 1].w : Bq[nf >> 1].y;
                        mma_f16(acc[t][nf], ah[t], b0, b1);
                    }
                {
                    size_t base = (size_t)BOFF + BSPLIT +
                        ((size_t)(ks * NF2 + g * 4) * 32 + lane) * 16;
#pragma unroll
                    for (int p = 0; p < 4; p++)
                        Bq[p] = *reinterpret_cast<const uint4*>(smem + base + p * 512);
                }
#pragma unroll
                for (int t = 0; t < 2; t++)
#pragma unroll
                    for (int nf = 0; nf < 8; nf++) {
                        uint32_t b0 = (nf & 1) ? Bq[nf >> 1].z : Bq[nf >> 1].x;
                        uint32_t b1 = (nf & 1) ? Bq[nf >> 1].w : Bq[nf >> 1].y;
                        mma_f16(acc[t][nf], ah[t], b0, b1);
                    }
            }
            __syncthreads();
        }

        if (!FUSE2) {
#pragma unroll
            for (int t = 0; t < 2; t++) {
                int rbase = tt * MTILE + warpM + t * 16 + (lane >> 2);
#pragma unroll
                for (int nf = 0; nf < 8; nf++) {
                    int col = g * 64 + nf * 8 + (lane & 3) * 2;
#pragma unroll
                    for (int hh = 0; hh < 2; hh++) {
                        int row = rbase + hh * 8;
                        if (row < n) {
                            float ox = fmaxf(acc[t][nf][hh * 2 + 0] + bs[col], 0.f);
                            float oy = fmaxf(acc[t][nf][hh * 2 + 1] + bs[col + 1], 0.f);
                            __half2 hp = __floats2half2_rn(ox, oy);
                            *reinterpret_cast<uint32_t*>(outP + (size_t)row * 128 + col) =
                                *reinterpret_cast<uint32_t*>(&hp);
                        }
                    }
                }
            }
        } else {
#pragma unroll
            for (int t = 0; t < 2; t++) {
                int rl = warpM + t * 16 + (lane >> 2);
#pragma unroll
                for (int nf = 0; nf < 8; nf++) {
                    int col = g * 64 + nf * 8 + (lane & 3) * 2;
#pragma unroll
                    for (int hh = 0; hh < 2; hh++) {
                        int r = rl + hh * 8;
                        float ox = fmaxf(acc[t][nf][hh * 2 + 0] + bs[col], 0.f);
                        float oy = fmaxf(acc[t][nf][hh * 2 + 1] + bs[col + 1], 0.f);
                        __half2 hp = __floats2half2_rn(ox, oy);
                        uint32_t off = SWZ((uint32_t)(r * 128 + (col & 63) * 2));
                        *reinterpret_cast<uint32_t*>(smem + 1024 + g * CHUNKB + off) =
                            *reinterpret_cast<uint32_t*>(&hp);
                    }
                }
            }
            __syncthreads();

            float acc2[2][4][4];
#pragma unroll
            for (int t = 0; t < 2; t++)
#pragma unroll
                for (int nf = 0; nf < 4; nf++)
#pragma unroll
                    for (int q = 0; q < 4; q++) acc2[t][nf][q] = 0.f;

#pragma unroll
            for (int ks2 = 0; ks2 < 8; ks2++) {
                const int chunk = ks2 >> 2, ksl2 = ks2 & 3;
                const uint32_t abase2 = sb + 1024 + chunk * CHUNKB;
                uint32_t ah2[2][4];
#pragma unroll
                for (int t = 0; t < 2; t++) {
                    int arow = warpM + t * 16 + (lane & 15);
                    int colb = ksl2 * 32 + ((lane >> 4) << 4);
                    ldm4(abase2 + SWZ((uint32_t)(arow * 128 + colb)), ah2[t]);
                }
                uint4 Bq[2];
                {
                    size_t base = (size_t)BOFF2 +
                        ((size_t)(ks2 * 4 + g * 2) * 32 + lane) * 16;
                    Bq[0] = *reinterpret_cast<const uint4*>(smem + base);
                    Bq[1] = *reinterpret_cast<const uint4*>(smem + base + 512);
                }
#pragma unroll
                for (int t = 0; t < 2; t++)
#pragma unroll
                    for (int nf = 0; nf < 4; nf++) {
                        uint32_t b0 = (nf & 1) ? Bq[nf >> 1].z : Bq[nf >> 1].x;
                        uint32_t b1 = (nf & 1) ? Bq[nf >> 1].w : Bq[nf >> 1].y;
                        mma_f16(acc2[t][nf], ah2[t], b0, b1);
                    }
                {
                    size_t base = (size_t)BOFF2 + BSPLIT2 +
                        ((size_t)(ks2 * 4 + g * 2) * 32 + lane) * 16;
                    Bq[0] = *reinterpret_cast<const uint4*>(smem + base);
                    Bq[1] = *reinterpret_cast<const uint4*>(smem + base + 512);
                }
#pragma unroll
                for (int t = 0; t < 2; t++)
#pragma unroll
                    for (int nf = 0; nf < 4; nf++) {
                        uint32_t b0 = (nf & 1) ? Bq[nf >> 1].z : Bq[nf >> 1].x;
                        uint32_t b1 = (nf & 1) ? Bq[nf >> 1].w : Bq[nf >> 1].y;
                        mma_f16(acc2[t][nf], ah2[t], b0, b1);
                    }
            }

#pragma unroll
            for (int t = 0; t < 2; t++) {
                int rbase = tt * MTILE + warpM + t * 16 + (lane >> 2);
#pragma unroll
                for (int nf = 0; nf < 4; nf++) {
                    int col = g * 32 + nf * 8 + (lane & 3) * 2;
#pragma unroll
                    for (int hh = 0; hh < 2; hh++) {
                        int row = rbase + hh * 8;
                        if (row < n) {
                            __half2 hp = __floats2half2_rn(
                                acc2[t][nf][hh * 2 + 0] + bs2[col],
                                acc2[t][nf][hh * 2 + 1] + bs2[col + 1]);
                            *reinterpret_cast<uint32_t*>(out2 + (size_t)row * 64 + col) =
                                *reinterpret_cast<uint32_t*>(&hp);
                        }
                    }
                }
            }
            __syncthreads();
        }
    }
}

// ---------------------------------------------------------------------------
// HMMA decoder (+ scratch zeroing prologue for next call's invariant)
// ---------------------------------------------------------------------------
__global__ __launch_bounds__(512, 1) void decoder_hmma(
    const __half* __restrict__ zc, const __half* __restrict__ zp,
    const int* __restrict__ rowIdx, const int* __restrict__ colIdx,
    const float* __restrict__ W1, const float* __restrict__ b1,
    const float* __restrict__ w2, const float* __restrict__ b2,
    float* __restrict__ out, int nE)
{
    constexpr int MTILE  = 256;
    constexpr int CHUNKB = MTILE * 128;
    constexpr int BOFF   = 1024 + 2 * CHUNKB;
    constexpr int BSPLIT = 8 * 4 * 32 * 16;

    // restore zero invariant for the next kernel_launch call (independent arrays)
    for (int i = blockIdx.x * blockDim.x + threadIdx.x; i < N_PROD;
         i += gridDim.x * blockDim.x) {
        g_cntP[i] = 0;
        if (i < N_CUST) g_cntC[i] = 0;
        if (i < 128) g_lbP[i] = 0;
        if (i < 64) g_lbC[i] = 0;
    }

    extern __shared__ char smem[];
    const uint32_t sb = smem_u32(smem);
    const int tid = threadIdx.x;
    const int w = tid >> 5, lane = tid & 31;
    const int warpM = w * 16;

    float* ps = (float*)smem;
    if (tid < 64) ps[tid] = b1[tid];
    else if (tid < 128) ps[tid] = w2[tid - 64];
    else if (tid == 128) ps[128] = b2[0];

    for (int idx = tid; idx < 2 * 8 * 4 * 32; idx += 512) {
        int l = idx & 31;
        int rest = idx >> 5;
        int nfp = rest % 4;
        int rest2 = rest / 4;
        int ks = rest2 % 8;
        int s = rest2 / 8;
        uint32_t vals[4];
#pragma unroll
        for (int e = 0; e < 2; e++) {
            int nf = nfp * 2 + e;
            int nn = nf * 8 + (l >> 2);
            int k0 = ks * 16 + (l & 3) * 2;
            float2 wa = *reinterpret_cast<const float2*>(W1 + nn * 128 + k0);
            float2 wb = *reinterpret_cast<const float2*>(W1 + nn * 128 + k0 + 8);
            unsigned short h, lo, r00, r01, r10, r11;
            split1h(wa.x, h, lo); r00 = s ? lo : h;
            split1h(wa.y, h, lo); r01 = s ? lo : h;
            split1h(wb.x, h, lo); r10 = s ? lo : h;
            split1h(wb.y, h, lo); r11 = s ? lo : h;
            vals[e * 2 + 0] = (uint32_t)r00 | ((uint32_t)r01 << 16);
            vals[e * 2 + 1] = (uint32_t)r10 | ((uint32_t)r11 << 16);
        }
        *reinterpret_cast<uint4*>(smem + BOFF + (size_t)idx * 16) =
            make_uint4(vals[0], vals[1], vals[2], vals[3]);
    }
    __syncthreads();

    const int ntiles = (nE + MTILE - 1) / MTILE;

    for (int tt = blockIdx.x; tt < ntiles; tt += gridDim.x) {
        float acc[8][4];
#pragma unroll
        for (int nf = 0; nf < 8; nf++)
#pragma unroll
            for (int q = 0; q < 4; q++) acc[nf][q] = 0.f;

        auto stage = [&](int c, int b) {
            const __half* src = (c == 0) ? zc : zp;
            const int* idxp = (c == 0) ? rowIdx : colIdx;
#pragma unroll
            for (int it = 0; it < 4; it++) {
                int u = tid + it * 512;
                int r0 = u >> 3;
                int ch = u & 7;
                int e = tt * MTILE + r0;
                int idx = (e < nE) ? __ldg(idxp + e) : -1;
                uint32_t dst = sb + 1024 + b * CHUNKB +
                               SWZ((uint32_t)(r0 * 128 + ch * 16));
                const void* gp = src + (size_t)(idx < 0 ? 0 : idx) * 64 + ch * 8;
                cp16(dst, gp, (idx >= 0) ? 16 : 0);
            }
            CP_COMMIT();
        };

        stage(0, 0);

        for (int c = 0; c < 2; c++) {
            if (c == 0) { stage(1, 1); CP_WAIT1(); }
            else CP_WAIT0();
            __syncthreads();

            const uint32_t abase = sb + 1024 + c * CHUNKB;
#pragma unroll
            for (int ksl = 0; ksl < 4; ksl++) {
                const int ks = c * 4 + ksl;
                uint32_t ah[4];
                {
                    int arow = warpM + (lane & 15);
                    int colb = ksl * 32 + ((lane >> 4) << 4);
                    ldm4(abase + SWZ((uint32_t)(arow * 128 + colb)), ah);
                }
                uint4 Bq[4];
                {
                    size_t base = (size_t)BOFF + ((size_t)(ks * 4) * 32 + lane) * 16;
#pragma unroll
                    for (int p = 0; p < 4; p++)
                        Bq[p] = *reinterpret_cast<const uint4*>(smem + base + p * 512);
                }
#pragma unroll
                for (int nf = 0; nf < 8; nf++) {
                    uint32_t b0 = (nf & 1) ? Bq[nf >> 1].z : Bq[nf >> 1].x;
                    uint32_t b1v = (nf & 1) ? Bq[nf >> 1].w : Bq[nf >> 1].y;
                    mma_f16(acc[nf], ah, b0, b1v);
                }
                {
                    size_t base = (size_t)BOFF + BSPLIT + ((size_t)(ks * 4) * 32 + lane) * 16;
#pragma unroll
                    for (int p = 0; p < 4; p++)
                        Bq[p] = *reinterpret_cast<const uint4*>(smem + base + p * 512);
                }
#pragma unroll
                for (int nf = 0; nf < 8; nf++) {
                    uint32_t b0 = (nf & 1) ? Bq[nf >> 1].z : Bq[nf >> 1].x;
                    uint32_t b1v = (nf & 1) ? Bq[nf >> 1].w : Bq[nf >> 1].y;
                    mma_f16(acc[nf], ah, b0, b1v);
                }
            }
            __syncthreads();
        }

        {
            float p0 = 0.f, p1 = 0.f;
#pragma unroll
            for (int nf = 0; nf < 8; nf++) {
                int col = nf * 8 + (lane & 3) * 2;
                float w20 = ps[64 + col], w21 = ps[64 + col + 1];
                float bb0 = ps[col], bb1 = ps[col + 1];
                p0 += fmaxf(acc[nf][0] + bb0, 0.f) * w20 +
                      fmaxf(acc[nf][1] + bb1, 0.f) * w21;
                p1 += fmaxf(acc[nf][2] + bb0, 0.f) * w20 +
                      fmaxf(acc[nf][3] + bb1, 0.f) * w21;
            }
            p0 += __shfl_xor_sync(0xffffffff, p0, 1);
            p0 += __shfl_xor_sync(0xffffffff, p0, 2);
            p1 += __shfl_xor_sync(0xffffffff, p1, 1);
            p1 += __shfl_xor_sync(0xffffffff, p1, 2);
            if ((lane & 3) == 0) {
                int e0 = tt * MTILE + warpM + (lane >> 2);
                if (e0 < nE) out[e0] = p0 + ps[128];
                if (e0 + 8 < nE) out[e0 + 8] = p1 + ps[128];
            }
        }
    }
}

// ---------------------------------------------------------------------------
// Host orchestration (PDL overlap on independent pairs)
// ---------------------------------------------------------------------------
extern "C" void kernel_launch(void* const* d_in, const int* in_sizes, int n_in,
                              void* d_out, int out_size) {
    const float* x_prod = (const float*)d_in[0];
    const float* x_cust = (const float*)d_in[1];
    const int* pp = (const int*)d_in[2];
    const int* pc = (const int*)d_in[3];
    const int* eli = (const int*)d_in[4];

    bool sig = (in_sizes[6] == HID);
    const float* it_W1l = (const float*)d_in[5];
    const float* it_W1r = (const float*)d_in[sig ? 7 : 6];
    const float* it_b1  = (const float*)d_in[sig ? 6 : 7];
    const float* it_W2l = (const float*)d_in[8];
    const float* it_W2r = (const float*)d_in[sig ? 10 : 9];
    const float* it_b2  = (const float*)d_in[sig ? 9 : 10];
    const float* it_Wlin = (const float*)d_in[11];
    const float* it_blin = (const float*)d_in[12];
    const float* us_W1l = (const float*)d_in[13];
    const float* us_W1r = (const float*)d_in[sig ? 15 : 14];
    const float* us_b1  = (const float*)d_in[sig ? 14 : 15];
    const float* us_W2l = (const float*)d_in[16];
    const float* us_W2r = (const float*)d_in[sig ? 18 : 17];
    const float* us_b2  = (const float*)d_in[sig ? 17 : 18];
    const float* us_W3l = (const float*)d_in[19];
    const float* us_W3r = (const float*)d_in[sig ? 21 : 20];
    const float* us_b3  = (const float*)d_in[sig ? 20 : 21];
    const float* us_Wlin = (const float*)d_in[22];
    const float* us_blin = (const float*)d_in[23];
    const float* de_W1 = (const float*)d_in[24];
    const float* de_b1 = (const float*)d_in[25];
    const float* de_W2 = (const float*)d_in[26];
    const float* de_b2 = (const float*)d_in[27];

#define GETP(var, sym, T) T* var; cudaGetSymbolAddress((void**)&var, sym)
    GETP(xP, g_xP, __half); GETP(xC, g_xC, __half);
    GETP(M0, g_M0, __half); GETP(M0C, g_M0C, __half);
    GETP(P1, g_P1, __half); GETP(P2, g_P2, __half);
    GETP(C1, g_C1, __half);
    GETP(zprod, g_zprod, __half); GETP(zcust, g_zcust, __half);
    GETP(offP, g_offP, int); GETP(csrP, g_csrP, int);
    GETP(offC, g_offC, int); GETP(csrC, g_csrC, int);
#undef GETP

    constexpr int SM_PLAIN = 1024 + 2 * 32768 + 2 * 65536;   // 197632
    constexpr int SM_FUSED = SM_PLAIN + 2 * 16384;           // 230400
    constexpr int SM_DEC   = 1024 + 2 * 32768 + 2 * 16384;   // 99328
    cudaFuncSetAttribute((hmma_dual<false>),
                         cudaFuncAttributeMaxDynamicSharedMemorySize, SM_PLAIN);
    cudaFuncSetAttribute((hmma_dual<true>),
                         cudaFuncAttributeMaxDynamicSharedMemorySize, SM_FUSED);
    cudaFuncSetAttribute(decoder_hmma,
                         cudaFuncAttributeMaxDynamicSharedMemorySize, SM_DEC);

    const int nbP = (N_PROD + 1023) / 1024;
    const int nbC = (N_CUST + 1023) / 1024;
    const int PRE_ITEMS = (N_PROD + N_CUST) * HID / 4 + E_PP + E_PC;
    const int agg2x_grid = ((N_PROD + N_CUST) * 32 + 255) / 256;
    const int aggP_grid = (N_PROD * 32 + 255) / 256;
    const int aggC_grid = (N_CUST * 32 + 255) / 256;

    // PDL launch config helpers
    cudaLaunchAttribute pdlAttr[1];
    pdlAttr[0].id = cudaLaunchAttributeProgrammaticStreamSerialization;
    pdlAttr[0].val.programmaticStreamSerializationAllowed = 1;

    cudaLaunchConfig_t cfgGemm{};
    cfgGemm.gridDim = dim3(148); cfgGemm.blockDim = dim3(512);
    cfgGemm.dynamicSmemBytes = SM_PLAIN; cfgGemm.stream = 0;
    cfgGemm.attrs = pdlAttr; cfgGemm.numAttrs = 1;

    cudaLaunchConfig_t cfgAggC{};
    cfgAggC.gridDim = dim3(aggC_grid); cfgAggC.blockDim = dim3(256);
    cfgAggC.dynamicSmemBytes = 0; cfgAggC.stream = 0;
    cfgAggC.attrs = pdlAttr; cfgAggC.numAttrs = 1;

    // 0-2: convert + counts, scans, fills (serial dependencies)
    k_pre<<<(PRE_ITEMS + 255) / 256, 256>>>(x_prod, x_cust, pp + E_PP, pc + E_PC);
    k_scan2x<<<nbP + nbC, 1024>>>();
    k_fill2x<<<(E_PP + E_PC + 255) / 256, 256>>>(pp, pc);

    // 3: both x-aggregations: M0 = mean_pp(x), M0C = mean_pc(x)
    agg2x<<<agg2x_grid, 256>>>();

    // 4: G1 it layer1 -> P1 (triggers dependents early: G2 independent of G1)
    hmma_dual<false><<<148, 512, SM_PLAIN>>>(
        M0, xP, it_W1l, it_W1r, it_b1, nullptr, nullptr, P1, nullptr, N_PROD, 1);
    // 5: G2 us layer1 -> P2 [PDL secondary: overlaps G1]
    cudaLaunchKernelEx(&cfgGemm, hmma_dual<false>,
        (const __half*)M0, (const __half*)xP, us_W1l, us_W1r, us_b1,
        (const float*)nullptr, (const float*)nullptr,
        (__half*)P2, (__half*)nullptr, (int)N_PROD, 0);

    // 6: M0 = mean_pp(P1) (waits G1+G2; triggers early: G5 independent)
    agg_mean<<<aggP_grid, 256>>>(P1, offP, csrP, M0, N_PROD, E_PP, 1);
    // 7: G5 us layer2 -> C1 [PDL secondary: overlaps agg; needs only M0C/xC (done)]
    cudaLaunchKernelEx(&cfgGemm, hmma_dual<false>,
        (const __half*)M0C, (const __half*)xC, us_W2l, us_W2r, us_b2,
        (const float*)nullptr, (const float*)nullptr,
        (__half*)C1, (__half*)nullptr, (int)N_CUST, 0);

    // 8: fused it layer2 + it linear -> zprod (waits all; triggers: aggPC2 indep)
    hmma_dual<true><<<148, 512, SM_FUSED>>>(
        M0, P1, it_W2l, it_W2r, it_b2, it_Wlin, it_blin, nullptr, zprod, N_PROD, 1);
    // 9: M0C = mean_pc(P2) [PDL secondary: overlaps fused GEMM; needs P2 (done)]
    cudaLaunchKernelEx(&cfgAggC, agg_mean,
        (const __half*)P2, (const int*)offC, (const int*)csrC,
        (__half*)M0C, (int)N_CUST, (int)E_PC, 0);

    // 10: fused us layer3 + us linear -> zcust (waits all)
    hmma_dual<true><<<148, 512, SM_FUSED>>>(
        M0C, C1, us_W3l, us_W3r, us_b3, us_Wlin, us_blin, nullptr, zcust, N_CUST, 0);

    // 11: HMMA decoder (+ zero-invariant restore in prologue)
    decoder_hmma<<<148, 512, SM_DEC>>>(zcust, zprod, eli, eli + E_LB,
                                       de_W1, de_b1, de_W2, de_b2,
                                       (float*)d_out, E_LB);
}

// round 12
// speedup vs baseline: 2.4841x; 1.0750x over previous
#include <cuda_runtime.h>
#include <cuda_fp16.h>
#include <cstdint>

#define N_PROD 100000
#define N_CUST 50000
#define HID    128
#define DOUT   64
#define E_PP   800000
#define E_PC   800000
#define E_LB   400000

typedef unsigned long long u64;

#define SWZ(x) ((x) ^ (((x) >> 3) & 0x70))
#define TRIGGER_DEPENDENTS() asm volatile("griddepcontrol.launch_dependents;" ::: "memory")

__device__ __forceinline__ uint32_t smem_u32(const void* p) {
    uint32_t a;
    asm("{ .reg .u64 t; cvta.to.shared.u64 t, %1; cvt.u32.u64 %0, t; }" : "=r"(a) : "l"(p));
    return a;
}
__device__ __forceinline__ void cp16(uint32_t dst, const void* src, int sz) {
    asm volatile("cp.async.cg.shared.global [%0],[%1],16,%2;"
                 :: "r"(dst), "l"(src), "r"(sz));
}
#define CP_COMMIT() asm volatile("cp.async.commit_group;" ::: "memory")
#define CP_WAIT1()  asm volatile("cp.async.wait_group 1;" ::: "memory")
#define CP_WAIT0()  asm volatile("cp.async.wait_group 0;" ::: "memory")

__device__ __forceinline__ void ldm4(uint32_t addr, uint32_t* r) {
    asm volatile("ldmatrix.sync.aligned.m8n8.x4.shared.b16 {%0,%1,%2,%3},[%4];"
                 : "=r"(r[0]), "=r"(r[1]), "=r"(r[2]), "=r"(r[3]) : "r"(addr));
}
__device__ __forceinline__ void mma_f16(float* d, const uint32_t* a,
                                        uint32_t b0, uint32_t b1) {
    asm volatile(
        "mma.sync.aligned.m16n8k16.row.col.f32.f16.f16.f32 "
        "{%0,%1,%2,%3},{%4,%5,%6,%7},{%8,%9},{%0,%1,%2,%3};"
        : "+f"(d[0]), "+f"(d[1]), "+f"(d[2]), "+f"(d[3])
        : "r"(a[0]), "r"(a[1]), "r"(a[2]), "r"(a[3]), "r"(b0), "r"(b1));
}
__device__ __forceinline__ void split1h(float w, unsigned short& h, unsigned short& l) {
    __half hh = __float2half_rn(w);
    __half hl = __float2half_rn(w - __half2float(hh));
    h = __half_as_ushort(hh);
    l = __half_as_ushort(hl);
}
__device__ __forceinline__ u64 pack4h(float a0, float a1, float a2, float a3) {
    __half2 p0 = __floats2half2_rn(a0, a1);
    __half2 p1 = __floats2half2_rn(a2, a3);
    u64 r;
    asm("mov.b64 %0,{%1,%2};" : "=l"(r)
        : "r"(*reinterpret_cast<uint32_t*>(&p0)), "r"(*reinterpret_cast<uint32_t*>(&p1)));
    return r;
}

// ---------------------------------------------------------------------------
// Scratch (fp16 activation planes; fp16 z)
// ---------------------------------------------------------------------------
__device__ __half g_xP[(size_t)N_PROD * HID];
__device__ __half g_xC[(size_t)N_CUST * HID];
__device__ __half g_M0[(size_t)N_PROD * HID];
__device__ __half g_M0C[(size_t)N_CUST * HID];
__device__ __half g_P1[(size_t)N_PROD * HID];
__device__ __half g_P2[(size_t)N_PROD * HID];
__device__ __half g_C1[(size_t)N_CUST * HID];
__device__ __half g_zprod[(size_t)N_PROD * DOUT];
__device__ __half g_zcust[(size_t)N_CUST * DOUT];

__device__ int g_cntP[N_PROD];
__device__ int g_cntC[N_CUST];
__device__ int g_offP[N_PROD];
__device__ int g_curP[N_PROD];
__device__ int g_csrP[E_PP];
__device__ int g_offC[N_CUST];
__device__ int g_curC[N_CUST];
__device__ int g_csrC[E_PC];
__device__ u64 g_lbP[128];
__device__ u64 g_lbC[64];

// ---------------------------------------------------------------------------
// Launch 0: convert x -> fp16 planes AND count both edge histograms
// ---------------------------------------------------------------------------
__global__ void k_pre(const float* __restrict__ xp, const float* __restrict__ xc,
                      const int* __restrict__ dstP, const int* __restrict__ dstC) {
    const int NP4 = N_PROD * HID / 4;
    const int NC4 = N_CUST * HID / 4;
    int i = blockIdx.x * blockDim.x + threadIdx.x;
    if (i < NP4 + NC4) {
        const float* src; __half* dh; int o;
        if (i < NP4) { src = xp; dh = g_xP; o = i; }
        else { src = xc; dh = g_xC; o = i - NP4; }
        float4 v = *reinterpret_cast<const float4*>(src + (size_t)o * 4);
        *reinterpret_cast<u64*>(dh + (size_t)o * 4) = pack4h(v.x, v.y, v.z, v.w);
        return;
    }
    int j = i - (NP4 + NC4);
    if (j < E_PP) { atomicAdd(&g_cntP[dstP[j]], 1); return; }
    j -= E_PP;
    if (j < E_PC) atomicAdd(&g_cntC[dstC[j]], 1);
}

// ---------------------------------------------------------------------------
// Launch 1: decoupled-lookback scan (P and C segments)
// ---------------------------------------------------------------------------
__device__ void scan_seg(const int* __restrict__ cnt, int n,
                         int* __restrict__ off, int* __restrict__ cur,
                         u64* __restrict__ st, int bid) {
    __shared__ int s[1024];
    __shared__ int s_prefix;
    int tx = threadIdx.x;
    int gid = bid * 1024 + tx;
    int v = (gid < n) ? cnt[gid] : 0;
    s[tx] = v;
    __syncthreads();
#pragma unroll
    for (int d = 1; d < 1024; d <<= 1) {
        int t = (tx >= d) ? s[tx - d] : 0;
        __syncthreads();
        s[tx] += t;
        __syncthreads();
    }
    int incl = s[tx];
    int total = s[1023];
    if (tx == 0) {
        if (bid == 0) {
            s_prefix = 0;
            atomicExch(st, ((u64)(unsigned)total << 32) | 2ULL);
        } else {
            atomicExch(st + bid, ((u64)(unsigned)total << 32) | 1ULL);
            int run = 0, j = bid - 1;
            while (true) {
                u64 x;
                do { x = atomicAdd(st + j, 0ULL); } while ((x & 3ULL) == 0ULL);
                run += (int)(unsigned)(x >> 32);
                if ((x & 3ULL) == 2ULL) break;
                j--;
            }
            s_prefix = run;
            atomicExch(st + bid, ((u64)(unsigned)(run + total) << 32) | 2ULL);
        }
    }
    __syncthreads();
    if (gid < n) {
        int e = s_prefix + incl - v;
        off[gid] = e;
        cur[gid] = e;
    }
}

__global__ void k_scan2x() {
    const int nbP = (N_PROD + 1023) / 1024;
    if ((int)blockIdx.x < nbP)
        scan_seg(g_cntP, N_PROD, g_offP, g_curP, g_lbP, blockIdx.x);
    else
        scan_seg(g_cntC, N_CUST, g_offC, g_curC, g_lbC, blockIdx.x - nbP);
}

__global__ void k_fill2x(const int* __restrict__ eP, const int* __restrict__ eC) {
    int e = blockIdx.x * blockDim.x + threadIdx.x;
    if (e < E_PP) {
        int d = eP[E_PP + e];
        int p = atomicAdd(&g_curP[d], 1);
        g_csrP[p] = eP[e];
    } else if (e < E_PP + E_PC) {
        int j = e - E_PP;
        int d = eC[E_PC + j];
        int p = atomicAdd(&g_curC[d], 1);
        g_csrC[p] = eC[j];
    }
}

// ---------------------------------------------------------------------------
// Mean aggregation body: HADD2 pairwise tree (fp16 pair-sum, fp32 accumulate)
// ---------------------------------------------------------------------------
__device__ __forceinline__ void agg_body(const __half* __restrict__ x,
                                         const int* __restrict__ off,
                                         const int* __restrict__ csr,
                                         __half* __restrict__ o,
                                         int w, int n, int E, int lane) {
    int beg = off[w];
    int end = (w + 1 < n) ? off[w + 1] : E;
    float a0 = 0.f, a1 = 0.f, a2 = 0.f, a3 = 0.f;
    int j = beg;
    for (; j + 3 < end; j += 4) {
        int s0 = csr[j], s1 = csr[j + 1], s2 = csr[j + 2], s3 = csr[j + 3];
        u64 p0 = __ldg(reinterpret_cast<const u64*>(x + (size_t)s0 * HID + lane * 4));
        u64 p1 = __ldg(reinterpret_cast<const u64*>(x + (size_t)s1 * HID + lane * 4));
        u64 p2 = __ldg(reinterpret_cast<const u64*>(x + (size_t)s2 * HID + lane * 4));
        u64 p3 = __ldg(reinterpret_cast<const u64*>(x + (size_t)s3 * HID + lane * 4));
        uint2 u0 = *reinterpret_cast<uint2*>(&p0);
        uint2 u1 = *reinterpret_cast<uint2*>(&p1);
        uint2 u2 = *reinterpret_cast<uint2*>(&p2);
        uint2 u3 = *reinterpret_cast<uint2*>(&p3);
        __half2 q0 = __hadd2(*reinterpret_cast<__half2*>(&u0.x),
                             *reinterpret_cast<__half2*>(&u1.x));
        __half2 q1 = __hadd2(*reinterpret_cast<__half2*>(&u0.y),
                             *reinterpret_cast<__half2*>(&u1.y));
        __half2 q2 = __hadd2(*reinterpret_cast<__half2*>(&u2.x),
                             *reinterpret_cast<__half2*>(&u3.x));
        __half2 q3 = __hadd2(*reinterpret_cast<__half2*>(&u2.y),
                             *reinterpret_cast<__half2*>(&u3.y));
        float2 f;
        f = __half22float2(q0); a0 += f.x; a1 += f.y;
        f = __half22float2(q1); a2 += f.x; a3 += f.y;
        f = __half22float2(q2); a0 += f.x; a1 += f.y;
        f = __half22float2(q3); a2 += f.x; a3 += f.y;
    }
    for (; j < end; j++) {
        int s0 = csr[j];
        u64 p = __ldg(reinterpret_cast<const u64*>(x + (size_t)s0 * HID + lane * 4));
        uint2 uu = *reinterpret_cast<uint2*>(&p);
        float2 f0 = __half22float2(*reinterpret_cast<__half2*>(&uu.x));
        float2 f1 = __half22float2(*reinterpret_cast<__half2*>(&uu.y));
        a0 += f0.x; a1 += f0.y; a2 += f1.x; a3 += f1.y;
    }
    float sc = (end > beg) ? 1.0f / (float)(end - beg) : 0.f;
    *reinterpret_cast<u64*>(o + (size_t)w * HID + lane * 4) =
        pack4h(a0 * sc, a1 * sc, a2 * sc, a3 * sc);
}

// Both x-aggregations in one launch
__global__ void agg2x() {
    int w = (blockIdx.x * blockDim.x + threadIdx.x) >> 5;
    int lane = threadIdx.x & 31;
    if (w < N_PROD)
        agg_body(g_xP, g_offP, g_csrP, g_M0, w, N_PROD, E_PP, lane);
    else if (w < N_PROD + N_CUST)
        agg_body(g_xP, g_offC, g_csrC, g_M0C, w - N_PROD, N_CUST, E_PC, lane);
}

__global__ void agg_mean(const __half* __restrict__ x,
                         const int* __restrict__ off, const int* __restrict__ csr,
                         __half* __restrict__ o, int n, int E, int trig) {
    if (trig) TRIGGER_DEPENDENTS();
    int w = (blockIdx.x * blockDim.x + threadIdx.x) >> 5;
    int lane = threadIdx.x & 31;
    if (w < n) agg_body(x, off, csr, o, w, n, E, lane);
}

// ---------------------------------------------------------------------------
// Dual f16 GEMM (2-term weight split), K=256, N=128, MTILE=256, relu.
//   FUSE2: restage relu'd tile and run second GEMM (128->64), write fp16 z.
// ---------------------------------------------------------------------------
template <bool FUSE2>
__global__ __launch_bounds__(512, 1) void hmma_dual(
    const __half* __restrict__ A, const __half* __restrict__ X,
    const float* __restrict__ Wl, const float* __restrict__ Wr,
    const float* __restrict__ bias,
    const float* __restrict__ W2, const float* __restrict__ b2,
    __half* __restrict__ outP, __half* __restrict__ out2,
    int n, int trig)
{
    if (trig) TRIGGER_DEPENDENTS();
    constexpr int KSTEPS = 16;
    constexpr int NF2    = 8;
    constexpr int MTILE  = 256;
    constexpr int CHUNKB = MTILE * 128;
    constexpr int BOFF   = 1024 + 2 * CHUNKB;
    constexpr int BSPLIT = KSTEPS * NF2 * 32 * 16;
    constexpr int BOFF2  = BOFF + 2 * BSPLIT;
    constexpr int BSPLIT2 = 8 * 4 * 32 * 16;
    constexpr int NCHUNK = 4;
    constexpr int CPOPS  = MTILE * 8;

    extern __shared__ char smem[];
    const uint32_t sb = smem_u32(smem);
    const int tid = threadIdx.x;
    const int w = tid >> 5, lane = tid & 31;
    const int g     = w & 1;
    const int warpM = (w >> 1) * 32;

    float* bs = (float*)smem;
    float* bs2 = (float*)(smem + 512);
    if (tid < 128) bs[tid] = bias[tid];
    if (FUSE2 && tid >= 128 && tid < 192) bs2[tid - 128] = b2[tid - 128];

    for (int idx = tid; idx < 2 * KSTEPS * NF2 * 32; idx += 512) {
        int l = idx & 31;
        int rest = idx >> 5;
        int nfp = rest % NF2;
        int rest2 = rest / NF2;
        int ks = rest2 % KSTEPS;
        int s = rest2 / KSTEPS;
        uint32_t vals[4];
#pragma unroll
        for (int e = 0; e < 2; e++) {
            int nf = nfp * 2 + e;
            int nn = nf * 8 + (l >> 2);
            int k0 = ks * 16 + (l & 3) * 2;
            const float* wp = Wl;
            int kk = k0;
            if (k0 >= 128) { wp = Wr; kk = k0 - 128; }
            float2 wa = *reinterpret_cast<const float2*>(wp + nn * 128 + kk);
            float2 wb = *reinterpret_cast<const float2*>(wp + nn * 128 + kk + 8);
            unsigned short h, lo, r00, r01, r10, r11;
            split1h(wa.x, h, lo); r00 = s ? lo : h;
            split1h(wa.y, h, lo); r01 = s ? lo : h;
            split1h(wb.x, h, lo); r10 = s ? lo : h;
            split1h(wb.y, h, lo); r11 = s ? lo : h;
            vals[e * 2 + 0] = (uint32_t)r00 | ((uint32_t)r01 << 16);
            vals[e * 2 + 1] = (uint32_t)r10 | ((uint32_t)r11 << 16);
        }
        *reinterpret_cast<uint4*>(smem + BOFF + (size_t)idx * 16) =
            make_uint4(vals[0], vals[1], vals[2], vals[3]);
    }
    if (FUSE2) {
        for (int idx = tid; idx < 2 * 8 * 4 * 32; idx += 512) {
            int l = idx & 31;
            int rest = idx >> 5;
            int nfp = rest % 4;
            int rest2 = rest / 4;
            int ks = rest2 % 8;
            int s = rest2 / 8;
            uint32_t vals[4];
#pragma unroll
            for (int e = 0; e < 2; e++) {
                int nf = nfp * 2 + e;
                int nn = nf * 8 + (l >> 2);
                int k0 = ks * 16 + (l & 3) * 2;
                float2 wa = *reinterpret_cast<const float2*>(W2 + nn * 128 + k0);
                float2 wb = *reinterpret_cast<const float2*>(W2 + nn * 128 + k0 + 8);
                unsigned short h, lo, r00, r01, r10, r11;
                split1h(wa.x, h, lo); r00 = s ? lo : h;
                split1h(wa.y, h, lo); r01 = s ? lo : h;
                split1h(wb.x, h, lo); r10 = s ? lo : h;
                split1h(wb.y, h, lo); r11 = s ? lo : h;
                vals[e * 2 + 0] = (uint32_t)r00 | ((uint32_t)r01 << 16);
                vals[e * 2 + 1] = (uint32_t)r10 | ((uint32_t)r11 << 16);
            }
            *reinterpret_cast<uint4*>(smem + BOFF2 + (size_t)idx * 16) =
                make_uint4(vals[0], vals[1], vals[2], vals[3]);
        }
    }
    __syncthreads();

    const int ntiles = (n + MTILE - 1) / MTILE;

    for (int tt = blockIdx.x; tt < ntiles; tt += gridDim.x) {
        float acc[2][8][4];
#pragma unroll
        for (int t = 0; t < 2; t++)
#pragma unroll
            for (int nf = 0; nf < 8; nf++)
#pragma unroll
                for (int q = 0; q < 4; q++) acc[t][nf][q] = 0.f;

        auto stage = [&](int c, int b) {
            const __half* src = (c >= 2) ? X : A;
            const int colbase = (c & 1) * 64;
#pragma unroll
            for (int it = 0; it < CPOPS / 512; it++) {
                int u = tid + it * 512;
                int r0 = u >> 3;
                int ch = u & 7;
                int gr = tt * MTILE + r0;
                uint32_t dst = sb + 1024 + b * CHUNKB +
                               SWZ((uint32_t)(r0 * 128 + ch * 16));
                const void* gp = src + (size_t)gr * 128 + colbase + ch * 8;
                cp16(dst, gp, (gr < n) ? 16 : 0);
            }
            CP_COMMIT();
        };

        stage(0, 0);

        for (int c = 0; c < NCHUNK; c++) {
            if (c + 1 < NCHUNK) { stage(c + 1, (c + 1) & 1); CP_WAIT1(); }
            else CP_WAIT0();
            __syncthreads();

            const uint32_t abase = sb + 1024 + (c & 1) * CHUNKB;
#pragma unroll
            for (int ksl = 0; ksl < 4; ksl++) {
                const int ks = c * 4 + ksl;
                uint32_t ah[2][4];
#pragma unroll
                for (int t = 0; t < 2; t++) {
                    int arow = warpM + t * 16 + (lane & 15);
                    int colb = ksl * 32 + ((lane >> 4) << 4);
                    ldm4(abase + SWZ((uint32_t)(arow * 128 + colb)), ah[t]);
                }
                uint4 Bq[4];
                {
                    size_t base = (size_t)BOFF +
                        ((size_t)(ks * NF2 + g * 4) * 32 + lane) * 16;
#pragma unroll
                    for (int p = 0; p < 4; p++)
                        Bq[p] = *reinterpret_cast<const uint4*>(smem + base + p * 512);
                }
#pragma unroll
                for (int t = 0; t < 2; t++)
#pragma unroll
                    for (int nf = 0; nf < 8; nf++) {
                        uint32_t b0 = (nf & 1) ? Bq[nf >> 1].z : Bq[nf >> 1].x;
                        uint32_t b1 = (nf & 1) ? Bq[nf >> 1].w : Bq[nf >> 1].y;
                        mma_f16(acc[t][nf], ah[t], b0, b1);
                    }
                {
                    size_t base = (size_t)BOFF + BSPLIT +
                        ((size_t)(ks * NF2 + g * 4) * 32 + lane) * 16;
#pragma unroll
                    for (int p = 0; p < 4; p++)
                        Bq[p] = *reinterpret_cast<const uint4*>(smem + base + p * 512);
                }
#pragma unroll
                for (int t = 0; t < 2; t++)
#pragma unroll
                    for (int nf = 0; nf < 8; nf++) {
                        uint32_t b0 = (nf & 1) ? Bq[nf >> 1].z : Bq[nf >> 1].x;
                        uint32_t b1 = (nf & 1) ? Bq[nf >> 1].w : Bq[nf >> 1].y;
                        mma_f16(acc[t][nf], ah[t], b0, b1);
                    }
            }
            __syncthreads();
        }

        if (!FUSE2) {
#pragma unroll
            for (int t = 0; t < 2; t++) {
                int rbase = tt * MTILE + warpM + t * 16 + (lane >> 2);
#pragma unroll
                for (int nf = 0; nf < 8; nf++) {
                    int col = g * 64 + nf * 8 + (lane & 3) * 2;
#pragma unroll
                    for (int hh = 0; hh < 2; hh++) {
                        int row = rbase + hh * 8;
                        if (row < n) {
                            float ox = fmaxf(acc[t][nf][hh * 2 + 0] + bs[col], 0.f);
                            float oy = fmaxf(acc[t][nf][hh * 2 + 1] + bs[col + 1], 0.f);
                            __half2 hp = __floats2half2_rn(ox, oy);
                            *reinterpret_cast<uint32_t*>(outP + (size_t)row * 128 + col) =
                                *reinterpret_cast<uint32_t*>(&hp);
                        }
                    }
                }
            }
        } else {
#pragma unroll
            for (int t = 0; t < 2; t++) {
                int rl = warpM + t * 16 + (lane >> 2);
#pragma unroll
                for (int nf = 0; nf < 8; nf++) {
                    int col = g * 64 + nf * 8 + (lane & 3) * 2;
#pragma unroll
                    for (int hh = 0; hh < 2; hh++) {
                        int r = rl + hh * 8;
                        float ox = fmaxf(acc[t][nf][hh * 2 + 0] + bs[col], 0.f);
                        float oy = fmaxf(acc[t][nf][hh * 2 + 1] + bs[col + 1], 0.f);
                        __half2 hp = __floats2half2_rn(ox, oy);
                        uint32_t off = SWZ((uint32_t)(r * 128 + (col & 63) * 2));
                        *reinterpret_cast<uint32_t*>(smem + 1024 + g * CHUNKB + off) =
                            *reinterpret_cast<uint32_t*>(&hp);
                    }
                }
            }
            __syncthreads();

            float acc2[2][4][4];
#pragma unroll
            for (int t = 0; t < 2; t++)
#pragma unroll
                for (int nf = 0; nf < 4; nf++)
#pragma unroll
                    for (int q = 0; q < 4; q++) acc2[t][nf][q] = 0.f;

#pragma unroll
            for (int ks2 = 0; ks2 < 8; ks2++) {
                const int chunk = ks2 >> 2, ksl2 = ks2 & 3;
                const uint32_t abase2 = sb + 1024 + chunk * CHUNKB;
                uint32_t ah2[2][4];
#pragma unroll
                for (int t = 0; t < 2; t++) {
                    int arow = warpM + t * 16 + (lane & 15);
                    int colb = ksl2 * 32 + ((lane >> 4) << 4);
                    ldm4(abase2 + SWZ((uint32_t)(arow * 128 + colb)), ah2[t]);
                }
                uint4 Bq[2];
                {
                    size_t base = (size_t)BOFF2 +
                        ((size_t)(ks2 * 4 + g * 2) * 32 + lane) * 16;
                    Bq[0] = *reinterpret_cast<const uint4*>(smem + base);
                    Bq[1] = *reinterpret_cast<const uint4*>(smem + base + 512);
                }
#pragma unroll
                for (int t = 0; t < 2; t++)
#pragma unroll
                    for (int nf = 0; nf < 4; nf++) {
                        uint32_t b0 = (nf & 1) ? Bq[nf >> 1].z : Bq[nf >> 1].x;
                        uint32_t b1 = (nf & 1) ? Bq[nf >> 1].w : Bq[nf >> 1].y;
                        mma_f16(acc2[t][nf], ah2[t], b0, b1);
                    }
                {
                    size_t base = (size_t)BOFF2 + BSPLIT2 +
                        ((size_t)(ks2 * 4 + g * 2) * 32 + lane) * 16;
                    Bq[0] = *reinterpret_cast<const uint4*>(smem + base);
                    Bq[1] = *reinterpret_cast<const uint4*>(smem + base + 512);
                }
#pragma unroll
                for (int t = 0; t < 2; t++)
#pragma unroll
                    for (int nf = 0; nf < 4; nf++) {
                        uint32_t b0 = (nf & 1) ? Bq[nf >> 1].z : Bq[nf >> 1].x;
                        uint32_t b1 = (nf & 1) ? Bq[nf >> 1].w : Bq[nf >> 1].y;
                        mma_f16(acc2[t][nf], ah2[t], b0, b1);
                    }
            }

#pragma unroll
            for (int t = 0; t < 2; t++) {
                int rbase = tt * MTILE + warpM + t * 16 + (lane >> 2);
#pragma unroll
                for (int nf = 0; nf < 4; nf++) {
                    int col = g * 32 + nf * 8 + (lane & 3) * 2;
#pragma unroll
                    for (int hh = 0; hh < 2; hh++) {
                        int row = rbase + hh * 8;
                        if (row < n) {
                            __half2 hp = __floats2half2_rn(
                                acc2[t][nf][hh * 2 + 0] + bs2[col],
                                acc2[t][nf][hh * 2 + 1] + bs2[col + 1]);
                            *reinterpret_cast<uint32_t*>(out2 + (size_t)row * 64 + col) =
                                *reinterpret_cast<uint32_t*>(&hp);
                        }
                    }
                }
            }
            __syncthreads();
        }
    }
}

// ---------------------------------------------------------------------------
// HMMA decoder (+ scratch zeroing prologue for next call's invariant)
// ---------------------------------------------------------------------------
__global__ __launch_bounds__(512, 1) void decoder_hmma(
    const __half* __restrict__ zc, const __half* __restrict__ zp,
    const int* __restrict__ rowIdx, const int* __restrict__ colIdx,
    const float* __restrict__ W1, const float* __restrict__ b1,
    const float* __restrict__ w2, const float* __restrict__ b2,
    float* __restrict__ out, int nE)
{
    constexpr int MTILE  = 256;
    constexpr int CHUNKB = MTILE * 128;
    constexpr int BOFF   = 1024 + 2 * CHUNKB;
    constexpr int BSPLIT = 8 * 4 * 32 * 16;

    for (int i = blockIdx.x * blockDim.x + threadIdx.x; i < N_PROD;
         i += gridDim.x * blockDim.x) {
        g_cntP[i] = 0;
        if (i < N_CUST) g_cntC[i] = 0;
        if (i < 128) g_lbP[i] = 0;
        if (i < 64) g_lbC[i] = 0;
    }

    extern __shared__ char smem[];
    const uint32_t sb = smem_u32(smem);
    const int tid = threadIdx.x;
    const int w = tid >> 5, lane = tid & 31;
    const int warpM = w * 16;

    float* ps = (float*)smem;
    if (tid < 64) ps[tid] = b1[tid];
    else if (tid < 128) ps[tid] = w2[tid - 64];
    else if (tid == 128) ps[128] = b2[0];

    for (int idx = tid; idx < 2 * 8 * 4 * 32; idx += 512) {
        int l = idx & 31;
        int rest = idx >> 5;
        int nfp = rest % 4;
        int rest2 = rest / 4;
        int ks = rest2 % 8;
        int s = rest2 / 8;
        uint32_t vals[4];
#pragma unroll
        for (int e = 0; e < 2; e++) {
            int nf = nfp * 2 + e;
            int nn = nf * 8 + (l >> 2);
            int k0 = ks * 16 + (l & 3) * 2;
            float2 wa = *reinterpret_cast<const float2*>(W1 + nn * 128 + k0);
            float2 wb = *reinterpret_cast<const float2*>(W1 + nn * 128 + k0 + 8);
            unsigned short h, lo, r00, r01, r10, r11;
            split1h(wa.x, h, lo); r00 = s ? lo : h;
            split1h(wa.y, h, lo); r01 = s ? lo : h;
            split1h(wb.x, h, lo); r10 = s ? lo : h;
            split1h(wb.y, h, lo); r11 = s ? lo : h;
            vals[e * 2 + 0] = (uint32_t)r00 | ((uint32_t)r01 << 16);
            vals[e * 2 + 1] = (uint32_t)r10 | ((uint32_t)r11 << 16);
        }
        *reinterpret_cast<uint4*>(smem + BOFF + (size_t)idx * 16) =
            make_uint4(vals[0], vals[1], vals[2], vals[3]);
    }
    __syncthreads();

    const int ntiles = (nE + MTILE - 1) / MTILE;

    for (int tt = blockIdx.x; tt < ntiles; tt += gridDim.x) {
        float acc[8][4];
#pragma unroll
        for (int nf = 0; nf < 8; nf++)
#pragma unroll
            for (int q = 0; q < 4; q++) acc[nf][q] = 0.f;

        auto stage = [&](int c, int b) {
            const __half* src = (c == 0) ? zc : zp;
            const int* idxp = (c == 0) ? rowIdx : colIdx;
#pragma unroll
            for (int it = 0; it < 4; it++) {
                int u = tid + it * 512;
                int r0 = u >> 3;
                int ch = u & 7;
                int e = tt * MTILE + r0;
                int idx = (e < nE) ? __ldg(idxp + e) : -1;
                uint32_t dst = sb + 1024 + b * CHUNKB +
                               SWZ((uint32_t)(r0 * 128 + ch * 16));
                const void* gp = src + (size_t)(idx < 0 ? 0 : idx) * 64 + ch * 8;
                cp16(dst, gp, (idx >= 0) ? 16 : 0);
            }
            CP_COMMIT();
        };

        stage(0, 0);

        for (int c = 0; c < 2; c++) {
            if (c == 0) { stage(1, 1); CP_WAIT1(); }
            else CP_WAIT0();
            __syncthreads();

            const uint32_t abase = sb + 1024 + c * CHUNKB;
#pragma unroll
            for (int ksl = 0; ksl < 4; ksl++) {
                const int ks = c * 4 + ksl;
                uint32_t ah[4];
                {
                    int arow = warpM + (lane & 15);
                    int colb = ksl * 32 + ((lane >> 4) << 4);
                    ldm4(abase + SWZ((uint32_t)(arow * 128 + colb)), ah);
                }
                uint4 Bq[4];
                {
                    size_t base = (size_t)BOFF + ((size_t)(ks * 4) * 32 + lane) * 16;
#pragma unroll
                    for (int p = 0; p < 4; p++)
                        Bq[p] = *reinterpret_cast<const uint4*>(smem + base + p * 512);
                }
#pragma unroll
                for (int nf = 0; nf < 8; nf++) {
                    uint32_t b0 = (nf & 1) ? Bq[nf >> 1].z : Bq[nf >> 1].x;
                    uint32_t b1v = (nf & 1) ? Bq[nf >> 1].w : Bq[nf >> 1].y;
                    mma_f16(acc[nf], ah, b0, b1v);
                }
                {
                    size_t base = (size_t)BOFF + BSPLIT + ((size_t)(ks * 4) * 32 + lane) * 16;
#pragma unroll
                    for (int p = 0; p < 4; p++)
                        Bq[p] = *reinterpret_cast<const uint4*>(smem + base + p * 512);
                }
#pragma unroll
                for (int nf = 0; nf < 8; nf++) {
                    uint32_t b0 = (nf & 1) ? Bq[nf >> 1].z : Bq[nf >> 1].x;
                    uint32_t b1v = (nf & 1) ? Bq[nf >> 1].w : Bq[nf >> 1].y;
                    mma_f16(acc[nf], ah, b0, b1v);
                }
            }
            __syncthreads();
        }

        {
            float p0 = 0.f, p1 = 0.f;
#pragma unroll
            for (int nf = 0; nf < 8; nf++) {
                int col = nf * 8 + (lane & 3) * 2;
                float w20 = ps[64 + col], w21 = ps[64 + col + 1];
                float bb0 = ps[col], bb1 = ps[col + 1];
                p0 += fmaxf(acc[nf][0] + bb0, 0.f) * w20 +
                      fmaxf(acc[nf][1] + bb1, 0.f) * w21;
                p1 += fmaxf(acc[nf][2] + bb0, 0.f) * w20 +
                      fmaxf(acc[nf][3] + bb1, 0.f) * w21;
            }
            p0 += __shfl_xor_sync(0xffffffff, p0, 1);
            p0 += __shfl_xor_sync(0xffffffff, p0, 2);
            p1 += __shfl_xor_sync(0xffffffff, p1, 1);
            p1 += __shfl_xor_sync(0xffffffff, p1, 2);
            if ((lane & 3) == 0) {
                int e0 = tt * MTILE + warpM + (lane >> 2);
                if (e0 < nE) out[e0] = p0 + ps[128];
                if (e0 + 8 < nE) out[e0 + 8] = p1 + ps[128];
            }
        }
    }
}

// ---------------------------------------------------------------------------
// Host orchestration (wide PDL DAG)
// ---------------------------------------------------------------------------
extern "C" void kernel_launch(void* const* d_in, const int* in_sizes, int n_in,
                              void* d_out, int out_size) {
    const float* x_prod = (const float*)d_in[0];
    const float* x_cust = (const float*)d_in[1];
    const int* pp = (const int*)d_in[2];
    const int* pc = (const int*)d_in[3];
    const int* eli = (const int*)d_in[4];

    bool sig = (in_sizes[6] == HID);
    const float* it_W1l = (const float*)d_in[5];
    const float* it_W1r = (const float*)d_in[sig ? 7 : 6];
    const float* it_b1  = (const float*)d_in[sig ? 6 : 7];
    const float* it_W2l = (const float*)d_in[8];
    const float* it_W2r = (const float*)d_in[sig ? 10 : 9];
    const float* it_b2  = (const float*)d_in[sig ? 9 : 10];
    const float* it_Wlin = (const float*)d_in[11];
    const float* it_blin = (const float*)d_in[12];
    const float* us_W1l = (const float*)d_in[13];
    const float* us_W1r = (const float*)d_in[sig ? 15 : 14];
    const float* us_b1  = (const float*)d_in[sig ? 14 : 15];
    const float* us_W2l = (const float*)d_in[16];
    const float* us_W2r = (const float*)d_in[sig ? 18 : 17];
    const float* us_b2  = (const float*)d_in[sig ? 17 : 18];
    const float* us_W3l = (const float*)d_in[19];
    const float* us_W3r = (const float*)d_in[sig ? 21 : 20];
    const float* us_b3  = (const float*)d_in[sig ? 20 : 21];
    const float* us_Wlin = (const float*)d_in[22];
    const float* us_blin = (const float*)d_in[23];
    const float* de_W1 = (const float*)d_in[24];
    const float* de_b1 = (const float*)d_in[25];
    const float* de_W2 = (const float*)d_in[26];
    const float* de_b2 = (const float*)d_in[27];

#define GETP(var, sym, T) T* var; cudaGetSymbolAddress((void**)&var, sym)
    GETP(xP, g_xP, __half); GETP(xC, g_xC, __half);
    GETP(M0, g_M0, __half); GETP(M0C, g_M0C, __half);
    GETP(P1, g_P1, __half); GETP(P2, g_P2, __half);
    GETP(C1, g_C1, __half);
    GETP(zprod, g_zprod, __half); GETP(zcust, g_zcust, __half);
    GETP(offP, g_offP, int); GETP(csrP, g_csrP, int);
    GETP(offC, g_offC, int); GETP(csrC, g_csrC, int);
#undef GETP

    constexpr int SM_PLAIN = 1024 + 2 * 32768 + 2 * 65536;   // 197632
    constexpr int SM_FUSED = SM_PLAIN + 2 * 16384;           // 230400
    constexpr int SM_DEC   = 1024 + 2 * 32768 + 2 * 16384;   // 99328
    cudaFuncSetAttribute((hmma_dual<false>),
                         cudaFuncAttributeMaxDynamicSharedMemorySize, SM_PLAIN);
    cudaFuncSetAttribute((hmma_dual<true>),
                         cudaFuncAttributeMaxDynamicSharedMemorySize, SM_FUSED);
    cudaFuncSetAttribute(decoder_hmma,
                         cudaFuncAttributeMaxDynamicSharedMemorySize, SM_DEC);

    const int nbP = (N_PROD + 1023) / 1024;
    const int nbC = (N_CUST + 1023) / 1024;
    const int PRE_ITEMS = (N_PROD + N_CUST) * HID / 4 + E_PP + E_PC;
    const int agg2x_grid = ((N_PROD + N_CUST) * 32 + 255) / 256;
    const int aggP_grid = (N_PROD * 32 + 255) / 256;
    const int aggC_grid = (N_CUST * 32 + 255) / 256;

    cudaLaunchAttribute pdlAttr[1];
    pdlAttr[0].id = cudaLaunchAttributeProgrammaticStreamSerialization;
    pdlAttr[0].val.programmaticStreamSerializationAllowed = 1;

    cudaLaunchConfig_t cfgGemm{};
    cfgGemm.gridDim = dim3(148); cfgGemm.blockDim = dim3(512);
    cfgGemm.dynamicSmemBytes = SM_PLAIN; cfgGemm.stream = 0;
    cfgGemm.attrs = pdlAttr; cfgGemm.numAttrs = 1;

    cudaLaunchConfig_t cfgGemmF{};
    cfgGemmF.gridDim = dim3(148); cfgGemmF.blockDim = dim3(512);
    cfgGemmF.dynamicSmemBytes = SM_FUSED; cfgGemmF.stream = 0;
    cfgGemmF.attrs = pdlAttr; cfgGemmF.numAttrs = 1;

    cudaLaunchConfig_t cfgAggC{};
    cfgAggC.gridDim = dim3(aggC_grid); cfgAggC.blockDim = dim3(256);
    cfgAggC.dynamicSmemBytes = 0; cfgAggC.stream = 0;
    cfgAggC.attrs = pdlAttr; cfgAggC.numAttrs = 1;

    // 0-2: convert + counts, scans, fills
    k_pre<<<(PRE_ITEMS + 255) / 256, 256>>>(x_prod, x_cust, pp + E_PP, pc + E_PC);
    k_scan2x<<<nbP + nbC, 1024>>>();
    k_fill2x<<<(E_PP + E_PC + 255) / 256, 256>>>(pp, pc);

    // 3: both x-aggregations: M0 = mean_pp(x), M0C = mean_pc(x)
    agg2x<<<agg2x_grid, 256>>>();

    // 4-6: G1, G2, G5 all independent (need only agg2x outputs + x planes)
    hmma_dual<false><<<148, 512, SM_PLAIN>>>(
        M0, xP, it_W1l, it_W1r, it_b1, nullptr, nullptr, P1, nullptr, N_PROD, 1);
    cudaLaunchKernelEx(&cfgGemm, hmma_dual<false>,
        (const __half*)M0, (const __half*)xP, us_W1l, us_W1r, us_b1,
        (const float*)nullptr, (const float*)nullptr,
        (__half*)P2, (__half*)nullptr, (int)N_PROD, 1);   // PDL + re-trigger
    cudaLaunchKernelEx(&cfgGemm, hmma_dual<false>,
        (const __half*)M0C, (const __half*)xC, us_W2l, us_W2r, us_b2,
        (const float*)nullptr, (const float*)nullptr,
        (__half*)C1, (__half*)nullptr, (int)N_CUST, 0);   // PDL

    // 7-8: aggP (needs P1) ; aggC2 (needs P2) — concurrent
    agg_mean<<<aggP_grid, 256>>>(P1, offP, csrP, M0, N_PROD, E_PP, 1);
    cudaLaunchKernelEx(&cfgAggC, agg_mean,
        (const __half*)P2, (const int*)offC, (const int*)csrC,
        (__half*)M0C, (int)N_CUST, (int)E_PC, 0);         // PDL

    // 9-10: fused G3 (needs M0,P1) ; fused G6 (needs M0C,C1) — concurrent
    hmma_dual<true><<<148, 512, SM_FUSED>>>(
        M0, P1, it_W2l, it_W2r, it_b2, it_Wlin, it_blin, nullptr, zprod, N_PROD, 1);
    cudaLaunchKernelEx(&cfgGemmF, hmma_dual<true>,
        (const __half*)M0C, (const __half*)C1, us_W3l, us_W3r, us_b3,
        us_Wlin, us_blin, (__half*)nullptr, (__half*)zcust, (int)N_CUST, 0);  // PDL

    // 11: HMMA decoder (+ zero-invariant restore)
    decoder_hmma<<<148, 512, SM_DEC>>>(zcust, zprod, eli, eli + E_LB,
                                       de_W1, de_b1, de_W2, de_b2,
                                       (float*)d_out, E_LB);
}